// round 1
// baseline (speedup 1.0000x reference)
#include <cuda_runtime.h>
#include <cuda_bf16.h>
#include <math.h>

#define G   32
#define NN  512
#define EE  8192
#define DD  256
#define KK  2048

// ---------------- scratch (device globals; no allocation allowed) ----------
__device__ float g_rs_out[G * NN];
__device__ float g_rs_in [G * NN];
__device__ float g_A  [(size_t)G * NN * NN];   // 32 MB  normalized adjacency (counts * rsqrt factors)
__device__ float g_adj[(size_t)G * NN * NN];   // 32 MB  binary adj at [src][dst]
__device__ float g_buf1[(size_t)G * NN * DD];  // 16 MB
__device__ float g_buf2[(size_t)G * NN * DD];  // 16 MB
__device__ float g_q   [(size_t)G * NN * DD];  // 16 MB  gathered codebook rows
__device__ float g_cnT [(size_t)DD * KK];      // 2 MB   normalized codebook, transposed [D][K]
__device__ int   g_idx [G * NN];
__device__ float g_ne  [G];
__device__ float g_eacc[G];
__device__ float g_vqacc;

// ---------------- utility kernels -----------------------------------------
__global__ void zero_kernel(float* p, size_t n) {
    for (size_t i = (size_t)blockIdx.x * blockDim.x + threadIdx.x; i < n;
         i += (size_t)gridDim.x * blockDim.x)
        p[i] = 0.f;
}

__global__ void zero_small_kernel() {
    int t = threadIdx.x;
    if (t < G) g_eacc[t] = 0.f;
    if (t == 0) g_vqacc = 0.f;
}

// ---------------- degrees --------------------------------------------------
__global__ __launch_bounds__(256) void degree_kernel(const int* __restrict__ src,
                                                     const int* __restrict__ dst) {
    int g = blockIdx.x;
    __shared__ int co[NN], ci[NN];
    for (int i = threadIdx.x; i < NN; i += blockDim.x) { co[i] = 0; ci[i] = 0; }
    __syncthreads();
    const int* s = src + g * EE;
    const int* d = dst + g * EE;
    for (int e = threadIdx.x; e < EE; e += blockDim.x) {
        atomicAdd(&co[s[e]], 1);
        atomicAdd(&ci[d[e]], 1);
    }
    __syncthreads();
    for (int i = threadIdx.x; i < NN; i += blockDim.x) {
        g_rs_out[g * NN + i] = rsqrtf((float)max(co[i], 1));
        g_rs_in [g * NN + i] = rsqrtf((float)max(ci[i], 1));
    }
}

// ---------------- scatter edges into dense A + binary adj ------------------
__global__ __launch_bounds__(256) void scatter_kernel(const int* __restrict__ src,
                                                      const int* __restrict__ dst) {
    int g = blockIdx.x;
    const int* s = src + g * EE;
    const int* d = dst + g * EE;
    float* A   = g_A   + (size_t)g * NN * NN;
    float* adj = g_adj + (size_t)g * NN * NN;
    for (int e = threadIdx.x; e < EE; e += blockDim.x) {
        int ss = s[e], dd = d[e];
        atomicAdd(&A[dd * NN + ss], g_rs_in[g * NN + dd] * g_rs_out[g * NN + ss]);
        adj[ss * NN + dd] = 1.0f;   // duplicates harmless
    }
}

// ---------------- num_edges (strict upper triangle of adj) -----------------
__global__ __launch_bounds__(256) void count_edges_kernel() {
    int g = blockIdx.x;
    const float* adj = g_adj + (size_t)g * NN * NN;
    float sum = 0.f;
    for (int idx = threadIdx.x; idx < NN * NN; idx += blockDim.x) {
        int i = idx >> 9, j = idx & 511;
        if (j > i) sum += adj[idx];
    }
    __shared__ float red[256];
    red[threadIdx.x] = sum;
    __syncthreads();
    for (int s = 128; s > 0; s >>= 1) {
        if (threadIdx.x < s) red[threadIdx.x] += red[threadIdx.x + s];
        __syncthreads();
    }
    if (threadIdx.x == 0) g_ne[g] = red[0];
}

// ---------------- normalize codebook -> transposed [D][K] ------------------
__global__ __launch_bounds__(256) void norm_codebook_kernel(const float* __restrict__ cb) {
    int k = blockIdx.x;            // 0..K-1
    float v = cb[(size_t)k * DD + threadIdx.x];
    float ss = v * v;
    __shared__ float red[8];
    for (int o = 16; o > 0; o >>= 1) ss += __shfl_down_sync(0xffffffffu, ss, o);
    if ((threadIdx.x & 31) == 0) red[threadIdx.x >> 5] = ss;
    __syncthreads();
    if (threadIdx.x == 0) {
        float t = 0.f;
        for (int i = 0; i < 8; i++) t += red[i];
        red[0] = t;
    }
    __syncthreads();
    float r = rsqrtf(red[0] + 1e-12f);
    g_cnT[(size_t)threadIdx.x * KK + k] = v * r;
}

// ---------------- generic tiled fp32 GEMM: C = act(A@B + bias) -------------
// A [M,K] row-major, B [K,N] row-major. 64x64 tile, BK=16, thread 4x4.
__global__ __launch_bounds__(256) void gemm64_kernel(
    const float* __restrict__ A, const float* __restrict__ B,
    const float* __restrict__ bias, float* __restrict__ C,
    int M, int Ncol, int Kd, size_t sA, size_t sB, size_t sC, int relu)
{
    int b = blockIdx.z;
    A += (size_t)b * sA; B += (size_t)b * sB; C += (size_t)b * sC;
    int rowbase = blockIdx.y * 64, colbase = blockIdx.x * 64;
    __shared__ float As[16 * 64], Bs[16 * 64];
    int tx = threadIdx.x & 15, ty = threadIdx.x >> 4;
    float acc[4][4] = {};
    for (int k0 = 0; k0 < Kd; k0 += 16) {
#pragma unroll
        for (int i = 0; i < 4; i++) {
            int idx = threadIdx.x + i * 256;    // 0..1023
            int kk = idx >> 6, m = idx & 63;
            As[kk * 64 + m] = A[(size_t)(rowbase + m) * Kd + k0 + kk];
            Bs[kk * 64 + m] = B[(size_t)(k0 + kk) * Ncol + colbase + m];
        }
        __syncthreads();
#pragma unroll
        for (int kk = 0; kk < 16; kk++) {
            float4 a4 = *(const float4*)&As[kk * 64 + ty * 4];
            float4 b4 = *(const float4*)&Bs[kk * 64 + tx * 4];
            float av[4] = {a4.x, a4.y, a4.z, a4.w};
            float bv[4] = {b4.x, b4.y, b4.z, b4.w};
#pragma unroll
            for (int i = 0; i < 4; i++)
#pragma unroll
                for (int j = 0; j < 4; j++) acc[i][j] += av[i] * bv[j];
        }
        __syncthreads();
    }
#pragma unroll
    for (int i = 0; i < 4; i++) {
        int r = rowbase + ty * 4 + i;
#pragma unroll
        for (int j = 0; j < 4; j++) {
            int c = colbase + tx * 4 + j;
            float v = acc[i][j];
            if (bias) v += bias[c];
            if (relu) v = fmaxf(v, 0.f);
            C[(size_t)r * Ncol + c] = v;
        }
    }
}

// ---------------- layernorm over D ----------------------------------------
__global__ __launch_bounds__(256) void layernorm_kernel(
    const float* __restrict__ x, const float* __restrict__ gamma,
    const float* __restrict__ beta, float* __restrict__ y)
{
    int row = blockIdx.x;
    float v = x[(size_t)row * DD + threadIdx.x];
    __shared__ float red[8];
    float s = v;
    for (int o = 16; o > 0; o >>= 1) s += __shfl_down_sync(0xffffffffu, s, o);
    if ((threadIdx.x & 31) == 0) red[threadIdx.x >> 5] = s;
    __syncthreads();
    if (threadIdx.x == 0) {
        float t = 0.f;
        for (int i = 0; i < 8; i++) t += red[i];
        red[0] = t;
    }
    __syncthreads();
    float mu = red[0] / DD;
    float d = v - mu;
    float s2 = d * d;
    __syncthreads();   // protect red before reuse
    for (int o = 16; o > 0; o >>= 1) s2 += __shfl_down_sync(0xffffffffu, s2, o);
    if ((threadIdx.x & 31) == 0) red[threadIdx.x >> 5] = s2;
    __syncthreads();
    if (threadIdx.x == 0) {
        float t = 0.f;
        for (int i = 0; i < 8; i++) t += red[i];
        red[0] = t;
    }
    __syncthreads();
    float var = red[0] / DD;
    y[(size_t)row * DD + threadIdx.x] =
        d * rsqrtf(var + 1e-5f) * gamma[threadIdx.x] + beta[threadIdx.x];
}

// ---------------- fused VQ argmax + gather + vq_loss -----------------------
// Block = 128 hf rows resident in SMEM; streams cnT; running argmax per row.
#define AM_SMEM ((256 * 128 + 8 * 128 + 16 * 128 + 16 * 128) * 4)   // 148 KB
__global__ __launch_bounds__(256, 1) void argmax_vq_kernel(
    const float* __restrict__ hf, const float* __restrict__ cb)
{
    extern __shared__ float sm[];
    float* As   = sm;                      // [256][128]  As[k][r]
    float* Bs   = sm + 256 * 128;          // [8][128]
    float* redv = Bs + 8 * 128;            // [16][128]
    int*   redi = (int*)(redv + 16 * 128); // [16][128]
    int rowbase = blockIdx.x * 128;
    int t = threadIdx.x, tx = t & 15, ty = t >> 4;

    // load hf tile transposed: As[k][r]
    for (int i = 0; i < 128; i++) {
        int idx = t + i * 256;
        int k = idx >> 7, r = idx & 127;
        As[k * 128 + r] = hf[(size_t)(rowbase + r) * DD + k];
    }
    __syncthreads();

    float best[8]; int bidx[8];
#pragma unroll
    for (int i = 0; i < 8; i++) { best[i] = -1e30f; bidx[i] = 0; }

    for (int c = 0; c < KK; c += 128) {
        float acc[8][8] = {};
        for (int k0 = 0; k0 < DD; k0 += 8) {
#pragma unroll
            for (int i = 0; i < 4; i++) {
                int idx = t + i * 256;
                int kk = idx >> 7, cc = idx & 127;
                Bs[kk * 128 + cc] = g_cnT[(size_t)(k0 + kk) * KK + c + cc];
            }
            __syncthreads();
#pragma unroll
            for (int kk = 0; kk < 8; kk++) {
                float4 a0 = *(const float4*)&As[(k0 + kk) * 128 + ty * 8];
                float4 a1 = *(const float4*)&As[(k0 + kk) * 128 + ty * 8 + 4];
                float4 b0 = *(const float4*)&Bs[kk * 128 + tx * 8];
                float4 b1 = *(const float4*)&Bs[kk * 128 + tx * 8 + 4];
                float av[8] = {a0.x, a0.y, a0.z, a0.w, a1.x, a1.y, a1.z, a1.w};
                float bv[8] = {b0.x, b0.y, b0.z, b0.w, b1.x, b1.y, b1.z, b1.w};
#pragma unroll
                for (int i = 0; i < 8; i++)
#pragma unroll
                    for (int j = 0; j < 8; j++) acc[i][j] += av[i] * bv[j];
            }
            __syncthreads();
        }
#pragma unroll
        for (int i = 0; i < 8; i++)
#pragma unroll
            for (int j = 0; j < 8; j++) {
                float v = acc[i][j];
                if (v > best[i]) { best[i] = v; bidx[i] = c + tx * 8 + j; }
            }
    }
    // reduce across tx (16 column-threads per row); first-max tie rule
#pragma unroll
    for (int i = 0; i < 8; i++) {
        redv[tx * 128 + ty * 8 + i] = best[i];
        redi[tx * 128 + ty * 8 + i] = bidx[i];
    }
    __syncthreads();
    if (t < 128) {
        float bv = redv[t]; int bi = redi[t];
        for (int x = 1; x < 16; x++) {
            float v = redv[x * 128 + t]; int ii = redi[x * 128 + t];
            if (v > bv || (v == bv && ii < bi)) { bv = v; bi = ii; }
        }
        g_idx[rowbase + t] = bi;
        redi[t] = bi;   // reuse as per-row idx table
    }
    __syncthreads();
    // gather q + vq partial: 2 threads per row, 128 dims each
    {
        int r = t >> 1, half = t & 1;
        int idx = redi[r];
        const float* crow = cb  + (size_t)idx * DD + half * 128;
        float*       qrow = g_q + (size_t)(rowbase + r) * DD + half * 128;
        float s = 0.f;
        for (int d = 0; d < 128; d++) {
            float cv = crow[d];
            float hv = As[(half * 128 + d) * 128 + r];
            float df = cv - hv;
            s += df * df;
            qrow[d] = cv;
        }
        for (int o = 16; o > 0; o >>= 1) s += __shfl_down_sync(0xffffffffu, s, o);
        if ((t & 31) == 0) atomicAdd(&g_vqacc, s);
    }
}

// ---------------- fused edge loss: logits tile GEMM + BCE reduce -----------
__global__ __launch_bounds__(256) void edge_loss_kernel(const float* __restrict__ qe) {
    int g = blockIdx.y;
    int tlin = blockIdx.x;               // 0..35  upper-triangular 8x8 tile index
    int bi = 0, rem = tlin;
    while (rem >= 8 - bi) { rem -= 8 - bi; bi++; }
    int bj = bi + rem;
    const float* Q   = qe    + (size_t)g * NN * DD;
    const float* adj = g_adj + (size_t)g * NN * NN;
    float ne = g_ne[g];
    float pw = ((float)NN * NN * 0.5f - ne) / (ne + 1e-6f);

    __shared__ float As[16 * 64], Bs[16 * 64];
    int tx = threadIdx.x & 15, ty = threadIdx.x >> 4;
    float acc[4][4] = {};
    int rowbase = bi * 64, colbase = bj * 64;
    for (int k0 = 0; k0 < DD; k0 += 16) {
#pragma unroll
        for (int i = 0; i < 4; i++) {
            int idx = threadIdx.x + i * 256;
            int kk = idx >> 6, m = idx & 63;
            As[kk * 64 + m] = Q[(size_t)(rowbase + m) * DD + k0 + kk];
            Bs[kk * 64 + m] = Q[(size_t)(colbase + m) * DD + k0 + kk];
        }
        __syncthreads();
#pragma unroll
        for (int kk = 0; kk < 16; kk++) {
            float4 a4 = *(const float4*)&As[kk * 64 + ty * 4];
            float4 b4 = *(const float4*)&Bs[kk * 64 + tx * 4];
            float av[4] = {a4.x, a4.y, a4.z, a4.w};
            float bv[4] = {b4.x, b4.y, b4.z, b4.w};
#pragma unroll
            for (int i = 0; i < 4; i++)
#pragma unroll
                for (int j = 0; j < 4; j++) acc[i][j] += av[i] * bv[j];
        }
        __syncthreads();
    }
    float sum = 0.f;
#pragma unroll
    for (int i = 0; i < 4; i++) {
        int r = rowbase + ty * 4 + i;
#pragma unroll
        for (int j = 0; j < 4; j++) {
            int c = colbase + tx * 4 + j;
            if (r < c) {
                float x = acc[i][j];
                float l1 = log1pf(expf(-fabsf(x)));
                float sp_p = fmaxf(x, 0.f) + l1;     // softplus(x)
                float sp_n = fmaxf(-x, 0.f) + l1;    // softplus(-x)
                float a = adj[r * NN + c];
                sum += pw * a * sp_n + (1.f - a) * sp_p;
            }
        }
    }
    for (int o = 16; o > 0; o >>= 1) sum += __shfl_down_sync(0xffffffffu, sum, o);
    __shared__ float red[8];
    if ((threadIdx.x & 31) == 0) red[threadIdx.x >> 5] = sum;
    __syncthreads();
    if (threadIdx.x == 0) {
        float tsum = 0.f;
        for (int i = 0; i < 8; i++) tsum += red[i];
        atomicAdd(&g_eacc[g], tsum);
    }
}

// ---------------- finalize --------------------------------------------------
__global__ void finalize_kernel(float* out, int out_size) {
    float es = 0.f;
    for (int g = 0; g < G; g++) es += g_eacc[g] / ((float)NN * (NN - 1) * 0.5f);
    es /= (float)G;
    float vq = 1000.0f * g_vqacc / ((float)G * NN * DD);
    float loss = es * 100.0f + vq;      // LAMB_EDGE=1, ALPHA=100, LAMB_NODE=0
    for (int i = 0; i < out_size; i++) out[i] = loss;
}

// ---------------- launch ----------------------------------------------------
extern "C" void kernel_launch(void* const* d_in, const int* in_sizes, int n_in,
                              void* d_out, int out_size) {
    (void)in_sizes; (void)n_in;
    const float* feats = (const float*)d_in[0];
    const int*   src   = (const int*)  d_in[1];
    const int*   dst   = (const int*)  d_in[2];
    const float* W1    = (const float*)d_in[3];
    const float* b1    = (const float*)d_in[4];
    const float* W2    = (const float*)d_in[5];
    const float* b2    = (const float*)d_in[6];
    const float* gamma = (const float*)d_in[7];
    const float* beta  = (const float*)d_in[8];
    const float* dec1W = (const float*)d_in[9];
    const float* dec1b = (const float*)d_in[10];
    const float* cb    = (const float*)d_in[13];
    float* out = (float*)d_out;

    float *pA, *pAdj, *pB1, *pB2, *pQ;
    cudaGetSymbolAddress((void**)&pA,   g_A);
    cudaGetSymbolAddress((void**)&pAdj, g_adj);
    cudaGetSymbolAddress((void**)&pB1,  g_buf1);
    cudaGetSymbolAddress((void**)&pB2,  g_buf2);
    cudaGetSymbolAddress((void**)&pQ,   g_q);

    cudaFuncSetAttribute(argmax_vq_kernel,
                         cudaFuncAttributeMaxDynamicSharedMemorySize, AM_SMEM);

    zero_kernel<<<2048, 256>>>(pA,   (size_t)G * NN * NN);
    zero_kernel<<<2048, 256>>>(pAdj, (size_t)G * NN * NN);
    zero_small_kernel<<<1, 64>>>();

    degree_kernel <<<G, 256>>>(src, dst);
    scatter_kernel<<<G, 256>>>(src, dst);
    count_edges_kernel<<<G, 256>>>();
    norm_codebook_kernel<<<KK, 256>>>(cb);

    // conv1: m = A @ feats  -> buf1
    gemm64_kernel<<<dim3(DD / 64, NN / 64, G), 256>>>(
        pA, feats, nullptr, pB1, NN, DD, NN,
        (size_t)NN * NN, (size_t)NN * DD, (size_t)NN * DD, 0);
    // h1 = relu(m @ W1 + b1) -> buf2
    gemm64_kernel<<<dim3(DD / 64, (G * NN) / 64, 1), 256>>>(
        pB1, W1, b1, pB2, G * NN, DD, DD, 0, 0, 0, 1);
    // layernorm -> buf1
    layernorm_kernel<<<G * NN, 256>>>(pB2, gamma, beta, pB1);
    // conv2: m2 = A @ h1ln -> buf2
    gemm64_kernel<<<dim3(DD / 64, NN / 64, G), 256>>>(
        pA, pB1, nullptr, pB2, NN, DD, NN,
        (size_t)NN * NN, (size_t)NN * DD, (size_t)NN * DD, 0);
    // hf = relu(m2 @ W2 + b2) -> buf1
    gemm64_kernel<<<dim3(DD / 64, (G * NN) / 64, 1), 256>>>(
        pB2, W2, b2, pB1, G * NN, DD, DD, 0, 0, 0, 1);

    // VQ argmax + gather + vq loss
    argmax_vq_kernel<<<(G * NN) / 128, 256, AM_SMEM>>>(pB1, cb);

    // qe = q @ dec1_W + dec1_b -> buf2
    gemm64_kernel<<<dim3(DD / 64, (G * NN) / 64, 1), 256>>>(
        pQ, dec1W, dec1b, pB2, G * NN, DD, DD, 0, 0, 0, 0);

    // fused edge BCE loss (upper-triangular tiles only)
    edge_loss_kernel<<<dim3(36, G), 256>>>(pB2);

    finalize_kernel<<<1, 1>>>(out, out_size);
}

// round 2
// speedup vs baseline: 1.0002x; 1.0002x over previous
#include <cuda_runtime.h>
#include <cuda_bf16.h>
#include <math.h>

#define G   32
#define NN  512
#define EE  8192
#define DD  256
#define KK  2048

// ---------------- scratch (device globals; no allocation allowed) ----------
__device__ float g_rs_out[G * NN];
__device__ float g_rs_in [G * NN];
__device__ float g_A  [(size_t)G * NN * NN];   // 32 MB  normalized adjacency (counts * rsqrt factors)
__device__ float g_adj[(size_t)G * NN * NN];   // 32 MB  binary adj at [src][dst]
__device__ float g_buf1[(size_t)G * NN * DD];  // 16 MB
__device__ float g_buf2[(size_t)G * NN * DD];  // 16 MB
__device__ float g_q   [(size_t)G * NN * DD];  // 16 MB  gathered codebook rows
__device__ float g_cnT [(size_t)DD * KK];      // 2 MB   normalized codebook, transposed [D][K]
__device__ int   g_idx [G * NN];
__device__ float g_ne  [G];
__device__ float g_eacc[G];
__device__ float g_vqacc;

// ---------------- utility kernels -----------------------------------------
__global__ void zero_kernel(float* p, size_t n) {
    for (size_t i = (size_t)blockIdx.x * blockDim.x + threadIdx.x; i < n;
         i += (size_t)gridDim.x * blockDim.x)
        p[i] = 0.f;
}

__global__ void zero_small_kernel() {
    int t = threadIdx.x;
    if (t < G) g_eacc[t] = 0.f;
    if (t == 0) g_vqacc = 0.f;
}

// ---------------- degrees --------------------------------------------------
__global__ __launch_bounds__(256) void degree_kernel(const int* __restrict__ src,
                                                     const int* __restrict__ dst) {
    int g = blockIdx.x;
    __shared__ int co[NN], ci[NN];
    for (int i = threadIdx.x; i < NN; i += blockDim.x) { co[i] = 0; ci[i] = 0; }
    __syncthreads();
    const int* s = src + g * EE;
    const int* d = dst + g * EE;
    for (int e = threadIdx.x; e < EE; e += blockDim.x) {
        atomicAdd(&co[s[e]], 1);
        atomicAdd(&ci[d[e]], 1);
    }
    __syncthreads();
    for (int i = threadIdx.x; i < NN; i += blockDim.x) {
        g_rs_out[g * NN + i] = rsqrtf((float)max(co[i], 1));
        g_rs_in [g * NN + i] = rsqrtf((float)max(ci[i], 1));
    }
}

// ---------------- scatter edges into dense A + binary adj ------------------
__global__ __launch_bounds__(256) void scatter_kernel(const int* __restrict__ src,
                                                      const int* __restrict__ dst) {
    int g = blockIdx.x;
    const int* s = src + g * EE;
    const int* d = dst + g * EE;
    float* A   = g_A   + (size_t)g * NN * NN;
    float* adj = g_adj + (size_t)g * NN * NN;
    for (int e = threadIdx.x; e < EE; e += blockDim.x) {
        int ss = s[e], dd = d[e];
        atomicAdd(&A[dd * NN + ss], g_rs_in[g * NN + dd] * g_rs_out[g * NN + ss]);
        adj[ss * NN + dd] = 1.0f;   // duplicates harmless
    }
}

// ---------------- num_edges (strict upper triangle of adj) -----------------
__global__ __launch_bounds__(256) void count_edges_kernel() {
    int g = blockIdx.x;
    const float* adj = g_adj + (size_t)g * NN * NN;
    float sum = 0.f;
    for (int idx = threadIdx.x; idx < NN * NN; idx += blockDim.x) {
        int i = idx >> 9, j = idx & 511;
        if (j > i) sum += adj[idx];
    }
    __shared__ float red[256];
    red[threadIdx.x] = sum;
    __syncthreads();
    for (int s = 128; s > 0; s >>= 1) {
        if (threadIdx.x < s) red[threadIdx.x] += red[threadIdx.x + s];
        __syncthreads();
    }
    if (threadIdx.x == 0) g_ne[g] = red[0];
}

// ---------------- normalize codebook -> transposed [D][K] ------------------
__global__ __launch_bounds__(256) void norm_codebook_kernel(const float* __restrict__ cb) {
    int k = blockIdx.x;            // 0..K-1
    float v = cb[(size_t)k * DD + threadIdx.x];
    float ss = v * v;
    __shared__ float red[8];
    for (int o = 16; o > 0; o >>= 1) ss += __shfl_down_sync(0xffffffffu, ss, o);
    if ((threadIdx.x & 31) == 0) red[threadIdx.x >> 5] = ss;
    __syncthreads();
    if (threadIdx.x == 0) {
        float t = 0.f;
        for (int i = 0; i < 8; i++) t += red[i];
        red[0] = t;
    }
    __syncthreads();
    float r = rsqrtf(red[0] + 1e-12f);
    g_cnT[(size_t)threadIdx.x * KK + k] = v * r;
}

// ---------------- generic tiled fp32 GEMM: C = act(A@B + bias) -------------
// A [M,K] row-major, B [K,N] row-major. 64x64 tile, BK=16, thread 4x4.
__global__ __launch_bounds__(256) void gemm64_kernel(
    const float* __restrict__ A, const float* __restrict__ B,
    const float* __restrict__ bias, float* __restrict__ C,
    int M, int Ncol, int Kd, size_t sA, size_t sB, size_t sC, int relu)
{
    int b = blockIdx.z;
    A += (size_t)b * sA; B += (size_t)b * sB; C += (size_t)b * sC;
    int rowbase = blockIdx.y * 64, colbase = blockIdx.x * 64;
    __shared__ float As[16 * 64], Bs[16 * 64];
    int tx = threadIdx.x & 15, ty = threadIdx.x >> 4;
    float acc[4][4] = {};
    for (int k0 = 0; k0 < Kd; k0 += 16) {
#pragma unroll
        for (int i = 0; i < 4; i++) {
            int idx = threadIdx.x + i * 256;    // 0..1023
            int kk = idx >> 6, m = idx & 63;
            As[kk * 64 + m] = A[(size_t)(rowbase + m) * Kd + k0 + kk];
            Bs[kk * 64 + m] = B[(size_t)(k0 + kk) * Ncol + colbase + m];
        }
        __syncthreads();
#pragma unroll
        for (int kk = 0; kk < 16; kk++) {
            float4 a4 = *(const float4*)&As[kk * 64 + ty * 4];
            float4 b4 = *(const float4*)&Bs[kk * 64 + tx * 4];
            float av[4] = {a4.x, a4.y, a4.z, a4.w};
            float bv[4] = {b4.x, b4.y, b4.z, b4.w};
#pragma unroll
            for (int i = 0; i < 4; i++)
#pragma unroll
                for (int j = 0; j < 4; j++) acc[i][j] += av[i] * bv[j];
        }
        __syncthreads();
    }
#pragma unroll
    for (int i = 0; i < 4; i++) {
        int r = rowbase + ty * 4 + i;
#pragma unroll
        for (int j = 0; j < 4; j++) {
            int c = colbase + tx * 4 + j;
            float v = acc[i][j];
            if (bias) v += bias[c];
            if (relu) v = fmaxf(v, 0.f);
            C[(size_t)r * Ncol + c] = v;
        }
    }
}

// ---------------- layernorm over D ----------------------------------------
__global__ __launch_bounds__(256) void layernorm_kernel(
    const float* __restrict__ x, const float* __restrict__ gamma,
    const float* __restrict__ beta, float* __restrict__ y)
{
    int row = blockIdx.x;
    float v = x[(size_t)row * DD + threadIdx.x];
    __shared__ float red[8];
    float s = v;
    for (int o = 16; o > 0; o >>= 1) s += __shfl_down_sync(0xffffffffu, s, o);
    if ((threadIdx.x & 31) == 0) red[threadIdx.x >> 5] = s;
    __syncthreads();
    if (threadIdx.x == 0) {
        float t = 0.f;
        for (int i = 0; i < 8; i++) t += red[i];
        red[0] = t;
    }
    __syncthreads();
    float mu = red[0] / DD;
    float d = v - mu;
    float s2 = d * d;
    __syncthreads();   // protect red before reuse
    for (int o = 16; o > 0; o >>= 1) s2 += __shfl_down_sync(0xffffffffu, s2, o);
    if ((threadIdx.x & 31) == 0) red[threadIdx.x >> 5] = s2;
    __syncthreads();
    if (threadIdx.x == 0) {
        float t = 0.f;
        for (int i = 0; i < 8; i++) t += red[i];
        red[0] = t;
    }
    __syncthreads();
    float var = red[0] / DD;
    y[(size_t)row * DD + threadIdx.x] =
        d * rsqrtf(var + 1e-5f) * gamma[threadIdx.x] + beta[threadIdx.x];
}

// ---------------- fused VQ argmax + gather + vq_loss -----------------------
// Block = 128 hf rows resident in SMEM; streams cnT; running argmax per row.
#define AM_SMEM ((256 * 128 + 8 * 128 + 16 * 128 + 16 * 128) * 4)   // 148 KB
__global__ __launch_bounds__(256, 1) void argmax_vq_kernel(
    const float* __restrict__ hf, const float* __restrict__ cb)
{
    extern __shared__ float sm[];
    float* As   = sm;                      // [256][128]  As[k][r]
    float* Bs   = sm + 256 * 128;          // [8][128]
    float* redv = Bs + 8 * 128;            // [16][128]
    int*   redi = (int*)(redv + 16 * 128); // [16][128]
    int rowbase = blockIdx.x * 128;
    int t = threadIdx.x, tx = t & 15, ty = t >> 4;

    // load hf tile transposed: As[k][r]
    for (int i = 0; i < 128; i++) {
        int idx = t + i * 256;
        int k = idx >> 7, r = idx & 127;
        As[k * 128 + r] = hf[(size_t)(rowbase + r) * DD + k];
    }
    __syncthreads();

    float best[8]; int bidx[8];
#pragma unroll
    for (int i = 0; i < 8; i++) { best[i] = -1e30f; bidx[i] = 0; }

    for (int c = 0; c < KK; c += 128) {
        float acc[8][8] = {};
        for (int k0 = 0; k0 < DD; k0 += 8) {
#pragma unroll
            for (int i = 0; i < 4; i++) {
                int idx = t + i * 256;
                int kk = idx >> 7, cc = idx & 127;
                Bs[kk * 128 + cc] = g_cnT[(size_t)(k0 + kk) * KK + c + cc];
            }
            __syncthreads();
#pragma unroll
            for (int kk = 0; kk < 8; kk++) {
                float4 a0 = *(const float4*)&As[(k0 + kk) * 128 + ty * 8];
                float4 a1 = *(const float4*)&As[(k0 + kk) * 128 + ty * 8 + 4];
                float4 b0 = *(const float4*)&Bs[kk * 128 + tx * 8];
                float4 b1 = *(const float4*)&Bs[kk * 128 + tx * 8 + 4];
                float av[8] = {a0.x, a0.y, a0.z, a0.w, a1.x, a1.y, a1.z, a1.w};
                float bv[8] = {b0.x, b0.y, b0.z, b0.w, b1.x, b1.y, b1.z, b1.w};
#pragma unroll
                for (int i = 0; i < 8; i++)
#pragma unroll
                    for (int j = 0; j < 8; j++) acc[i][j] += av[i] * bv[j];
            }
            __syncthreads();
        }
#pragma unroll
        for (int i = 0; i < 8; i++)
#pragma unroll
            for (int j = 0; j < 8; j++) {
                float v = acc[i][j];
                if (v > best[i]) { best[i] = v; bidx[i] = c + tx * 8 + j; }
            }
    }
    // reduce across tx (16 column-threads per row); first-max tie rule
#pragma unroll
    for (int i = 0; i < 8; i++) {
        redv[tx * 128 + ty * 8 + i] = best[i];
        redi[tx * 128 + ty * 8 + i] = bidx[i];
    }
    __syncthreads();
    if (t < 128) {
        float bv = redv[t]; int bi = redi[t];
        for (int x = 1; x < 16; x++) {
            float v = redv[x * 128 + t]; int ii = redi[x * 128 + t];
            if (v > bv || (v == bv && ii < bi)) { bv = v; bi = ii; }
        }
        g_idx[rowbase + t] = bi;
        redi[t] = bi;   // reuse as per-row idx table
    }
    __syncthreads();
    // gather q + vq partial: 2 threads per row, 128 dims each
    {
        int r = t >> 1, half = t & 1;
        int idx = redi[r];
        const float* crow = cb  + (size_t)idx * DD + half * 128;
        float*       qrow = g_q + (size_t)(rowbase + r) * DD + half * 128;
        float s = 0.f;
        for (int d = 0; d < 128; d++) {
            float cv = crow[d];
            float hv = As[(half * 128 + d) * 128 + r];
            float df = cv - hv;
            s += df * df;
            qrow[d] = cv;
        }
        for (int o = 16; o > 0; o >>= 1) s += __shfl_down_sync(0xffffffffu, s, o);
        if ((t & 31) == 0) atomicAdd(&g_vqacc, s);
    }
}

// ---------------- fused edge loss: logits tile GEMM + BCE reduce -----------
__global__ __launch_bounds__(256) void edge_loss_kernel(const float* __restrict__ qe) {
    int g = blockIdx.y;
    int tlin = blockIdx.x;               // 0..35  upper-triangular 8x8 tile index
    int bi = 0, rem = tlin;
    while (rem >= 8 - bi) { rem -= 8 - bi; bi++; }
    int bj = bi + rem;
    const float* Q   = qe    + (size_t)g * NN * DD;
    const float* adj = g_adj + (size_t)g * NN * NN;
    float ne = g_ne[g];
    float pw = ((float)NN * NN * 0.5f - ne) / (ne + 1e-6f);

    __shared__ float As[16 * 64], Bs[16 * 64];
    int tx = threadIdx.x & 15, ty = threadIdx.x >> 4;
    float acc[4][4] = {};
    int rowbase = bi * 64, colbase = bj * 64;
    for (int k0 = 0; k0 < DD; k0 += 16) {
#pragma unroll
        for (int i = 0; i < 4; i++) {
            int idx = threadIdx.x + i * 256;
            int kk = idx >> 6, m = idx & 63;
            As[kk * 64 + m] = Q[(size_t)(rowbase + m) * DD + k0 + kk];
            Bs[kk * 64 + m] = Q[(size_t)(colbase + m) * DD + k0 + kk];
        }
        __syncthreads();
#pragma unroll
        for (int kk = 0; kk < 16; kk++) {
            float4 a4 = *(const float4*)&As[kk * 64 + ty * 4];
            float4 b4 = *(const float4*)&Bs[kk * 64 + tx * 4];
            float av[4] = {a4.x, a4.y, a4.z, a4.w};
            float bv[4] = {b4.x, b4.y, b4.z, b4.w};
#pragma unroll
            for (int i = 0; i < 4; i++)
#pragma unroll
                for (int j = 0; j < 4; j++) acc[i][j] += av[i] * bv[j];
        }
        __syncthreads();
    }
    float sum = 0.f;
#pragma unroll
    for (int i = 0; i < 4; i++) {
        int r = rowbase + ty * 4 + i;
#pragma unroll
        for (int j = 0; j < 4; j++) {
            int c = colbase + tx * 4 + j;
            if (r < c) {
                float x = acc[i][j];
                float l1 = log1pf(expf(-fabsf(x)));
                float sp_p = fmaxf(x, 0.f) + l1;     // softplus(x)
                float sp_n = fmaxf(-x, 0.f) + l1;    // softplus(-x)
                float a = adj[r * NN + c];
                sum += pw * a * sp_n + (1.f - a) * sp_p;
            }
        }
    }
    for (int o = 16; o > 0; o >>= 1) sum += __shfl_down_sync(0xffffffffu, sum, o);
    __shared__ float red[8];
    if ((threadIdx.x & 31) == 0) red[threadIdx.x >> 5] = sum;
    __syncthreads();
    if (threadIdx.x == 0) {
        float tsum = 0.f;
        for (int i = 0; i < 8; i++) tsum += red[i];
        atomicAdd(&g_eacc[g], tsum);
    }
}

// ---------------- finalize --------------------------------------------------
__global__ void finalize_kernel(float* out, int out_size) {
    float es = 0.f;
    for (int g = 0; g < G; g++) es += g_eacc[g] / ((float)NN * (NN - 1) * 0.5f);
    es /= (float)G;
    float vq = 1000.0f * g_vqacc / ((float)G * NN * DD);
    float loss = es * 100.0f + vq;      // LAMB_EDGE=1, ALPHA=100, LAMB_NODE=0
    for (int i = 0; i < out_size; i++) out[i] = loss;
}

// ---------------- launch ----------------------------------------------------
extern "C" void kernel_launch(void* const* d_in, const int* in_sizes, int n_in,
                              void* d_out, int out_size) {
    (void)in_sizes; (void)n_in;
    const float* feats = (const float*)d_in[0];
    const int*   src   = (const int*)  d_in[1];
    const int*   dst   = (const int*)  d_in[2];
    const float* W1    = (const float*)d_in[3];
    const float* b1    = (const float*)d_in[4];
    const float* W2    = (const float*)d_in[5];
    const float* b2    = (const float*)d_in[6];
    const float* gamma = (const float*)d_in[7];
    const float* beta  = (const float*)d_in[8];
    const float* dec1W = (const float*)d_in[9];
    const float* dec1b = (const float*)d_in[10];
    const float* cb    = (const float*)d_in[13];
    float* out = (float*)d_out;

    float *pA, *pAdj, *pB1, *pB2, *pQ;
    cudaGetSymbolAddress((void**)&pA,   g_A);
    cudaGetSymbolAddress((void**)&pAdj, g_adj);
    cudaGetSymbolAddress((void**)&pB1,  g_buf1);
    cudaGetSymbolAddress((void**)&pB2,  g_buf2);
    cudaGetSymbolAddress((void**)&pQ,   g_q);

    cudaFuncSetAttribute(argmax_vq_kernel,
                         cudaFuncAttributeMaxDynamicSharedMemorySize, AM_SMEM);

    zero_kernel<<<2048, 256>>>(pA,   (size_t)G * NN * NN);
    zero_kernel<<<2048, 256>>>(pAdj, (size_t)G * NN * NN);
    zero_small_kernel<<<1, 64>>>();

    degree_kernel <<<G, 256>>>(src, dst);
    scatter_kernel<<<G, 256>>>(src, dst);
    count_edges_kernel<<<G, 256>>>();
    norm_codebook_kernel<<<KK, 256>>>(cb);

    // conv1: m = A @ feats  -> buf1
    gemm64_kernel<<<dim3(DD / 64, NN / 64, G), 256>>>(
        pA, feats, nullptr, pB1, NN, DD, NN,
        (size_t)NN * NN, (size_t)NN * DD, (size_t)NN * DD, 0);
    // h1 = relu(m @ W1 + b1) -> buf2
    gemm64_kernel<<<dim3(DD / 64, (G * NN) / 64, 1), 256>>>(
        pB1, W1, b1, pB2, G * NN, DD, DD, 0, 0, 0, 1);
    // layernorm -> buf1
    layernorm_kernel<<<G * NN, 256>>>(pB2, gamma, beta, pB1);
    // conv2: m2 = A @ h1ln -> buf2
    gemm64_kernel<<<dim3(DD / 64, NN / 64, G), 256>>>(
        pA, pB1, nullptr, pB2, NN, DD, NN,
        (size_t)NN * NN, (size_t)NN * DD, (size_t)NN * DD, 0);
    // hf = relu(m2 @ W2 + b2) -> buf1
    gemm64_kernel<<<dim3(DD / 64, (G * NN) / 64, 1), 256>>>(
        pB2, W2, b2, pB1, G * NN, DD, DD, 0, 0, 0, 1);

    // VQ argmax + gather + vq loss
    argmax_vq_kernel<<<(G * NN) / 128, 256, AM_SMEM>>>(pB1, cb);

    // qe = q @ dec1_W + dec1_b -> buf2
    gemm64_kernel<<<dim3(DD / 64, (G * NN) / 64, 1), 256>>>(
        pQ, dec1W, dec1b, pB2, G * NN, DD, DD, 0, 0, 0, 0);

    // fused edge BCE loss (upper-triangular tiles only)
    edge_loss_kernel<<<dim3(36, G), 256>>>(pB2);

    finalize_kernel<<<1, 1>>>(out, out_size);
}

// round 3
// speedup vs baseline: 3.5404x; 3.5398x over previous
#include <cuda_runtime.h>
#include <cuda_bf16.h>
#include <math.h>
#include <stdint.h>

#define G   32
#define NN  512
#define EE  8192
#define DD  256
#define KK  2048

typedef __nv_bfloat16 bf16;

// ---------------- scratch (device globals) ---------------------------------
__device__ float g_rs_out[G * NN];
__device__ float g_rs_in [G * NN];
__device__ float g_A   [(size_t)G * NN * NN];   // 32 MB fp32 normalized adjacency
__device__ float g_adj [(size_t)G * NN * NN];   // 32 MB fp32 binary adj
__device__ bf16  g_Ab  [(size_t)G * NN * NN];   // 16 MB bf16 adjacency
__device__ bf16  g_Xt  [(size_t)G * DD * NN];   // 8 MB  transposed features [g][d][node]
__device__ bf16  g_m   [(size_t)G * NN * DD];   // 8 MB  conv output (bf16 row-major)
__device__ float g_f1  [(size_t)G * NN * DD];   // 16 MB fp32 buffer (h1 / hf)
__device__ bf16  g_hb  [(size_t)G * NN * DD];   // 8 MB  hf bf16
__device__ bf16  g_qb  [(size_t)G * NN * DD];   // 8 MB  gathered codebook bf16
__device__ bf16  g_qe  [(size_t)G * NN * DD];   // 8 MB  decoded qe bf16
__device__ bf16  g_cnb [(size_t)KK * DD];       // 1 MB  normalized codebook bf16 [k][d]
__device__ bf16  g_W1t [DD * DD];
__device__ bf16  g_W2t [DD * DD];
__device__ bf16  g_D1t [DD * DD];
__device__ int   g_idx [G * NN];
__device__ float g_ne  [G];
__device__ float g_eacc[G];
__device__ float g_vqacc;

// ---------------- small utility kernels ------------------------------------
__global__ void zero_kernel(float* p, size_t n) {
    for (size_t i = (size_t)blockIdx.x * blockDim.x + threadIdx.x; i < n;
         i += (size_t)gridDim.x * blockDim.x)
        p[i] = 0.f;
}

__global__ void zero_small_kernel() {
    int t = threadIdx.x;
    if (t < G) g_eacc[t] = 0.f;
    if (t == 0) g_vqacc = 0.f;
}

__global__ void f2b_kernel(const float* __restrict__ in, bf16* __restrict__ out, size_t n) {
    for (size_t i = (size_t)blockIdx.x * blockDim.x + threadIdx.x; i < n;
         i += (size_t)gridDim.x * blockDim.x)
        out[i] = __float2bfloat16(in[i]);
}

// transpose + convert: out[c][r] (bf16) = in[r][c] (f32), batched
__global__ __launch_bounds__(256) void transpose_kernel(
    const float* __restrict__ in, bf16* __restrict__ out,
    int R, int C, size_t sIn, size_t sOut)
{
    __shared__ float tile[32][33];
    int b = blockIdx.z;
    in  += (size_t)b * sIn;
    out += (size_t)b * sOut;
    int r0 = blockIdx.y * 32, c0 = blockIdx.x * 32;
    int tx = threadIdx.x & 31, ty = threadIdx.x >> 5;
#pragma unroll
    for (int i = 0; i < 4; i++) {
        int r = ty + i * 8;
        tile[r][tx] = in[(size_t)(r0 + r) * C + c0 + tx];
    }
    __syncthreads();
#pragma unroll
    for (int i = 0; i < 4; i++) {
        int r = ty + i * 8;
        out[(size_t)(c0 + r) * R + r0 + tx] = __float2bfloat16(tile[tx][r]);
    }
}

// ---------------- degrees / scatter / edge count ---------------------------
__global__ __launch_bounds__(256) void degree_kernel(const int* __restrict__ src,
                                                     const int* __restrict__ dst) {
    int g = blockIdx.x;
    __shared__ int co[NN], ci[NN];
    for (int i = threadIdx.x; i < NN; i += blockDim.x) { co[i] = 0; ci[i] = 0; }
    __syncthreads();
    const int* s = src + g * EE;
    const int* d = dst + g * EE;
    for (int e = threadIdx.x; e < EE; e += blockDim.x) {
        atomicAdd(&co[s[e]], 1);
        atomicAdd(&ci[d[e]], 1);
    }
    __syncthreads();
    for (int i = threadIdx.x; i < NN; i += blockDim.x) {
        g_rs_out[g * NN + i] = rsqrtf((float)max(co[i], 1));
        g_rs_in [g * NN + i] = rsqrtf((float)max(ci[i], 1));
    }
}

__global__ __launch_bounds__(256) void scatter_kernel(const int* __restrict__ src,
                                                      const int* __restrict__ dst) {
    int g = blockIdx.x;
    const int* s = src + g * EE;
    const int* d = dst + g * EE;
    float* A   = g_A   + (size_t)g * NN * NN;
    float* adj = g_adj + (size_t)g * NN * NN;
    for (int e = threadIdx.x; e < EE; e += blockDim.x) {
        int ss = s[e], dd = d[e];
        atomicAdd(&A[dd * NN + ss], g_rs_in[g * NN + dd] * g_rs_out[g * NN + ss]);
        adj[ss * NN + dd] = 1.0f;
    }
}

__global__ __launch_bounds__(256) void count_edges_kernel() {
    int g = blockIdx.x;
    const float* adj = g_adj + (size_t)g * NN * NN;
    float sum = 0.f;
    for (int idx = threadIdx.x; idx < NN * NN; idx += blockDim.x) {
        int i = idx >> 9, j = idx & 511;
        if (j > i) sum += adj[idx];
    }
    __shared__ float red[256];
    red[threadIdx.x] = sum;
    __syncthreads();
    for (int s = 128; s > 0; s >>= 1) {
        if (threadIdx.x < s) red[threadIdx.x] += red[threadIdx.x + s];
        __syncthreads();
    }
    if (threadIdx.x == 0) g_ne[g] = red[0];
}

// ---------------- normalize codebook -> bf16 [k][d] ------------------------
__global__ __launch_bounds__(256) void norm_codebook_kernel(const float* __restrict__ cb) {
    int k = blockIdx.x;
    float v = cb[(size_t)k * DD + threadIdx.x];
    float ss = v * v;
    __shared__ float red[8];
    for (int o = 16; o > 0; o >>= 1) ss += __shfl_down_sync(0xffffffffu, ss, o);
    if ((threadIdx.x & 31) == 0) red[threadIdx.x >> 5] = ss;
    __syncthreads();
    if (threadIdx.x == 0) {
        float t = 0.f;
        for (int i = 0; i < 8; i++) t += red[i];
        red[0] = t;
    }
    __syncthreads();
    float r = rsqrtf(red[0] + 1e-12f);
    g_cnb[(size_t)k * DD + threadIdx.x] = __float2bfloat16(v * r);
}

// ---------------- MMA helpers ----------------------------------------------
__device__ __forceinline__ void mma16816(float c[4], uint32_t a0, uint32_t a1,
                                         uint32_t a2, uint32_t a3,
                                         uint32_t b0, uint32_t b1) {
    asm volatile(
        "mma.sync.aligned.m16n8k16.row.col.f32.bf16.bf16.f32 "
        "{%0,%1,%2,%3}, {%4,%5,%6,%7}, {%8,%9}, {%0,%1,%2,%3};\n"
        : "+f"(c[0]), "+f"(c[1]), "+f"(c[2]), "+f"(c[3])
        : "r"(a0), "r"(a1), "r"(a2), "r"(a3), "r"(b0), "r"(b1));
}

#define LDT 40   // smem row pitch for 32-wide k tiles (bank-conflict free)

// stage a 128x32 bf16 tile (row-major src, leading dim ld) into smem [128][LDT]
__device__ __forceinline__ void stage_tile(const bf16* __restrict__ src, size_t ld,
                                           bf16* __restrict__ dstS) {
    int t = threadIdx.x;
#pragma unroll
    for (int i = 0; i < 2; i++) {
        int idx = t + i * 256;         // 0..511
        int row = idx >> 2;
        int col = (idx & 3) * 8;
        *(uint4*)&dstS[row * LDT + col] =
            *(const uint4*)&src[(size_t)row * ld + col];
    }
}

// compute one 32-wide k tile: acc[4][4][4] over warp tile m64 x n32
__device__ __forceinline__ void mma_ktile(const bf16* As, const bf16* Bs,
                                          int moff, int noff, int kbase,
                                          int lr, int lq, float acc[4][4][4]) {
#pragma unroll
    for (int ks = 0; ks < 2; ks++) {
        int kk = kbase + ks * 16 + 2 * lq;
        uint32_t bfr[4][2];
#pragma unroll
        for (int fn = 0; fn < 4; fn++) {
            const bf16* bp = &Bs[(noff + fn * 8 + lr) * LDT + kk];
            bfr[fn][0] = *(const uint32_t*)bp;
            bfr[fn][1] = *(const uint32_t*)(bp + 8);
        }
#pragma unroll
        for (int fm = 0; fm < 4; fm++) {
            const bf16* ap = &As[(moff + fm * 16 + lr) * LDT + kk];
            uint32_t a0 = *(const uint32_t*)ap;
            uint32_t a1 = *(const uint32_t*)(ap + 8 * LDT);
            uint32_t a2 = *(const uint32_t*)(ap + 8);
            uint32_t a3 = *(const uint32_t*)(ap + 8 * LDT + 8);
#pragma unroll
            for (int fn = 0; fn < 4; fn++)
                mma16816(acc[fm][fn], a0, a1, a2, a3, bfr[fn][0], bfr[fn][1]);
        }
    }
}

// ---------------- generic bf16 HMMA GEMM: C = act(A @ Bt^T + bias) ---------
// A [M,K] bf16 row-major; Bt [N,K] bf16 row-major. 128x128 tile, 8 warps.
__global__ __launch_bounds__(256) void hgemm_kernel(
    const bf16* __restrict__ A, const bf16* __restrict__ Bt,
    const float* __restrict__ bias, float* __restrict__ Cf, bf16* __restrict__ Cb,
    int M, int Ncol, int Kd, size_t sA, size_t sBt, size_t sC, int relu)
{
    __shared__ bf16 As[128 * LDT], Bs[128 * LDT];
    int b = blockIdx.z;
    A  += (size_t)b * sA;
    Bt += (size_t)b * sBt;
    int rowbase = blockIdx.y * 128, colbase = blockIdx.x * 128;
    int t = threadIdx.x, lane = t & 31, wid = t >> 5;
    int lr = lane >> 2, lq = lane & 3;
    int moff = (wid & 1) * 64, noff = (wid >> 1) * 32;

    float acc[4][4][4] = {};
    for (int kt = 0; kt < Kd; kt += 32) {
        stage_tile(A  + (size_t)rowbase * Kd + kt, Kd, As);
        stage_tile(Bt + (size_t)colbase * Kd + kt, Kd, Bs);
        __syncthreads();
        mma_ktile(As, Bs, moff, noff, 0, lr, lq, acc);
        __syncthreads();
    }
#pragma unroll
    for (int fm = 0; fm < 4; fm++)
#pragma unroll
        for (int fn = 0; fn < 4; fn++)
#pragma unroll
            for (int i = 0; i < 4; i++) {
                int row = rowbase + moff + fm * 16 + lr + (i >> 1) * 8;
                int col = colbase + noff + fn * 8 + 2 * lq + (i & 1);
                float v = acc[fm][fn][i];
                if (bias) v += bias[col];
                if (relu) v = fmaxf(v, 0.f);
                size_t o = (size_t)b * sC + (size_t)row * Ncol + col;
                if (Cf) Cf[o] = v;
                if (Cb) Cb[o] = __float2bfloat16(v);
            }
}

// ---------------- layernorm (in-place capable, fp32) ------------------------
__global__ __launch_bounds__(256) void layernorm_kernel(
    const float* __restrict__ x, const float* __restrict__ gamma,
    const float* __restrict__ beta, float* __restrict__ y)
{
    int row = blockIdx.x;
    float v = x[(size_t)row * DD + threadIdx.x];
    __shared__ float red[8];
    float s = v;
    for (int o = 16; o > 0; o >>= 1) s += __shfl_down_sync(0xffffffffu, s, o);
    if ((threadIdx.x & 31) == 0) red[threadIdx.x >> 5] = s;
    __syncthreads();
    if (threadIdx.x == 0) {
        float tt = 0.f;
        for (int i = 0; i < 8; i++) tt += red[i];
        red[0] = tt;
    }
    __syncthreads();
    float mu = red[0] / DD;
    float d = v - mu;
    float s2 = d * d;
    __syncthreads();
    for (int o = 16; o > 0; o >>= 1) s2 += __shfl_down_sync(0xffffffffu, s2, o);
    if ((threadIdx.x & 31) == 0) red[threadIdx.x >> 5] = s2;
    __syncthreads();
    if (threadIdx.x == 0) {
        float tt = 0.f;
        for (int i = 0; i < 8; i++) tt += red[i];
        red[0] = tt;
    }
    __syncthreads();
    float var = red[0] / DD;
    y[(size_t)row * DD + threadIdx.x] =
        d * rsqrtf(var + 1e-5f) * gamma[threadIdx.x] + beta[threadIdx.x];
}

// ---------------- fused VQ argmax (HMMA) + gather + vq loss -----------------
#define LDA2 264
#define AM_SMEM ((128 * LDA2 + 128 * LDT) * 2 + 16 * 128 * 8)
__global__ __launch_bounds__(256) void argmax_vq_kernel(
    const bf16* __restrict__ hfb, const float* __restrict__ hf,
    const float* __restrict__ cb)
{
    extern __shared__ char smraw[];
    bf16*  As   = (bf16*)smraw;                       // [128][264]
    bf16*  Bs   = As + 128 * LDA2;                    // [128][40]
    float* redv = (float*)(Bs + 128 * LDT);           // [16][128]
    int*   redi = (int*)(redv + 16 * 128);            // [16][128]
    int rowbase = blockIdx.x * 128;
    int t = threadIdx.x, lane = t & 31, wid = t >> 5;
    int lr = lane >> 2, lq = lane & 3;
    int moff = (wid >> 2) * 64, noff = (wid & 3) * 32;

    // stage full 128x256 hf panel (bf16)
    const bf16* src = hfb + (size_t)rowbase * DD;
#pragma unroll
    for (int i = 0; i < 16; i++) {
        int idx = t + i * 256;
        int row = idx >> 5;
        int col = (idx & 31) * 8;
        *(uint4*)&As[row * LDA2 + col] = *(const uint4*)&src[(size_t)row * DD + col];
    }
    __syncthreads();

    float best[4][2];
    int   bidx[4][2];
#pragma unroll
    for (int fm = 0; fm < 4; fm++)
#pragma unroll
        for (int h = 0; h < 2; h++) { best[fm][h] = -1e30f; bidx[fm][h] = 0; }

    for (int cc = 0; cc < KK / 128; cc++) {
        float acc[4][4][4] = {};
        for (int kt = 0; kt < DD; kt += 32) {
            stage_tile(g_cnb + (size_t)(cc * 128) * DD + kt, DD, Bs);
            __syncthreads();
            // A fragments read at column kt within the resident panel
#pragma unroll
            for (int ks = 0; ks < 2; ks++) {
                int kk = kt + ks * 16 + 2 * lq;
                int kb = ks * 16 + 2 * lq;
                uint32_t bfr[4][2];
#pragma unroll
                for (int fn = 0; fn < 4; fn++) {
                    const bf16* bp = &Bs[(noff + fn * 8 + lr) * LDT + kb];
                    bfr[fn][0] = *(const uint32_t*)bp;
                    bfr[fn][1] = *(const uint32_t*)(bp + 8);
                }
#pragma unroll
                for (int fm = 0; fm < 4; fm++) {
                    const bf16* ap = &As[(moff + fm * 16 + lr) * LDA2 + kk];
                    uint32_t a0 = *(const uint32_t*)ap;
                    uint32_t a1 = *(const uint32_t*)(ap + 8 * LDA2);
                    uint32_t a2 = *(const uint32_t*)(ap + 8);
                    uint32_t a3 = *(const uint32_t*)(ap + 8 * LDA2 + 8);
#pragma unroll
                    for (int fn = 0; fn < 4; fn++)
                        mma16816(acc[fm][fn], a0, a1, a2, a3, bfr[fn][0], bfr[fn][1]);
                }
            }
            __syncthreads();
        }
        // running argmax (ascending col order preserves first-max rule)
#pragma unroll
        for (int fm = 0; fm < 4; fm++)
#pragma unroll
            for (int fn = 0; fn < 4; fn++) {
                int colb = cc * 128 + noff + fn * 8 + 2 * lq;
                float* c = acc[fm][fn];
                if (c[0] > best[fm][0]) { best[fm][0] = c[0]; bidx[fm][0] = colb; }
                if (c[1] > best[fm][0]) { best[fm][0] = c[1]; bidx[fm][0] = colb + 1; }
                if (c[2] > best[fm][1]) { best[fm][1] = c[2]; bidx[fm][1] = colb; }
                if (c[3] > best[fm][1]) { best[fm][1] = c[3]; bidx[fm][1] = colb + 1; }
            }
    }
    // cross-thread reduce: 16 owners per row
    int owner = (wid & 3) * 4 + lq;
#pragma unroll
    for (int fm = 0; fm < 4; fm++)
#pragma unroll
        for (int h = 0; h < 2; h++) {
            int lrow = moff + fm * 16 + lr + h * 8;
            redv[owner * 128 + lrow] = best[fm][h];
            redi[owner * 128 + lrow] = bidx[fm][h];
        }
    __syncthreads();
    if (t < 128) {
        float bv = redv[t];
        int bi = redi[t];
        for (int x = 1; x < 16; x++) {
            float v = redv[x * 128 + t];
            int ii = redi[x * 128 + t];
            if (v > bv || (v == bv && ii < bi)) { bv = v; bi = ii; }
        }
        g_idx[rowbase + t] = bi;
        redi[t] = bi;
    }
    __syncthreads();
    // gather q (bf16) + fp32 vq partial
    {
        int r = t >> 1, half = t & 1;
        int idx = redi[r];
        const float* crow = cb + (size_t)idx * DD + half * 128;
        const float* hrow = hf + (size_t)(rowbase + r) * DD + half * 128;
        bf16* qrow = g_qb + (size_t)(rowbase + r) * DD + half * 128;
        float s = 0.f;
        for (int d = 0; d < 128; d++) {
            float cv = crow[d];
            float df = cv - hrow[d];
            s += df * df;
            qrow[d] = __float2bfloat16(cv);
        }
        for (int o = 16; o > 0; o >>= 1) s += __shfl_down_sync(0xffffffffu, s, o);
        if ((t & 31) == 0) atomicAdd(&g_vqacc, s);
    }
}

// ---------------- fused edge loss: HMMA logits tile + BCE -------------------
__global__ __launch_bounds__(256) void edge_loss_kernel(const bf16* __restrict__ qe) {
    __shared__ bf16 As[128 * LDT], Bs[128 * LDT];
    int g = blockIdx.y;
    int tlin = blockIdx.x;                    // 0..9 upper-tri 4x4 tile index
    int bi = 0, rem = tlin;
    while (rem >= 4 - bi) { rem -= 4 - bi; bi++; }
    int bj = bi + rem;
    const bf16* Q = qe + (size_t)g * NN * DD;
    const float* adj = g_adj + (size_t)g * NN * NN;
    float ne = g_ne[g];
    float pw = ((float)NN * NN * 0.5f - ne) / (ne + 1e-6f);

    int t = threadIdx.x, lane = t & 31, wid = t >> 5;
    int lr = lane >> 2, lq = lane & 3;
    int moff = (wid & 1) * 64, noff = (wid >> 1) * 32;
    int rowbase = bi * 128, colbase = bj * 128;

    float acc[4][4][4] = {};
    for (int kt = 0; kt < DD; kt += 32) {
        stage_tile(Q + (size_t)rowbase * DD + kt, DD, As);
        stage_tile(Q + (size_t)colbase * DD + kt, DD, Bs);
        __syncthreads();
        mma_ktile(As, Bs, moff, noff, 0, lr, lq, acc);
        __syncthreads();
    }
    float sum = 0.f;
#pragma unroll
    for (int fm = 0; fm < 4; fm++)
#pragma unroll
        for (int fn = 0; fn < 4; fn++)
#pragma unroll
            for (int i = 0; i < 4; i++) {
                int row = rowbase + moff + fm * 16 + lr + (i >> 1) * 8;
                int col = colbase + noff + fn * 8 + 2 * lq + (i & 1);
                if (row < col) {
                    float x = acc[fm][fn][i];
                    float l1 = log1pf(__expf(-fabsf(x)));
                    float sp_p = fmaxf(x, 0.f) + l1;
                    float sp_n = fmaxf(-x, 0.f) + l1;
                    float a = adj[row * NN + col];
                    sum += pw * a * sp_n + (1.f - a) * sp_p;
                }
            }
    for (int o = 16; o > 0; o >>= 1) sum += __shfl_down_sync(0xffffffffu, sum, o);
    __shared__ float red[8];
    if ((t & 31) == 0) red[t >> 5] = sum;
    __syncthreads();
    if (t == 0) {
        float ts = 0.f;
        for (int i = 0; i < 8; i++) ts += red[i];
        atomicAdd(&g_eacc[g], ts);
    }
}

// ---------------- finalize --------------------------------------------------
__global__ void finalize_kernel(float* out, int out_size) {
    float es = 0.f;
    for (int g = 0; g < G; g++) es += g_eacc[g] / ((float)NN * (NN - 1) * 0.5f);
    es /= (float)G;
    float vq = 1000.0f * g_vqacc / ((float)G * NN * DD);
    float loss = es * 100.0f + vq;
    for (int i = 0; i < out_size; i++) out[i] = loss;
}

// ---------------- launch ----------------------------------------------------
extern "C" void kernel_launch(void* const* d_in, const int* in_sizes, int n_in,
                              void* d_out, int out_size) {
    (void)in_sizes; (void)n_in;
    const float* feats = (const float*)d_in[0];
    const int*   src   = (const int*)  d_in[1];
    const int*   dst   = (const int*)  d_in[2];
    const float* W1    = (const float*)d_in[3];
    const float* b1    = (const float*)d_in[4];
    const float* W2    = (const float*)d_in[5];
    const float* b2    = (const float*)d_in[6];
    const float* gamma = (const float*)d_in[7];
    const float* beta  = (const float*)d_in[8];
    const float* dec1W = (const float*)d_in[9];
    const float* dec1b = (const float*)d_in[10];
    const float* cb    = (const float*)d_in[13];
    float* out = (float*)d_out;

    float *pA, *pAdj, *pF1;
    bf16 *pAb, *pXt, *pM, *pHb, *pQb, *pQe, *pW1t, *pW2t, *pD1t;
    cudaGetSymbolAddress((void**)&pA,   g_A);
    cudaGetSymbolAddress((void**)&pAdj, g_adj);
    cudaGetSymbolAddress((void**)&pF1,  g_f1);
    cudaGetSymbolAddress((void**)&pAb,  g_Ab);
    cudaGetSymbolAddress((void**)&pXt,  g_Xt);
    cudaGetSymbolAddress((void**)&pM,   g_m);
    cudaGetSymbolAddress((void**)&pHb,  g_hb);
    cudaGetSymbolAddress((void**)&pQb,  g_qb);
    cudaGetSymbolAddress((void**)&pQe,  g_qe);
    cudaGetSymbolAddress((void**)&pW1t, g_W1t);
    cudaGetSymbolAddress((void**)&pW2t, g_W2t);
    cudaGetSymbolAddress((void**)&pD1t, g_D1t);

    cudaFuncSetAttribute(argmax_vq_kernel,
                         cudaFuncAttributeMaxDynamicSharedMemorySize, AM_SMEM);

    zero_kernel<<<2048, 256>>>(pA,   (size_t)G * NN * NN);
    zero_kernel<<<2048, 256>>>(pAdj, (size_t)G * NN * NN);
    zero_small_kernel<<<1, 64>>>();

    degree_kernel <<<G, 256>>>(src, dst);
    scatter_kernel<<<G, 256>>>(src, dst);
    count_edges_kernel<<<G, 256>>>();
    norm_codebook_kernel<<<KK, 256>>>(cb);

    // conversions / transposes
    f2b_kernel<<<2048, 256>>>(pA, pAb, (size_t)G * NN * NN);
    transpose_kernel<<<dim3(DD / 32, NN / 32, G), 256>>>(
        feats, pXt, NN, DD, (size_t)NN * DD, (size_t)NN * DD);
    transpose_kernel<<<dim3(DD / 32, DD / 32, 1), 256>>>(W1,    pW1t, DD, DD, 0, 0);
    transpose_kernel<<<dim3(DD / 32, DD / 32, 1), 256>>>(W2,    pW2t, DD, DD, 0, 0);
    transpose_kernel<<<dim3(DD / 32, DD / 32, 1), 256>>>(dec1W, pD1t, DD, DD, 0, 0);

    // conv1: m = Ab @ Xt^T  (bf16 out)
    hgemm_kernel<<<dim3(DD / 128, NN / 128, G), 256>>>(
        pAb, pXt, nullptr, nullptr, pM, NN, DD, NN,
        (size_t)NN * NN, (size_t)DD * NN, (size_t)NN * DD, 0);
    // h1 = relu(m @ W1 + b1)  (fp32 out)
    hgemm_kernel<<<dim3(DD / 128, (G * NN) / 128, 1), 256>>>(
        pM, pW1t, b1, pF1, nullptr, G * NN, DD, DD, 0, 0, 0, 1);
    // layernorm (in-place fp32)
    layernorm_kernel<<<G * NN, 256>>>(pF1, gamma, beta, pF1);
    // transpose ln output -> Xt (bf16)
    transpose_kernel<<<dim3(DD / 32, NN / 32, G), 256>>>(
        pF1, pXt, NN, DD, (size_t)NN * DD, (size_t)NN * DD);
    // conv2: m2 = Ab @ Xt^T  (bf16 out)
    hgemm_kernel<<<dim3(DD / 128, NN / 128, G), 256>>>(
        pAb, pXt, nullptr, nullptr, pM, NN, DD, NN,
        (size_t)NN * NN, (size_t)DD * NN, (size_t)NN * DD, 0);
    // hf = relu(m2 @ W2 + b2)  (fp32 + bf16 out)
    hgemm_kernel<<<dim3(DD / 128, (G * NN) / 128, 1), 256>>>(
        pM, pW2t, b2, pF1, pHb, G * NN, DD, DD, 0, 0, 0, 1);

    // VQ argmax + gather + vq loss
    argmax_vq_kernel<<<(G * NN) / 128, 256, AM_SMEM>>>(pHb, pF1, cb);

    // qe = q @ dec1_W + dec1_b  (bf16 out)
    hgemm_kernel<<<dim3(DD / 128, (G * NN) / 128, 1), 256>>>(
        pQb, pD1t, dec1b, nullptr, pQe, G * NN, DD, DD, 0, 0, 0, 0);

    // fused edge BCE loss (upper-triangular 128x128 tiles)
    edge_loss_kernel<<<dim3(10, G), 256>>>(pQe);

    finalize_kernel<<<1, 1>>>(out, out_size);
}

// round 4
// speedup vs baseline: 4.2070x; 1.1883x over previous
#include <cuda_runtime.h>
#include <cuda_bf16.h>
#include <math.h>
#include <stdint.h>

#define G   32
#define NN  512
#define EE  8192
#define DD  256
#define KK  2048

typedef __nv_bfloat16 bf16;

#define LDP 264                       // smem panel pitch (elements)
#define PANEL_ELEMS (128 * LDP)       // one 128x256 panel (padded)
#define PANEL_BYTES (PANEL_ELEMS * 2) // 67584 B

// ---------------- scratch (device globals) ---------------------------------
__device__ float g_A   [(size_t)G * NN * NN];   // 32 MB fp32 normalized adjacency
__device__ bf16  g_Ab  [(size_t)G * NN * NN];   // 16 MB bf16 adjacency (A[d][s])
__device__ bf16  g_Xt  [(size_t)G * DD * NN];   // 8 MB  transposed activations
__device__ bf16  g_m   [(size_t)G * NN * DD];   // 8 MB  conv output bf16
__device__ float g_f1  [(size_t)G * NN * DD];   // 16 MB fp32 buffer
__device__ bf16  g_hb  [(size_t)G * NN * DD];   // 8 MB  hf bf16
__device__ bf16  g_qb  [(size_t)G * NN * DD];   // 8 MB  gathered codebook bf16
__device__ bf16  g_qe  [(size_t)G * NN * DD];   // 8 MB  decoded qe bf16
__device__ bf16  g_cnb [(size_t)KK * DD];       // 1 MB  normalized codebook bf16
__device__ bf16  g_W1t [DD * DD];
__device__ bf16  g_W2t [DD * DD];
__device__ bf16  g_D1t [DD * DD];
__device__ int   g_idx [G * NN];
__device__ float g_ne  [G];
__device__ float g_eacc[G];
__device__ float g_vqacc;

// ---------------- cp.async helpers -----------------------------------------
__device__ __forceinline__ void cpasync16(void* smem, const void* gptr) {
    uint32_t a = (uint32_t)__cvta_generic_to_shared(smem);
    asm volatile("cp.async.cg.shared.global [%0], [%1], 16;\n" :: "r"(a), "l"(gptr));
}
#define CP_COMMIT() asm volatile("cp.async.commit_group;\n" ::: "memory")
#define CP_WAIT0()  asm volatile("cp.async.wait_group 0;\n" ::: "memory")

// stage a 128x256 bf16 panel (row-major src, leading dim ld) into smem [128][LDP]
__device__ __forceinline__ void stage_panel(const bf16* __restrict__ src, size_t ld,
                                            bf16* __restrict__ dstS) {
    int t = threadIdx.x;
#pragma unroll
    for (int i = 0; i < 16; i++) {
        int idx = t + i * 256;          // 0..4095
        int r = idx >> 5;               // 32 x 16B chunks per row
        int c = (idx & 31) * 8;
        cpasync16(&dstS[r * LDP + c], &src[(size_t)r * ld + c]);
    }
}

// ---------------- MMA core --------------------------------------------------
__device__ __forceinline__ void mma16816(float c[4], uint32_t a0, uint32_t a1,
                                         uint32_t a2, uint32_t a3,
                                         uint32_t b0, uint32_t b1) {
    asm volatile(
        "mma.sync.aligned.m16n8k16.row.col.f32.bf16.bf16.f32 "
        "{%0,%1,%2,%3}, {%4,%5,%6,%7}, {%8,%9}, {%0,%1,%2,%3};\n"
        : "+f"(c[0]), "+f"(c[1]), "+f"(c[2]), "+f"(c[3])
        : "r"(a0), "r"(a1), "r"(a2), "r"(a3), "r"(b0), "r"(b1));
}

// full 256-K panel compute: warp tile m64 x n32, acc[4][4][4]
__device__ __forceinline__ void mma_panel(const bf16* As, const bf16* Bs,
                                          int moff, int noff,
                                          int lr, int lq, float acc[4][4][4]) {
#pragma unroll
    for (int kt = 0; kt < 256; kt += 16) {
        int kk = kt + 2 * lq;
        uint32_t bfr[4][2];
#pragma unroll
        for (int fn = 0; fn < 4; fn++) {
            const bf16* bp = &Bs[(noff + fn * 8 + lr) * LDP + kk];
            bfr[fn][0] = *(const uint32_t*)bp;
            bfr[fn][1] = *(const uint32_t*)(bp + 8);
        }
#pragma unroll
        for (int fm = 0; fm < 4; fm++) {
            const bf16* ap = &As[(moff + fm * 16 + lr) * LDP + kk];
            uint32_t a0 = *(const uint32_t*)ap;
            uint32_t a1 = *(const uint32_t*)(ap + 8 * LDP);
            uint32_t a2 = *(const uint32_t*)(ap + 8);
            uint32_t a3 = *(const uint32_t*)(ap + 8 * LDP + 8);
#pragma unroll
            for (int fn = 0; fn < 4; fn++)
                mma16816(acc[fm][fn], a0, a1, a2, a3, bfr[fn][0], bfr[fn][1]);
        }
    }
}

// ---------------- fused setup: zero A, degrees, scatter, convert, count -----
__global__ __launch_bounds__(256) void setup_kernel(const int* __restrict__ src,
                                                    const int* __restrict__ dst) {
    int g = blockIdx.x, t = threadIdx.x;
    __shared__ int co[NN], ci[NN];
    __shared__ float rso[NN], rsi[NN];
    __shared__ float redc[8];
    float* A = g_A + (size_t)g * NN * NN;
    float4* A4 = (float4*)A;
    for (int i = t; i < NN; i += 256) { co[i] = 0; ci[i] = 0; }
    for (int i = t; i < NN * NN / 4; i += 256) A4[i] = make_float4(0.f, 0.f, 0.f, 0.f);
    __syncthreads();
    const int* s = src + g * EE;
    const int* d = dst + g * EE;
    for (int e = t; e < EE; e += 256) {
        atomicAdd(&co[s[e]], 1);
        atomicAdd(&ci[d[e]], 1);
    }
    __syncthreads();
    for (int i = t; i < NN; i += 256) {
        rso[i] = rsqrtf((float)max(co[i], 1));
        rsi[i] = rsqrtf((float)max(ci[i], 1));
    }
    __syncthreads();
    for (int e = t; e < EE; e += 256) {
        int ss = s[e], dd = d[e];
        atomicAdd(&A[dd * NN + ss], rsi[dd] * rso[ss]);
    }
    __syncthreads();
    // convert to bf16 + count strict-lower-triangle nonzeros (== upper-tri of adj)
    bf16* Ab = g_Ab + (size_t)g * NN * NN;
    __nv_bfloat162* Ab2 = (__nv_bfloat162*)Ab;
    float cnt = 0.f;
    for (int i = t; i < NN * NN / 4; i += 256) {
        float4 v = A4[i];
        Ab2[i * 2]     = __floats2bfloat162_rn(v.x, v.y);
        Ab2[i * 2 + 1] = __floats2bfloat162_rn(v.z, v.w);
        int base = i * 4;
        int row = base >> 9, col = base & 511;
        if (row > col + 0 && v.x != 0.f) cnt += 1.f;
        if (row > col + 1 && v.y != 0.f) cnt += 1.f;
        if (row > col + 2 && v.z != 0.f) cnt += 1.f;
        if (row > col + 3 && v.w != 0.f) cnt += 1.f;
    }
    for (int o = 16; o > 0; o >>= 1) cnt += __shfl_down_sync(0xffffffffu, cnt, o);
    if ((t & 31) == 0) redc[t >> 5] = cnt;
    __syncthreads();
    if (t == 0) {
        float tot = 0.f;
        for (int i = 0; i < 8; i++) tot += redc[i];
        g_ne[g] = tot;
        g_eacc[g] = 0.f;
        if (g == 0) g_vqacc = 0.f;
    }
}

// ---------------- normalize codebook -> bf16 [k][d] ------------------------
__global__ __launch_bounds__(256) void norm_codebook_kernel(const float* __restrict__ cb) {
    int k = blockIdx.x;
    float v = cb[(size_t)k * DD + threadIdx.x];
    float ss = v * v;
    __shared__ float red[8];
    for (int o = 16; o > 0; o >>= 1) ss += __shfl_down_sync(0xffffffffu, ss, o);
    if ((threadIdx.x & 31) == 0) red[threadIdx.x >> 5] = ss;
    __syncthreads();
    if (threadIdx.x == 0) {
        float t = 0.f;
        for (int i = 0; i < 8; i++) t += red[i];
        red[0] = t;
    }
    __syncthreads();
    float r = rsqrtf(red[0] + 1e-12f);
    g_cnb[(size_t)k * DD + threadIdx.x] = __float2bfloat16(v * r);
}

// ---------------- transpose + convert ---------------------------------------
__global__ __launch_bounds__(256) void transpose_kernel(
    const float* __restrict__ in, bf16* __restrict__ out,
    int R, int C, size_t sIn, size_t sOut)
{
    __shared__ float tile[32][33];
    int b = blockIdx.z;
    in  += (size_t)b * sIn;
    out += (size_t)b * sOut;
    int r0 = blockIdx.y * 32, c0 = blockIdx.x * 32;
    int tx = threadIdx.x & 31, ty = threadIdx.x >> 5;
#pragma unroll
    for (int i = 0; i < 4; i++) {
        int r = ty + i * 8;
        tile[r][tx] = in[(size_t)(r0 + r) * C + c0 + tx];
    }
    __syncthreads();
#pragma unroll
    for (int i = 0; i < 4; i++) {
        int r = ty + i * 8;
        out[(size_t)(c0 + r) * R + r0 + tx] = __float2bfloat16(tile[tx][r]);
    }
}

// ---------------- generic bf16 HMMA GEMM: C = act(A @ Bt^T + bias) ---------
__global__ __launch_bounds__(256) void hgemm_kernel(
    const bf16* __restrict__ A, const bf16* __restrict__ Bt,
    const float* __restrict__ bias, float* __restrict__ Cf, bf16* __restrict__ Cb,
    int M, int Ncol, int Kd, size_t sA, size_t sBt, size_t sC, int relu)
{
    extern __shared__ bf16 dynsm[];
    bf16* As = dynsm;
    bf16* Bs = dynsm + PANEL_ELEMS;
    int b = blockIdx.z;
    A  += (size_t)b * sA;
    Bt += (size_t)b * sBt;
    int rowbase = blockIdx.y * 128, colbase = blockIdx.x * 128;
    int t = threadIdx.x, lane = t & 31, wid = t >> 5;
    int lr = lane >> 2, lq = lane & 3;
    int moff = (wid & 1) * 64, noff = (wid >> 1) * 32;

    float acc[4][4][4] = {};
    for (int p = 0; p < Kd; p += 256) {
        stage_panel(A  + (size_t)rowbase * Kd + p, Kd, As);
        stage_panel(Bt + (size_t)colbase * Kd + p, Kd, Bs);
        CP_COMMIT();
        CP_WAIT0();
        __syncthreads();
        mma_panel(As, Bs, moff, noff, lr, lq, acc);
        if (p + 256 < Kd) __syncthreads();
    }
#pragma unroll
    for (int fm = 0; fm < 4; fm++)
#pragma unroll
        for (int fn = 0; fn < 4; fn++)
#pragma unroll
            for (int i = 0; i < 4; i++) {
                int row = rowbase + moff + fm * 16 + lr + (i >> 1) * 8;
                int col = colbase + noff + fn * 8 + 2 * lq + (i & 1);
                float v = acc[fm][fn][i];
                if (bias) v += bias[col];
                if (relu) v = fmaxf(v, 0.f);
                size_t o = (size_t)b * sC + (size_t)row * Ncol + col;
                if (Cf) Cf[o] = v;
                if (Cb) Cb[o] = __float2bfloat16(v);
            }
}

// ---------------- layernorm (fp32) ------------------------------------------
__global__ __launch_bounds__(256) void layernorm_kernel(
    const float* __restrict__ x, const float* __restrict__ gamma,
    const float* __restrict__ beta, float* __restrict__ y)
{
    int row = blockIdx.x;
    float v = x[(size_t)row * DD + threadIdx.x];
    __shared__ float red[8];
    float s = v;
    for (int o = 16; o > 0; o >>= 1) s += __shfl_down_sync(0xffffffffu, s, o);
    if ((threadIdx.x & 31) == 0) red[threadIdx.x >> 5] = s;
    __syncthreads();
    if (threadIdx.x == 0) {
        float tt = 0.f;
        for (int i = 0; i < 8; i++) tt += red[i];
        red[0] = tt;
    }
    __syncthreads();
    float mu = red[0] / DD;
    float d = v - mu;
    float s2 = d * d;
    __syncthreads();
    for (int o = 16; o > 0; o >>= 1) s2 += __shfl_down_sync(0xffffffffu, s2, o);
    if ((threadIdx.x & 31) == 0) red[threadIdx.x >> 5] = s2;
    __syncthreads();
    if (threadIdx.x == 0) {
        float tt = 0.f;
        for (int i = 0; i < 8; i++) tt += red[i];
        red[0] = tt;
    }
    __syncthreads();
    float var = red[0] / DD;
    y[(size_t)row * DD + threadIdx.x] =
        d * rsqrtf(var + 1e-5f) * gamma[threadIdx.x] + beta[threadIdx.x];
}

// ---------------- fused VQ argmax (double-buffered) + gather + vq loss ------
#define AM_SMEM (3 * PANEL_BYTES + 16 * 128 * 8)
__global__ __launch_bounds__(256, 1) void argmax_vq_kernel(
    const bf16* __restrict__ hfb, const float* __restrict__ hf,
    const float* __restrict__ cb)
{
    extern __shared__ char smraw[];
    bf16*  As   = (bf16*)smraw;                    // hf panel, resident
    bf16*  Bs0  = As + PANEL_ELEMS;
    bf16*  Bs1  = Bs0 + PANEL_ELEMS;
    float* redv = (float*)(Bs1 + PANEL_ELEMS);     // [16][128]
    int*   redi = (int*)(redv + 16 * 128);         // [16][128]
    int rowbase = blockIdx.x * 128;
    int t = threadIdx.x, lane = t & 31, wid = t >> 5;
    int lr = lane >> 2, lq = lane & 3;
    int moff = (wid >> 2) * 64, noff = (wid & 3) * 32;

    stage_panel(hfb + (size_t)rowbase * DD, DD, As);
    stage_panel(g_cnb, DD, Bs0);
    CP_COMMIT();
    CP_WAIT0();
    __syncthreads();

    float best[4][2];
    int   bidx[4][2];
#pragma unroll
    for (int fm = 0; fm < 4; fm++)
#pragma unroll
        for (int h = 0; h < 2; h++) { best[fm][h] = -1e30f; bidx[fm][h] = 0; }

    for (int cc = 0; cc < KK / 128; cc++) {
        bf16* Bcur  = (cc & 1) ? Bs1 : Bs0;
        bf16* Bnext = (cc & 1) ? Bs0 : Bs1;
        if (cc + 1 < KK / 128) {
            stage_panel(g_cnb + (size_t)(cc + 1) * 128 * DD, DD, Bnext);
            CP_COMMIT();
        }
        float acc[4][4][4] = {};
        mma_panel(As, Bcur, moff, noff, lr, lq, acc);
#pragma unroll
        for (int fm = 0; fm < 4; fm++)
#pragma unroll
            for (int fn = 0; fn < 4; fn++) {
                int colb = cc * 128 + noff + fn * 8 + 2 * lq;
                float* c = acc[fm][fn];
                if (c[0] > best[fm][0]) { best[fm][0] = c[0]; bidx[fm][0] = colb; }
                if (c[1] > best[fm][0]) { best[fm][0] = c[1]; bidx[fm][0] = colb + 1; }
                if (c[2] > best[fm][1]) { best[fm][1] = c[2]; bidx[fm][1] = colb; }
                if (c[3] > best[fm][1]) { best[fm][1] = c[3]; bidx[fm][1] = colb + 1; }
            }
        CP_WAIT0();
        __syncthreads();
    }
    int owner = (wid & 3) * 4 + lq;
#pragma unroll
    for (int fm = 0; fm < 4; fm++)
#pragma unroll
        for (int h = 0; h < 2; h++) {
            int lrow = moff + fm * 16 + lr + h * 8;
            redv[owner * 128 + lrow] = best[fm][h];
            redi[owner * 128 + lrow] = bidx[fm][h];
        }
    __syncthreads();
    if (t < 128) {
        float bv = redv[t];
        int bi = redi[t];
        for (int x = 1; x < 16; x++) {
            float v = redv[x * 128 + t];
            int ii = redi[x * 128 + t];
            if (v > bv || (v == bv && ii < bi)) { bv = v; bi = ii; }
        }
        g_idx[rowbase + t] = bi;
        redi[t] = bi;
    }
    __syncthreads();
    // gather q (bf16) + fp32 vq partial
    {
        int r = t >> 1, half = t & 1;
        int idx = redi[r];
        const float* crow = cb + (size_t)idx * DD + half * 128;
        const float* hrow = hf + (size_t)(rowbase + r) * DD + half * 128;
        bf16* qrow = g_qb + (size_t)(rowbase + r) * DD + half * 128;
        float s = 0.f;
        for (int d = 0; d < 128; d++) {
            float cv = crow[d];
            float df = cv - hrow[d];
            s += df * df;
            qrow[d] = __float2bfloat16(cv);
        }
        for (int o = 16; o > 0; o >>= 1) s += __shfl_down_sync(0xffffffffu, s, o);
        if ((t & 31) == 0) atomicAdd(&g_vqacc, s);
    }
}

// ---------------- fused edge loss: HMMA logits + BCE ------------------------
__global__ __launch_bounds__(256) void edge_loss_kernel(const bf16* __restrict__ qe) {
    extern __shared__ bf16 dynsm[];
    bf16* As = dynsm;
    bf16* Bs = dynsm + PANEL_ELEMS;
    __shared__ float red[8];
    int g = blockIdx.y;
    int tlin = blockIdx.x;                 // 0..9 upper-tri 4x4 tile index
    int bi = 0, rem = tlin;
    while (rem >= 4 - bi) { rem -= 4 - bi; bi++; }
    int bj = bi + rem;
    const bf16* Q = qe + (size_t)g * NN * DD;
    const unsigned short* AbT = (const unsigned short*)(g_Ab + (size_t)g * NN * NN);
    float ne = g_ne[g];
    float pw = ((float)NN * NN * 0.5f - ne) / (ne + 1e-6f);

    int t = threadIdx.x, lane = t & 31, wid = t >> 5;
    int lr = lane >> 2, lq = lane & 3;
    int moff = (wid & 1) * 64, noff = (wid >> 1) * 32;
    int rowbase = bi * 128, colbase = bj * 128;

    stage_panel(Q + (size_t)rowbase * DD, DD, As);
    stage_panel(Q + (size_t)colbase * DD, DD, Bs);
    CP_COMMIT();
    CP_WAIT0();
    __syncthreads();

    float acc[4][4][4] = {};
    mma_panel(As, Bs, moff, noff, lr, lq, acc);

    float sum = 0.f;
#pragma unroll
    for (int fm = 0; fm < 4; fm++)
#pragma unroll
        for (int fn = 0; fn < 4; fn++)
#pragma unroll
            for (int i = 0; i < 4; i++) {
                int row = rowbase + moff + fm * 16 + lr + (i >> 1) * 8;
                int col = colbase + noff + fn * 8 + 2 * lq + (i & 1);
                if (row < col) {
                    float x = acc[fm][fn][i];
                    float l1 = log1pf(__expf(-fabsf(x)));
                    float sp_p = fmaxf(x, 0.f) + l1;
                    float sp_n = fmaxf(-x, 0.f) + l1;
                    // adj[row][col] == 1  <=>  A[col][row] != 0  (positive sums)
                    float a = (AbT[col * NN + row] != 0) ? 1.f : 0.f;
                    sum += pw * a * sp_n + (1.f - a) * sp_p;
                }
            }
    for (int o = 16; o > 0; o >>= 1) sum += __shfl_down_sync(0xffffffffu, sum, o);
    if ((t & 31) == 0) red[t >> 5] = sum;
    __syncthreads();
    if (t == 0) {
        float ts = 0.f;
        for (int i = 0; i < 8; i++) ts += red[i];
        atomicAdd(&g_eacc[g], ts);
    }
}

// ---------------- finalize --------------------------------------------------
__global__ void finalize_kernel(float* out, int out_size) {
    float es = 0.f;
    for (int g = 0; g < G; g++) es += g_eacc[g] / ((float)NN * (NN - 1) * 0.5f);
    es /= (float)G;
    float vq = 1000.0f * g_vqacc / ((float)G * NN * DD);
    float loss = es * 100.0f + vq;
    for (int i = 0; i < out_size; i++) out[i] = loss;
}

// ---------------- launch ----------------------------------------------------
extern "C" void kernel_launch(void* const* d_in, const int* in_sizes, int n_in,
                              void* d_out, int out_size) {
    (void)in_sizes; (void)n_in;
    const float* feats = (const float*)d_in[0];
    const int*   src   = (const int*)  d_in[1];
    const int*   dst   = (const int*)  d_in[2];
    const float* W1    = (const float*)d_in[3];
    const float* b1    = (const float*)d_in[4];
    const float* W2    = (const float*)d_in[5];
    const float* b2    = (const float*)d_in[6];
    const float* gamma = (const float*)d_in[7];
    const float* beta  = (const float*)d_in[8];
    const float* dec1W = (const float*)d_in[9];
    const float* dec1b = (const float*)d_in[10];
    const float* cb    = (const float*)d_in[13];
    float* out = (float*)d_out;

    float* pF1;
    bf16 *pAb, *pXt, *pM, *pHb, *pQb, *pQe, *pW1t, *pW2t, *pD1t;
    cudaGetSymbolAddress((void**)&pF1,  g_f1);
    cudaGetSymbolAddress((void**)&pAb,  g_Ab);
    cudaGetSymbolAddress((void**)&pXt,  g_Xt);
    cudaGetSymbolAddress((void**)&pM,   g_m);
    cudaGetSymbolAddress((void**)&pHb,  g_hb);
    cudaGetSymbolAddress((void**)&pQb,  g_qb);
    cudaGetSymbolAddress((void**)&pQe,  g_qe);
    cudaGetSymbolAddress((void**)&pW1t, g_W1t);
    cudaGetSymbolAddress((void**)&pW2t, g_W2t);
    cudaGetSymbolAddress((void**)&pD1t, g_D1t);

    const int HG_SMEM = 2 * PANEL_BYTES;
    cudaFuncSetAttribute(hgemm_kernel,
                         cudaFuncAttributeMaxDynamicSharedMemorySize, HG_SMEM);
    cudaFuncSetAttribute(edge_loss_kernel,
                         cudaFuncAttributeMaxDynamicSharedMemorySize, HG_SMEM);
    cudaFuncSetAttribute(argmax_vq_kernel,
                         cudaFuncAttributeMaxDynamicSharedMemorySize, AM_SMEM);

    // setup: zero A, degrees, scatter, bf16 convert, edge count, acc zero
    setup_kernel<<<G, 256>>>(src, dst);
    norm_codebook_kernel<<<KK, 256>>>(cb);

    // transposes / conversions
    transpose_kernel<<<dim3(DD / 32, NN / 32, G), 256>>>(
        feats, pXt, NN, DD, (size_t)NN * DD, (size_t)NN * DD);
    transpose_kernel<<<dim3(DD / 32, DD / 32, 1), 256>>>(W1,    pW1t, DD, DD, 0, 0);
    transpose_kernel<<<dim3(DD / 32, DD / 32, 1), 256>>>(W2,    pW2t, DD, DD, 0, 0);
    transpose_kernel<<<dim3(DD / 32, DD / 32, 1), 256>>>(dec1W, pD1t, DD, DD, 0, 0);

    // conv1: m = Ab @ Xt^T  (bf16 out)
    hgemm_kernel<<<dim3(DD / 128, NN / 128, G), 256, HG_SMEM>>>(
        pAb, pXt, nullptr, nullptr, pM, NN, DD, NN,
        (size_t)NN * NN, (size_t)DD * NN, (size_t)NN * DD, 0);
    // h1 = relu(m @ W1 + b1)  (fp32 out)
    hgemm_kernel<<<dim3(DD / 128, (G * NN) / 128, 1), 256, HG_SMEM>>>(
        pM, pW1t, b1, pF1, nullptr, G * NN, DD, DD, 0, 0, 0, 1);
    // layernorm (in-place fp32)
    layernorm_kernel<<<G * NN, 256>>>(pF1, gamma, beta, pF1);
    transpose_kernel<<<dim3(DD / 32, NN / 32, G), 256>>>(
        pF1, pXt, NN, DD, (size_t)NN * DD, (size_t)NN * DD);
    // conv2
    hgemm_kernel<<<dim3(DD / 128, NN / 128, G), 256, HG_SMEM>>>(
        pAb, pXt, nullptr, nullptr, pM, NN, DD, NN,
        (size_t)NN * NN, (size_t)DD * NN, (size_t)NN * DD, 0);
    // hf = relu(m2 @ W2 + b2)  (fp32 + bf16 out)
    hgemm_kernel<<<dim3(DD / 128, (G * NN) / 128, 1), 256, HG_SMEM>>>(
        pM, pW2t, b2, pF1, pHb, G * NN, DD, DD, 0, 0, 0, 1);

    // VQ argmax + gather + vq loss
    argmax_vq_kernel<<<(G * NN) / 128, 256, AM_SMEM>>>(pHb, pF1, cb);

    // qe = q @ dec1_W + dec1_b  (bf16 out)
    hgemm_kernel<<<dim3(DD / 128, (G * NN) / 128, 1), 256, HG_SMEM>>>(
        pQb, pD1t, dec1b, nullptr, pQe, G * NN, DD, DD, 0, 0, 0, 0);

    // fused edge BCE loss
    edge_loss_kernel<<<dim3(10, G), 256, HG_SMEM>>>(pQe);

    finalize_kernel<<<1, 1>>>(out, out_size);
}

// round 5
// speedup vs baseline: 5.0294x; 1.1955x over previous
#include <cuda_runtime.h>
#include <cuda_bf16.h>
#include <math.h>
#include <stdint.h>

#define G   32
#define NN  512
#define EE  8192
#define DD  256
#define KK  2048

typedef __nv_bfloat16 bf16;

// K=128 panels for GEMM kernels (2 blocks/SM)
#define LDQ 136
#define P128_ELEMS (128 * LDQ)
#define P128_BYTES (P128_ELEMS * 2)     // 34816 B
// K=256 panels for argmax kernel (codebook streaming)
#define LDP 264
#define P256_ELEMS (128 * LDP)
#define P256_BYTES (P256_ELEMS * 2)     // 67584 B

// ---------------- scratch (device globals) ---------------------------------
__device__ float g_A   [(size_t)G * NN * NN];   // 32 MB fp32 normalized adjacency
__device__ bf16  g_Ab  [(size_t)G * NN * NN];   // 16 MB bf16 adjacency
__device__ bf16  g_Xt  [(size_t)G * DD * NN];   // 8 MB  transposed activations
__device__ bf16  g_m   [(size_t)G * NN * DD];   // 8 MB  conv output bf16
__device__ float g_f1  [(size_t)G * NN * DD];   // 16 MB fp32 buffer
__device__ bf16  g_hb  [(size_t)G * NN * DD];   // 8 MB  hf bf16
__device__ bf16  g_qb  [(size_t)G * NN * DD];   // 8 MB  gathered codebook bf16
__device__ bf16  g_qe  [(size_t)G * NN * DD];   // 8 MB  decoded qe bf16
__device__ bf16  g_cnb [(size_t)KK * DD];       // 1 MB  normalized codebook bf16
__device__ bf16  g_W1t [DD * DD];
__device__ bf16  g_W2t [DD * DD];
__device__ bf16  g_D1t [DD * DD];
__device__ int   g_idx [G * NN];
__device__ float g_ne  [G];
__device__ float g_eacc[G];
__device__ float g_vqacc;

// ---------------- cp.async helpers -----------------------------------------
__device__ __forceinline__ void cpasync16(void* smem, const void* gptr) {
    uint32_t a = (uint32_t)__cvta_generic_to_shared(smem);
    asm volatile("cp.async.cg.shared.global [%0], [%1], 16;\n" :: "r"(a), "l"(gptr));
}
#define CP_COMMIT() asm volatile("cp.async.commit_group;\n" ::: "memory")
#define CP_WAIT0()  asm volatile("cp.async.wait_group 0;\n" ::: "memory")

// stage 128x128 bf16 tile into smem [128][LDQ]
__device__ __forceinline__ void stage128(const bf16* __restrict__ src, size_t ld,
                                         bf16* __restrict__ dstS) {
    int t = threadIdx.x;
#pragma unroll
    for (int i = 0; i < 8; i++) {
        int idx = t + i * 256;          // 0..2047
        int r = idx >> 4;
        int c = (idx & 15) * 8;
        cpasync16(&dstS[r * LDQ + c], &src[(size_t)r * ld + c]);
    }
}

// stage 128x256 bf16 panel into smem [128][LDP]
__device__ __forceinline__ void stage256(const bf16* __restrict__ src, size_t ld,
                                         bf16* __restrict__ dstS) {
    int t = threadIdx.x;
#pragma unroll
    for (int i = 0; i < 16; i++) {
        int idx = t + i * 256;          // 0..4095
        int r = idx >> 5;
        int c = (idx & 31) * 8;
        cpasync16(&dstS[r * LDP + c], &src[(size_t)r * ld + c]);
    }
}

// ---------------- MMA core --------------------------------------------------
__device__ __forceinline__ void mma16816(float c[4], uint32_t a0, uint32_t a1,
                                         uint32_t a2, uint32_t a3,
                                         uint32_t b0, uint32_t b1) {
    asm volatile(
        "mma.sync.aligned.m16n8k16.row.col.f32.bf16.bf16.f32 "
        "{%0,%1,%2,%3}, {%4,%5,%6,%7}, {%8,%9}, {%0,%1,%2,%3};\n"
        : "+f"(c[0]), "+f"(c[1]), "+f"(c[2]), "+f"(c[3])
        : "r"(a0), "r"(a1), "r"(a2), "r"(a3), "r"(b0), "r"(b1));
}

// K=128 tile compute, pitch LDQ: warp tile m64 x n32
__device__ __forceinline__ void mma_panel128(const bf16* As, const bf16* Bs,
                                             int moff, int noff,
                                             int lr, int lq, float acc[4][4][4]) {
#pragma unroll
    for (int kt = 0; kt < 128; kt += 16) {
        int kk = kt + 2 * lq;
        uint32_t bfr[4][2];
#pragma unroll
        for (int fn = 0; fn < 4; fn++) {
            const bf16* bp = &Bs[(noff + fn * 8 + lr) * LDQ + kk];
            bfr[fn][0] = *(const uint32_t*)bp;
            bfr[fn][1] = *(const uint32_t*)(bp + 8);
        }
#pragma unroll
        for (int fm = 0; fm < 4; fm++) {
            const bf16* ap = &As[(moff + fm * 16 + lr) * LDQ + kk];
            uint32_t a0 = *(const uint32_t*)ap;
            uint32_t a1 = *(const uint32_t*)(ap + 8 * LDQ);
            uint32_t a2 = *(const uint32_t*)(ap + 8);
            uint32_t a3 = *(const uint32_t*)(ap + 8 * LDQ + 8);
#pragma unroll
            for (int fn = 0; fn < 4; fn++)
                mma16816(acc[fm][fn], a0, a1, a2, a3, bfr[fn][0], bfr[fn][1]);
        }
    }
}

// K=256 panel compute, pitch LDP (argmax kernel)
__device__ __forceinline__ void mma_panel256(const bf16* As, const bf16* Bs,
                                             int moff, int noff,
                                             int lr, int lq, float acc[4][4][4]) {
#pragma unroll
    for (int kt = 0; kt < 256; kt += 16) {
        int kk = kt + 2 * lq;
        uint32_t bfr[4][2];
#pragma unroll
        for (int fn = 0; fn < 4; fn++) {
            const bf16* bp = &Bs[(noff + fn * 8 + lr) * LDP + kk];
            bfr[fn][0] = *(const uint32_t*)bp;
            bfr[fn][1] = *(const uint32_t*)(bp + 8);
        }
#pragma unroll
        for (int fm = 0; fm < 4; fm++) {
            const bf16* ap = &As[(moff + fm * 16 + lr) * LDP + kk];
            uint32_t a0 = *(const uint32_t*)ap;
            uint32_t a1 = *(const uint32_t*)(ap + 8 * LDP);
            uint32_t a2 = *(const uint32_t*)(ap + 8);
            uint32_t a3 = *(const uint32_t*)(ap + 8 * LDP + 8);
#pragma unroll
            for (int fn = 0; fn < 4; fn++)
                mma16816(acc[fm][fn], a0, a1, a2, a3, bfr[fn][0], bfr[fn][1]);
        }
    }
}

// ---------------- setup: zero A + accumulators (full chip) ------------------
__global__ __launch_bounds__(256) void zeroA_kernel() {
    float4* A4 = (float4*)g_A;
    size_t n = (size_t)G * NN * NN / 4;
    for (size_t i = (size_t)blockIdx.x * blockDim.x + threadIdx.x; i < n;
         i += (size_t)gridDim.x * blockDim.x)
        A4[i] = make_float4(0.f, 0.f, 0.f, 0.f);
    if (blockIdx.x == 0 && threadIdx.x < G) {
        g_ne[threadIdx.x] = 0.f;
        g_eacc[threadIdx.x] = 0.f;
        if (threadIdx.x == 0) g_vqacc = 0.f;
    }
}

// ---------------- degrees + scatter (per graph) -----------------------------
__global__ __launch_bounds__(512) void deg_scatter_kernel(const int* __restrict__ src,
                                                          const int* __restrict__ dst) {
    int g = blockIdx.x, t = threadIdx.x;
    __shared__ int co[NN], ci[NN];
    __shared__ float rso[NN], rsi[NN];
    for (int i = t; i < NN; i += 512) { co[i] = 0; ci[i] = 0; }
    __syncthreads();
    const int* s = src + g * EE;
    const int* d = dst + g * EE;
    for (int e = t; e < EE; e += 512) {
        atomicAdd(&co[s[e]], 1);
        atomicAdd(&ci[d[e]], 1);
    }
    __syncthreads();
    for (int i = t; i < NN; i += 512) {
        rso[i] = rsqrtf((float)max(co[i], 1));
        rsi[i] = rsqrtf((float)max(ci[i], 1));
    }
    __syncthreads();
    float* A = g_A + (size_t)g * NN * NN;
    for (int e = t; e < EE; e += 512) {
        int ss = s[e], dd = d[e];
        atomicAdd(&A[dd * NN + ss], rsi[dd] * rso[ss]);
    }
}

// ---------------- convert fp32 A -> bf16 + count edges (full chip) ----------
__global__ __launch_bounds__(256) void convert_count_kernel() {
    int g = blockIdx.x >> 3;
    int part = blockIdx.x & 7;
    const float4* A4 = (const float4*)(g_A + (size_t)g * NN * NN);
    __nv_bfloat162* Ab2 = (__nv_bfloat162*)(g_Ab + (size_t)g * NN * NN);
    float cnt = 0.f;
    int base0 = part * 8192;               // float4 index within graph slab
    for (int i = base0 + threadIdx.x; i < base0 + 8192; i += 256) {
        float4 v = A4[i];
        Ab2[2 * i]     = __floats2bfloat162_rn(v.x, v.y);
        Ab2[2 * i + 1] = __floats2bfloat162_rn(v.z, v.w);
        int b = i * 4;
        int row = b >> 9, col = b & 511;
        if (row > col + 0 && v.x != 0.f) cnt += 1.f;
        if (row > col + 1 && v.y != 0.f) cnt += 1.f;
        if (row > col + 2 && v.z != 0.f) cnt += 1.f;
        if (row > col + 3 && v.w != 0.f) cnt += 1.f;
    }
    __shared__ float red[8];
    for (int o = 16; o > 0; o >>= 1) cnt += __shfl_down_sync(0xffffffffu, cnt, o);
    if ((threadIdx.x & 31) == 0) red[threadIdx.x >> 5] = cnt;
    __syncthreads();
    if (threadIdx.x == 0) {
        float tot = 0.f;
        for (int i = 0; i < 8; i++) tot += red[i];
        atomicAdd(&g_ne[g], tot);
    }
}

// ---------------- prep: codebook norm + 3 weight transposes (one kernel) ----
__global__ __launch_bounds__(256) void prep_kernel(const float* __restrict__ cb,
                                                   const float* __restrict__ W1,
                                                   const float* __restrict__ W2,
                                                   const float* __restrict__ D1) {
    __shared__ float tile[32][33];
    int b = blockIdx.x;
    if (b < KK) {
        // codebook row norm -> bf16
        int k = b;
        float v = cb[(size_t)k * DD + threadIdx.x];
        float ss = v * v;
        __shared__ float red[8];
        for (int o = 16; o > 0; o >>= 1) ss += __shfl_down_sync(0xffffffffu, ss, o);
        if ((threadIdx.x & 31) == 0) red[threadIdx.x >> 5] = ss;
        __syncthreads();
        if (threadIdx.x == 0) {
            float t = 0.f;
            for (int i = 0; i < 8; i++) t += red[i];
            red[0] = t;
        }
        __syncthreads();
        float r = rsqrtf(red[0] + 1e-12f);
        g_cnb[(size_t)k * DD + threadIdx.x] = __float2bfloat16(v * r);
    } else {
        int r2 = b - KK;
        int which = r2 >> 6, t2 = r2 & 63;
        const float* srcW = which == 0 ? W1 : which == 1 ? W2 : D1;
        bf16* dstW = which == 0 ? g_W1t : which == 1 ? g_W2t : g_D1t;
        int bx = t2 & 7, by = t2 >> 3;
        int r0 = by * 32, c0 = bx * 32;
        int tx = threadIdx.x & 31, ty = threadIdx.x >> 5;
#pragma unroll
        for (int i = 0; i < 4; i++) {
            int r = ty + i * 8;
            tile[r][tx] = srcW[(size_t)(r0 + r) * DD + c0 + tx];
        }
        __syncthreads();
#pragma unroll
        for (int i = 0; i < 4; i++) {
            int r = ty + i * 8;
            dstW[(size_t)(c0 + r) * DD + r0 + tx] = __float2bfloat16(tile[tx][r]);
        }
    }
}

// ---------------- transpose + convert (feats) -------------------------------
__global__ __launch_bounds__(256) void transpose_kernel(
    const float* __restrict__ in, bf16* __restrict__ out,
    int R, int C, size_t sIn, size_t sOut)
{
    __shared__ float tile[32][33];
    int b = blockIdx.z;
    in  += (size_t)b * sIn;
    out += (size_t)b * sOut;
    int r0 = blockIdx.y * 32, c0 = blockIdx.x * 32;
    int tx = threadIdx.x & 31, ty = threadIdx.x >> 5;
#pragma unroll
    for (int i = 0; i < 4; i++) {
        int r = ty + i * 8;
        tile[r][tx] = in[(size_t)(r0 + r) * C + c0 + tx];
    }
    __syncthreads();
#pragma unroll
    for (int i = 0; i < 4; i++) {
        int r = ty + i * 8;
        out[(size_t)(c0 + r) * R + r0 + tx] = __float2bfloat16(tile[tx][r]);
    }
}

// ---------------- generic bf16 HMMA GEMM: C = act(A @ Bt^T + bias) ---------
__global__ __launch_bounds__(256) void hgemm_kernel(
    const bf16* __restrict__ A, const bf16* __restrict__ Bt,
    const float* __restrict__ bias, float* __restrict__ Cf, bf16* __restrict__ Cb,
    int M, int Ncol, int Kd, size_t sA, size_t sBt, size_t sC, int relu)
{
    extern __shared__ bf16 dynsm[];
    bf16* As = dynsm;
    bf16* Bs = dynsm + P128_ELEMS;
    int b = blockIdx.z;
    A  += (size_t)b * sA;
    Bt += (size_t)b * sBt;
    int rowbase = blockIdx.y * 128, colbase = blockIdx.x * 128;
    int t = threadIdx.x, lane = t & 31, wid = t >> 5;
    int lr = lane >> 2, lq = lane & 3;
    int moff = (wid & 1) * 64, noff = (wid >> 1) * 32;

    float acc[4][4][4] = {};
    for (int p = 0; p < Kd; p += 128) {
        stage128(A  + (size_t)rowbase * Kd + p, Kd, As);
        stage128(Bt + (size_t)colbase * Kd + p, Kd, Bs);
        CP_COMMIT();
        CP_WAIT0();
        __syncthreads();
        mma_panel128(As, Bs, moff, noff, lr, lq, acc);
        if (p + 128 < Kd) __syncthreads();
    }
#pragma unroll
    for (int fm = 0; fm < 4; fm++)
#pragma unroll
        for (int fn = 0; fn < 4; fn++)
#pragma unroll
            for (int i = 0; i < 4; i++) {
                int row = rowbase + moff + fm * 16 + lr + (i >> 1) * 8;
                int col = colbase + noff + fn * 8 + 2 * lq + (i & 1);
                float v = acc[fm][fn][i];
                if (bias) v += bias[col];
                if (relu) v = fmaxf(v, 0.f);
                size_t o = (size_t)b * sC + (size_t)row * Ncol + col;
                if (Cf) Cf[o] = v;
                if (Cb) Cb[o] = __float2bfloat16(v);
            }
}

// ---------------- fused layernorm + transpose -------------------------------
// block = 32 rows of one graph; outputs bf16 Xt[g][d][node]
__global__ __launch_bounds__(256) void ln_transpose_kernel(
    const float* __restrict__ x, const float* __restrict__ gamma,
    const float* __restrict__ beta, bf16* __restrict__ xt)
{
    __shared__ bf16 tile[32][258];
    __shared__ float gsh[DD], bsh[DD];
    int g = blockIdx.x >> 4;
    int rb = (blockIdx.x & 15) * 32;
    int t = threadIdx.x, lane = t & 31, warp = t >> 5;
    gsh[t] = gamma[t];
    bsh[t] = beta[t];
    __syncthreads();
#pragma unroll
    for (int rr = 0; rr < 4; rr++) {
        int row = rb + warp * 4 + rr;
        const float* xr = x + ((size_t)g * NN + row) * DD;
        float v[8];
        float s = 0.f;
#pragma unroll
        for (int j = 0; j < 8; j++) { v[j] = xr[lane + j * 32]; s += v[j]; }
        for (int o = 16; o > 0; o >>= 1) s += __shfl_xor_sync(0xffffffffu, s, o);
        float mu = s / DD;
        float s2 = 0.f;
#pragma unroll
        for (int j = 0; j < 8; j++) { float d = v[j] - mu; s2 += d * d; }
        for (int o = 16; o > 0; o >>= 1) s2 += __shfl_xor_sync(0xffffffffu, s2, o);
        float rs = rsqrtf(s2 / DD + 1e-5f);
#pragma unroll
        for (int j = 0; j < 8; j++) {
            int d = lane + j * 32;
            tile[row - rb][d] = __float2bfloat16((v[j] - mu) * rs * gsh[d] + bsh[d]);
        }
    }
    __syncthreads();
    bf16* dst = xt + (size_t)g * DD * NN;
    for (int i = t; i < 32 * DD; i += 256) {
        int d = i >> 5, node = i & 31;
        dst[(size_t)d * NN + rb + node] = tile[node][d];
    }
}

// ---------------- fused VQ argmax (double-buffered) + gather + vq loss ------
#define AM_SMEM (3 * P256_BYTES + 16 * 128 * 8)
__global__ __launch_bounds__(256, 1) void argmax_vq_kernel(
    const bf16* __restrict__ hfb, const float* __restrict__ hf,
    const float* __restrict__ cb)
{
    extern __shared__ char smraw[];
    bf16*  As   = (bf16*)smraw;                    // hf panel, resident
    bf16*  Bs0  = As + P256_ELEMS;
    bf16*  Bs1  = Bs0 + P256_ELEMS;
    float* redv = (float*)(Bs1 + P256_ELEMS);      // [16][128]
    int*   redi = (int*)(redv + 16 * 128);         // [16][128]
    int rowbase = blockIdx.x * 128;
    int t = threadIdx.x, lane = t & 31, wid = t >> 5;
    int lr = lane >> 2, lq = lane & 3;
    int moff = (wid >> 2) * 64, noff = (wid & 3) * 32;

    stage256(hfb + (size_t)rowbase * DD, DD, As);
    stage256(g_cnb, DD, Bs0);
    CP_COMMIT();
    CP_WAIT0();
    __syncthreads();

    float best[4][2];
    int   bidx[4][2];
#pragma unroll
    for (int fm = 0; fm < 4; fm++)
#pragma unroll
        for (int h = 0; h < 2; h++) { best[fm][h] = -1e30f; bidx[fm][h] = 0; }

    for (int cc = 0; cc < KK / 128; cc++) {
        bf16* Bcur  = (cc & 1) ? Bs1 : Bs0;
        bf16* Bnext = (cc & 1) ? Bs0 : Bs1;
        if (cc + 1 < KK / 128) {
            stage256(g_cnb + (size_t)(cc + 1) * 128 * DD, DD, Bnext);
            CP_COMMIT();
        }
        float acc[4][4][4] = {};
        mma_panel256(As, Bcur, moff, noff, lr, lq, acc);
#pragma unroll
        for (int fm = 0; fm < 4; fm++)
#pragma unroll
            for (int fn = 0; fn < 4; fn++) {
                int colb = cc * 128 + noff + fn * 8 + 2 * lq;
                float* c = acc[fm][fn];
                if (c[0] > best[fm][0]) { best[fm][0] = c[0]; bidx[fm][0] = colb; }
                if (c[1] > best[fm][0]) { best[fm][0] = c[1]; bidx[fm][0] = colb + 1; }
                if (c[2] > best[fm][1]) { best[fm][1] = c[2]; bidx[fm][1] = colb; }
                if (c[3] > best[fm][1]) { best[fm][1] = c[3]; bidx[fm][1] = colb + 1; }
            }
        CP_WAIT0();
        __syncthreads();
    }
    int owner = (wid & 3) * 4 + lq;
#pragma unroll
    for (int fm = 0; fm < 4; fm++)
#pragma unroll
        for (int h = 0; h < 2; h++) {
            int lrow = moff + fm * 16 + lr + h * 8;
            redv[owner * 128 + lrow] = best[fm][h];
            redi[owner * 128 + lrow] = bidx[fm][h];
        }
    __syncthreads();
    if (t < 128) {
        float bv = redv[t];
        int bi = redi[t];
        for (int x = 1; x < 16; x++) {
            float v = redv[x * 128 + t];
            int ii = redi[x * 128 + t];
            if (v > bv || (v == bv && ii < bi)) { bv = v; bi = ii; }
        }
        g_idx[rowbase + t] = bi;
        redi[t] = bi;
    }
    __syncthreads();
    // gather q (bf16) + fp32 vq partial
    {
        int r = t >> 1, half = t & 1;
        int idx = redi[r];
        const float* crow = cb + (size_t)idx * DD + half * 128;
        const float* hrow = hf + (size_t)(rowbase + r) * DD + half * 128;
        bf16* qrow = g_qb + (size_t)(rowbase + r) * DD + half * 128;
        float s = 0.f;
        for (int d = 0; d < 128; d++) {
            float cv = crow[d];
            float df = cv - hrow[d];
            s += df * df;
            qrow[d] = __float2bfloat16(cv);
        }
        for (int o = 16; o > 0; o >>= 1) s += __shfl_down_sync(0xffffffffu, s, o);
        if ((t & 31) == 0) atomicAdd(&g_vqacc, s);
    }
}

// ---------------- fused edge loss: HMMA logits + BCE ------------------------
__global__ __launch_bounds__(256) void edge_loss_kernel(const bf16* __restrict__ qe) {
    extern __shared__ bf16 dynsm[];
    bf16* As = dynsm;
    bf16* Bs = dynsm + P128_ELEMS;
    __shared__ float red[8];
    int g = blockIdx.y;
    int tlin = blockIdx.x;                 // 0..9 upper-tri 4x4 tile index
    int bi = 0, rem = tlin;
    while (rem >= 4 - bi) { rem -= 4 - bi; bi++; }
    int bj = bi + rem;
    const bf16* Q = qe + (size_t)g * NN * DD;
    const unsigned short* AbT = (const unsigned short*)(g_Ab + (size_t)g * NN * NN);
    float ne = g_ne[g];
    float pw = ((float)NN * NN * 0.5f - ne) / (ne + 1e-6f);

    int t = threadIdx.x, lane = t & 31, wid = t >> 5;
    int lr = lane >> 2, lq = lane & 3;
    int moff = (wid & 1) * 64, noff = (wid >> 1) * 32;
    int rowbase = bi * 128, colbase = bj * 128;

    float acc[4][4][4] = {};
    for (int p = 0; p < DD; p += 128) {
        stage128(Q + (size_t)rowbase * DD + p, DD, As);
        stage128(Q + (size_t)colbase * DD + p, DD, Bs);
        CP_COMMIT();
        CP_WAIT0();
        __syncthreads();
        mma_panel128(As, Bs, moff, noff, lr, lq, acc);
        if (p + 128 < DD) __syncthreads();
    }

    float sum = 0.f;
#pragma unroll
    for (int fm = 0; fm < 4; fm++)
#pragma unroll
        for (int fn = 0; fn < 4; fn++)
#pragma unroll
            for (int i = 0; i < 4; i++) {
                int row = rowbase + moff + fm * 16 + lr + (i >> 1) * 8;
                int col = colbase + noff + fn * 8 + 2 * lq + (i & 1);
                if (row < col) {
                    float x = acc[fm][fn][i];
                    float l1 = log1pf(__expf(-fabsf(x)));
                    float sp_p = fmaxf(x, 0.f) + l1;
                    float sp_n = fmaxf(-x, 0.f) + l1;
                    float a = (AbT[col * NN + row] != 0) ? 1.f : 0.f;
                    sum += pw * a * sp_n + (1.f - a) * sp_p;
                }
            }
    for (int o = 16; o > 0; o >>= 1) sum += __shfl_down_sync(0xffffffffu, sum, o);
    if ((t & 31) == 0) red[t >> 5] = sum;
    __syncthreads();
    if (t == 0) {
        float ts = 0.f;
        for (int i = 0; i < 8; i++) ts += red[i];
        atomicAdd(&g_eacc[g], ts);
    }
}

// ---------------- finalize --------------------------------------------------
__global__ void finalize_kernel(float* out, int out_size) {
    float es = 0.f;
    for (int g = 0; g < G; g++) es += g_eacc[g] / ((float)NN * (NN - 1) * 0.5f);
    es /= (float)G;
    float vq = 1000.0f * g_vqacc / ((float)G * NN * DD);
    float loss = es * 100.0f + vq;
    for (int i = 0; i < out_size; i++) out[i] = loss;
}

// ---------------- launch ----------------------------------------------------
extern "C" void kernel_launch(void* const* d_in, const int* in_sizes, int n_in,
                              void* d_out, int out_size) {
    (void)in_sizes; (void)n_in;
    const float* feats = (const float*)d_in[0];
    const int*   src   = (const int*)  d_in[1];
    const int*   dst   = (const int*)  d_in[2];
    const float* W1    = (const float*)d_in[3];
    const float* b1    = (const float*)d_in[4];
    const float* W2    = (const float*)d_in[5];
    const float* b2    = (const float*)d_in[6];
    const float* gamma = (const float*)d_in[7];
    const float* beta  = (const float*)d_in[8];
    const float* dec1W = (const float*)d_in[9];
    const float* dec1b = (const float*)d_in[10];
    const float* cb    = (const float*)d_in[13];
    float* out = (float*)d_out;

    float* pF1;
    bf16 *pAb, *pXt, *pM, *pHb, *pQb, *pQe, *pW1t, *pW2t, *pD1t;
    cudaGetSymbolAddress((void**)&pF1,  g_f1);
    cudaGetSymbolAddress((void**)&pAb,  g_Ab);
    cudaGetSymbolAddress((void**)&pXt,  g_Xt);
    cudaGetSymbolAddress((void**)&pM,   g_m);
    cudaGetSymbolAddress((void**)&pHb,  g_hb);
    cudaGetSymbolAddress((void**)&pQb,  g_qb);
    cudaGetSymbolAddress((void**)&pQe,  g_qe);
    cudaGetSymbolAddress((void**)&pW1t, g_W1t);
    cudaGetSymbolAddress((void**)&pW2t, g_W2t);
    cudaGetSymbolAddress((void**)&pD1t, g_D1t);

    const int HG_SMEM = 2 * P128_BYTES;
    cudaFuncSetAttribute(hgemm_kernel,
                         cudaFuncAttributeMaxDynamicSharedMemorySize, HG_SMEM);
    cudaFuncSetAttribute(edge_loss_kernel,
                         cudaFuncAttributeMaxDynamicSharedMemorySize, HG_SMEM);
    cudaFuncSetAttribute(argmax_vq_kernel,
                         cudaFuncAttributeMaxDynamicSharedMemorySize, AM_SMEM);

    zeroA_kernel<<<2048, 256>>>();
    prep_kernel<<<KK + 192, 256>>>(cb, W1, W2, dec1W);
    transpose_kernel<<<dim3(DD / 32, NN / 32, G), 256>>>(
        feats, pXt, NN, DD, (size_t)NN * DD, (size_t)NN * DD);
    deg_scatter_kernel<<<G, 512>>>(src, dst);
    convert_count_kernel<<<G * 8, 256>>>();

    // conv1: m = Ab @ Xt^T  (bf16 out)
    hgemm_kernel<<<dim3(DD / 128, NN / 128, G), 256, HG_SMEM>>>(
        pAb, pXt, nullptr, nullptr, pM, NN, DD, NN,
        (size_t)NN * NN, (size_t)DD * NN, (size_t)NN * DD, 0);
    // h1 = relu(m @ W1 + b1)  (fp32 out)
    hgemm_kernel<<<dim3(DD / 128, (G * NN) / 128, 1), 256, HG_SMEM>>>(
        pM, pW1t, b1, pF1, nullptr, G * NN, DD, DD, 0, 0, 0, 1);
    // fused layernorm + transpose -> Xt
    ln_transpose_kernel<<<G * 16, 256>>>(pF1, gamma, beta, pXt);
    // conv2
    hgemm_kernel<<<dim3(DD / 128, NN / 128, G), 256, HG_SMEM>>>(
        pAb, pXt, nullptr, nullptr, pM, NN, DD, NN,
        (size_t)NN * NN, (size_t)DD * NN, (size_t)NN * DD, 0);
    // hf = relu(m2 @ W2 + b2)  (fp32 + bf16 out)
    hgemm_kernel<<<dim3(DD / 128, (G * NN) / 128, 1), 256, HG_SMEM>>>(
        pM, pW2t, b2, pF1, pHb, G * NN, DD, DD, 0, 0, 0, 1);

    // VQ argmax + gather + vq loss
    argmax_vq_kernel<<<(G * NN) / 128, 256, AM_SMEM>>>(pHb, pF1, cb);

    // qe = q @ dec1_W + dec1_b  (bf16 out)
    hgemm_kernel<<<dim3(DD / 128, (G * NN) / 128, 1), 256, HG_SMEM>>>(
        pQb, pD1t, dec1b, nullptr, pQe, G * NN, DD, DD, 0, 0, 0, 0);

    // fused edge BCE loss
    edge_loss_kernel<<<dim3(10, G), 256, HG_SMEM>>>(pQe);

    finalize_kernel<<<1, 1>>>(out, out_size);
}

// round 6
// speedup vs baseline: 5.2837x; 1.0506x over previous
#include <cuda_runtime.h>
#include <cuda_bf16.h>
#include <math.h>
#include <stdint.h>

#define G   32
#define NN  512
#define EE  8192
#define DD  256
#define KK  2048

typedef __nv_bfloat16 bf16;

// K=128 panels for GEMM kernels (2 blocks/SM)
#define LDQ 136
#define P128_ELEMS (128 * LDQ)
#define P128_BYTES (P128_ELEMS * 2)     // 34816 B
// K=256 panels for argmax kernel
#define LDP 264
#define P256_ELEMS (128 * LDP)
#define P256_BYTES (P256_ELEMS * 2)     // 67584 B

// ---------------- scratch (device globals) ---------------------------------
__device__ bf16  g_Ab  [(size_t)G * NN * NN];   // 16 MB bf16 adjacency (A[dst][src])
__device__ bf16  g_Xt  [(size_t)G * DD * NN];   // 8 MB  transposed activations
__device__ bf16  g_m   [(size_t)G * NN * DD];   // 8 MB  conv output bf16
__device__ float g_f1  [(size_t)G * NN * DD];   // 16 MB fp32 buffer
__device__ bf16  g_hb  [(size_t)G * NN * DD];   // 8 MB  hf bf16
__device__ bf16  g_qb  [(size_t)G * NN * DD];   // 8 MB  gathered codebook bf16
__device__ bf16  g_qe  [(size_t)G * NN * DD];   // 8 MB  decoded qe bf16
__device__ bf16  g_cnb [(size_t)KK * DD];       // 1 MB  normalized codebook bf16
__device__ bf16  g_W1t [DD * DD];
__device__ bf16  g_W2t [DD * DD];
__device__ bf16  g_D1t [DD * DD];
__device__ int   g_idx [G * NN];
__device__ float g_epos[G];
__device__ float g_eneg[G];
__device__ float g_ecnt[G];
__device__ float g_vqacc;

// ---------------- cp.async helpers -----------------------------------------
__device__ __forceinline__ void cpasync16(void* smem, const void* gptr) {
    uint32_t a = (uint32_t)__cvta_generic_to_shared(smem);
    asm volatile("cp.async.cg.shared.global [%0], [%1], 16;\n" :: "r"(a), "l"(gptr));
}
#define CP_COMMIT() asm volatile("cp.async.commit_group;\n" ::: "memory")
#define CP_WAIT0()  asm volatile("cp.async.wait_group 0;\n" ::: "memory")

__device__ __forceinline__ void stage128(const bf16* __restrict__ src, size_t ld,
                                         bf16* __restrict__ dstS) {
    int t = threadIdx.x;
#pragma unroll
    for (int i = 0; i < 8; i++) {
        int idx = t + i * 256;
        int r = idx >> 4;
        int c = (idx & 15) * 8;
        cpasync16(&dstS[r * LDQ + c], &src[(size_t)r * ld + c]);
    }
}

__device__ __forceinline__ void stage256(const bf16* __restrict__ src, size_t ld,
                                         bf16* __restrict__ dstS) {
    int t = threadIdx.x;
#pragma unroll
    for (int i = 0; i < 16; i++) {
        int idx = t + i * 256;
        int r = idx >> 5;
        int c = (idx & 31) * 8;
        cpasync16(&dstS[r * LDP + c], &src[(size_t)r * ld + c]);
    }
}

// ---------------- MMA core --------------------------------------------------
__device__ __forceinline__ void mma16816(float c[4], uint32_t a0, uint32_t a1,
                                         uint32_t a2, uint32_t a3,
                                         uint32_t b0, uint32_t b1) {
    asm volatile(
        "mma.sync.aligned.m16n8k16.row.col.f32.bf16.bf16.f32 "
        "{%0,%1,%2,%3}, {%4,%5,%6,%7}, {%8,%9}, {%0,%1,%2,%3};\n"
        : "+f"(c[0]), "+f"(c[1]), "+f"(c[2]), "+f"(c[3])
        : "r"(a0), "r"(a1), "r"(a2), "r"(a3), "r"(b0), "r"(b1));
}

__device__ __forceinline__ void mma_panel128(const bf16* As, const bf16* Bs,
                                             int moff, int noff,
                                             int lr, int lq, float acc[4][4][4]) {
#pragma unroll
    for (int kt = 0; kt < 128; kt += 16) {
        int kk = kt + 2 * lq;
        uint32_t bfr[4][2];
#pragma unroll
        for (int fn = 0; fn < 4; fn++) {
            const bf16* bp = &Bs[(noff + fn * 8 + lr) * LDQ + kk];
            bfr[fn][0] = *(const uint32_t*)bp;
            bfr[fn][1] = *(const uint32_t*)(bp + 8);
        }
#pragma unroll
        for (int fm = 0; fm < 4; fm++) {
            const bf16* ap = &As[(moff + fm * 16 + lr) * LDQ + kk];
            uint32_t a0 = *(const uint32_t*)ap;
            uint32_t a1 = *(const uint32_t*)(ap + 8 * LDQ);
            uint32_t a2 = *(const uint32_t*)(ap + 8);
            uint32_t a3 = *(const uint32_t*)(ap + 8 * LDQ + 8);
#pragma unroll
            for (int fn = 0; fn < 4; fn++)
                mma16816(acc[fm][fn], a0, a1, a2, a3, bfr[fn][0], bfr[fn][1]);
        }
    }
}

__device__ __forceinline__ void mma_panel256(const bf16* As, const bf16* Bs,
                                             int moff, int noff,
                                             int lr, int lq, float acc[4][4][4]) {
#pragma unroll
    for (int kt = 0; kt < 256; kt += 16) {
        int kk = kt + 2 * lq;
        uint32_t bfr[4][2];
#pragma unroll
        for (int fn = 0; fn < 4; fn++) {
            const bf16* bp = &Bs[(noff + fn * 8 + lr) * LDP + kk];
            bfr[fn][0] = *(const uint32_t*)bp;
            bfr[fn][1] = *(const uint32_t*)(bp + 8);
        }
#pragma unroll
        for (int fm = 0; fm < 4; fm++) {
            const bf16* ap = &As[(moff + fm * 16 + lr) * LDP + kk];
            uint32_t a0 = *(const uint32_t*)ap;
            uint32_t a1 = *(const uint32_t*)(ap + 8 * LDP);
            uint32_t a2 = *(const uint32_t*)(ap + 8);
            uint32_t a3 = *(const uint32_t*)(ap + 8 * LDP + 8);
#pragma unroll
            for (int fn = 0; fn < 4; fn++)
                mma16816(acc[fm][fn], a0, a1, a2, a3, bfr[fn][0], bfr[fn][1]);
        }
    }
}

// ---------------- zero bf16 A + accumulators (full chip) --------------------
__global__ __launch_bounds__(256) void zeroAb_kernel() {
    uint4* A4 = (uint4*)g_Ab;
    size_t n = (size_t)G * NN * NN * 2 / 16;
    for (size_t i = (size_t)blockIdx.x * blockDim.x + threadIdx.x; i < n;
         i += (size_t)gridDim.x * blockDim.x)
        A4[i] = make_uint4(0u, 0u, 0u, 0u);
    if (blockIdx.x == 0 && threadIdx.x < G) {
        g_epos[threadIdx.x] = 0.f;
        g_eneg[threadIdx.x] = 0.f;
        g_ecnt[threadIdx.x] = 0.f;
        if (threadIdx.x == 0) g_vqacc = 0.f;
    }
}

// ---------------- degrees + scatter (8 blocks per graph, bf16 atomics) ------
__global__ __launch_bounds__(512) void deg_scatter_kernel(const int* __restrict__ src,
                                                          const int* __restrict__ dst) {
    int g = blockIdx.x >> 3;
    int part = blockIdx.x & 7;
    int t = threadIdx.x;
    __shared__ int co[NN], ci[NN];
    __shared__ float rso[NN], rsi[NN];
    for (int i = t; i < NN; i += 512) { co[i] = 0; ci[i] = 0; }
    __syncthreads();
    const int* s = src + g * EE;
    const int* d = dst + g * EE;
    for (int e = t; e < EE; e += 512) {
        atomicAdd(&co[s[e]], 1);
        atomicAdd(&ci[d[e]], 1);
    }
    __syncthreads();
    for (int i = t; i < NN; i += 512) {
        rso[i] = rsqrtf((float)max(co[i], 1));
        rsi[i] = rsqrtf((float)max(ci[i], 1));
    }
    __syncthreads();
    bf16* A = g_Ab + (size_t)g * NN * NN;
    int e0 = part * (EE / 8);
    for (int e = e0 + t; e < e0 + EE / 8; e += 512) {
        int ss = s[e], dd = d[e];
        atomicAdd(&A[dd * NN + ss], __float2bfloat16(rsi[dd] * rso[ss]));
    }
}

// ---------------- prep: codebook norm + 3 weight transposes -----------------
__global__ __launch_bounds__(256) void prep_kernel(const float* __restrict__ cb,
                                                   const float* __restrict__ W1,
                                                   const float* __restrict__ W2,
                                                   const float* __restrict__ D1) {
    __shared__ float tile[32][33];
    int b = blockIdx.x;
    if (b < KK) {
        int k = b;
        float v = cb[(size_t)k * DD + threadIdx.x];
        float ss = v * v;
        __shared__ float red[8];
        for (int o = 16; o > 0; o >>= 1) ss += __shfl_down_sync(0xffffffffu, ss, o);
        if ((threadIdx.x & 31) == 0) red[threadIdx.x >> 5] = ss;
        __syncthreads();
        if (threadIdx.x == 0) {
            float t = 0.f;
            for (int i = 0; i < 8; i++) t += red[i];
            red[0] = t;
        }
        __syncthreads();
        float r = rsqrtf(red[0] + 1e-12f);
        g_cnb[(size_t)k * DD + threadIdx.x] = __float2bfloat16(v * r);
    } else {
        int r2 = b - KK;
        int which = r2 >> 6, t2 = r2 & 63;
        const float* srcW = which == 0 ? W1 : which == 1 ? W2 : D1;
        bf16* dstW = which == 0 ? g_W1t : which == 1 ? g_W2t : g_D1t;
        int bx = t2 & 7, by = t2 >> 3;
        int r0 = by * 32, c0 = bx * 32;
        int tx = threadIdx.x & 31, ty = threadIdx.x >> 5;
#pragma unroll
        for (int i = 0; i < 4; i++) {
            int r = ty + i * 8;
            tile[r][tx] = srcW[(size_t)(r0 + r) * DD + c0 + tx];
        }
        __syncthreads();
#pragma unroll
        for (int i = 0; i < 4; i++) {
            int r = ty + i * 8;
            dstW[(size_t)(c0 + r) * DD + r0 + tx] = __float2bfloat16(tile[tx][r]);
        }
    }
}

// ---------------- transpose + convert (feats) -------------------------------
__global__ __launch_bounds__(256) void transpose_kernel(
    const float* __restrict__ in, bf16* __restrict__ out,
    int R, int C, size_t sIn, size_t sOut)
{
    __shared__ float tile[32][33];
    int b = blockIdx.z;
    in  += (size_t)b * sIn;
    out += (size_t)b * sOut;
    int r0 = blockIdx.y * 32, c0 = blockIdx.x * 32;
    int tx = threadIdx.x & 31, ty = threadIdx.x >> 5;
#pragma unroll
    for (int i = 0; i < 4; i++) {
        int r = ty + i * 8;
        tile[r][tx] = in[(size_t)(r0 + r) * C + c0 + tx];
    }
    __syncthreads();
#pragma unroll
    for (int i = 0; i < 4; i++) {
        int r = ty + i * 8;
        out[(size_t)(c0 + r) * R + r0 + tx] = __float2bfloat16(tile[tx][r]);
    }
}

// ---------------- generic bf16 HMMA GEMM: C = act(A @ Bt^T + bias) ---------
__global__ __launch_bounds__(256) void hgemm_kernel(
    const bf16* __restrict__ A, const bf16* __restrict__ Bt,
    const float* __restrict__ bias, float* __restrict__ Cf, bf16* __restrict__ Cb,
    int M, int Ncol, int Kd, size_t sA, size_t sBt, size_t sC, int relu)
{
    extern __shared__ bf16 dynsm[];
    bf16* As = dynsm;
    bf16* Bs = dynsm + P128_ELEMS;
    int b = blockIdx.z;
    A  += (size_t)b * sA;
    Bt += (size_t)b * sBt;
    int rowbase = blockIdx.y * 128, colbase = blockIdx.x * 128;
    int t = threadIdx.x, lane = t & 31, wid = t >> 5;
    int lr = lane >> 2, lq = lane & 3;
    int moff = (wid & 1) * 64, noff = (wid >> 1) * 32;

    float acc[4][4][4] = {};
    for (int p = 0; p < Kd; p += 128) {
        stage128(A  + (size_t)rowbase * Kd + p, Kd, As);
        stage128(Bt + (size_t)colbase * Kd + p, Kd, Bs);
        CP_COMMIT();
        CP_WAIT0();
        __syncthreads();
        mma_panel128(As, Bs, moff, noff, lr, lq, acc);
        if (p + 128 < Kd) __syncthreads();
    }
#pragma unroll
    for (int fm = 0; fm < 4; fm++)
#pragma unroll
        for (int fn = 0; fn < 4; fn++)
#pragma unroll
            for (int i = 0; i < 4; i++) {
                int row = rowbase + moff + fm * 16 + lr + (i >> 1) * 8;
                int col = colbase + noff + fn * 8 + 2 * lq + (i & 1);
                float v = acc[fm][fn][i];
                if (bias) v += bias[col];
                if (relu) v = fmaxf(v, 0.f);
                size_t o = (size_t)b * sC + (size_t)row * Ncol + col;
                if (Cf) Cf[o] = v;
                if (Cb) Cb[o] = __float2bfloat16(v);
            }
}

// ---------------- fused layernorm + transpose -------------------------------
__global__ __launch_bounds__(256) void ln_transpose_kernel(
    const float* __restrict__ x, const float* __restrict__ gamma,
    const float* __restrict__ beta, bf16* __restrict__ xt)
{
    __shared__ bf16 tile[32][258];
    __shared__ float gsh[DD], bsh[DD];
    int g = blockIdx.x >> 4;
    int rb = (blockIdx.x & 15) * 32;
    int t = threadIdx.x, lane = t & 31, warp = t >> 5;
    gsh[t] = gamma[t];
    bsh[t] = beta[t];
    __syncthreads();
#pragma unroll
    for (int rr = 0; rr < 4; rr++) {
        int row = rb + warp * 4 + rr;
        const float* xr = x + ((size_t)g * NN + row) * DD;
        float v[8];
        float s = 0.f;
#pragma unroll
        for (int j = 0; j < 8; j++) { v[j] = xr[lane + j * 32]; s += v[j]; }
        for (int o = 16; o > 0; o >>= 1) s += __shfl_xor_sync(0xffffffffu, s, o);
        float mu = s / DD;
        float s2 = 0.f;
#pragma unroll
        for (int j = 0; j < 8; j++) { float d = v[j] - mu; s2 += d * d; }
        for (int o = 16; o > 0; o >>= 1) s2 += __shfl_xor_sync(0xffffffffu, s2, o);
        float rs = rsqrtf(s2 / DD + 1e-5f);
#pragma unroll
        for (int j = 0; j < 8; j++) {
            int d = lane + j * 32;
            tile[row - rb][d] = __float2bfloat16((v[j] - mu) * rs * gsh[d] + bsh[d]);
        }
    }
    __syncthreads();
    bf16* dst = xt + (size_t)g * DD * NN;
    for (int i = t; i < 32 * DD; i += 256) {
        int d = i >> 5, node = i & 31;
        dst[(size_t)d * NN + rb + node] = tile[node][d];
    }
}

// ---------------- fused VQ argmax (double-buffered) + gather + vq loss ------
#define AM_SMEM (3 * P256_BYTES + 16 * 128 * 8)
__global__ __launch_bounds__(256, 1) void argmax_vq_kernel(
    const bf16* __restrict__ hfb, const float* __restrict__ hf,
    const float* __restrict__ cb)
{
    extern __shared__ char smraw[];
    bf16*  As   = (bf16*)smraw;
    bf16*  Bs0  = As + P256_ELEMS;
    bf16*  Bs1  = Bs0 + P256_ELEMS;
    float* redv = (float*)(Bs1 + P256_ELEMS);
    int*   redi = (int*)(redv + 16 * 128);
    int rowbase = blockIdx.x * 128;
    int t = threadIdx.x, lane = t & 31, wid = t >> 5;
    int lr = lane >> 2, lq = lane & 3;
    int moff = (wid >> 2) * 64, noff = (wid & 3) * 32;

    stage256(hfb + (size_t)rowbase * DD, DD, As);
    stage256(g_cnb, DD, Bs0);
    CP_COMMIT();
    CP_WAIT0();
    __syncthreads();

    float best[4][2];
    int   bidx[4][2];
#pragma unroll
    for (int fm = 0; fm < 4; fm++)
#pragma unroll
        for (int h = 0; h < 2; h++) { best[fm][h] = -1e30f; bidx[fm][h] = 0; }

    for (int cc = 0; cc < KK / 128; cc++) {
        bf16* Bcur  = (cc & 1) ? Bs1 : Bs0;
        bf16* Bnext = (cc & 1) ? Bs0 : Bs1;
        if (cc + 1 < KK / 128) {
            stage256(g_cnb + (size_t)(cc + 1) * 128 * DD, DD, Bnext);
            CP_COMMIT();
        }
        float acc[4][4][4] = {};
        mma_panel256(As, Bcur, moff, noff, lr, lq, acc);
#pragma unroll
        for (int fm = 0; fm < 4; fm++)
#pragma unroll
            for (int fn = 0; fn < 4; fn++) {
                int colb = cc * 128 + noff + fn * 8 + 2 * lq;
                float* c = acc[fm][fn];
                if (c[0] > best[fm][0]) { best[fm][0] = c[0]; bidx[fm][0] = colb; }
                if (c[1] > best[fm][0]) { best[fm][0] = c[1]; bidx[fm][0] = colb + 1; }
                if (c[2] > best[fm][1]) { best[fm][1] = c[2]; bidx[fm][1] = colb; }
                if (c[3] > best[fm][1]) { best[fm][1] = c[3]; bidx[fm][1] = colb + 1; }
            }
        CP_WAIT0();
        __syncthreads();
    }
    int owner = (wid & 3) * 4 + lq;
#pragma unroll
    for (int fm = 0; fm < 4; fm++)
#pragma unroll
        for (int h = 0; h < 2; h++) {
            int lrow = moff + fm * 16 + lr + h * 8;
            redv[owner * 128 + lrow] = best[fm][h];
            redi[owner * 128 + lrow] = bidx[fm][h];
        }
    __syncthreads();
    if (t < 128) {
        float bv = redv[t];
        int bi = redi[t];
        for (int x = 1; x < 16; x++) {
            float v = redv[x * 128 + t];
            int ii = redi[x * 128 + t];
            if (v > bv || (v == bv && ii < bi)) { bv = v; bi = ii; }
        }
        g_idx[rowbase + t] = bi;
        redi[t] = bi;
    }
    __syncthreads();
    {
        int r = t >> 1, half = t & 1;
        int idx = redi[r];
        const float* crow = cb + (size_t)idx * DD + half * 128;
        const float* hrow = hf + (size_t)(rowbase + r) * DD + half * 128;
        bf16* qrow = g_qb + (size_t)(rowbase + r) * DD + half * 128;
        float s = 0.f;
        for (int d = 0; d < 128; d++) {
            float cv = crow[d];
            float df = cv - hrow[d];
            s += df * df;
            qrow[d] = __float2bfloat16(cv);
        }
        for (int o = 16; o > 0; o >>= 1) s += __shfl_down_sync(0xffffffffu, s, o);
        if ((t & 31) == 0) atomicAdd(&g_vqacc, s);
    }
}

// ---------------- fused edge loss: HMMA logits + BCE + edge count -----------
__global__ __launch_bounds__(256) void edge_loss_kernel(const bf16* __restrict__ qe) {
    extern __shared__ bf16 dynsm[];
    bf16* As = dynsm;
    bf16* Bs = dynsm + P128_ELEMS;
    __shared__ float redp[8], redn[8], redc[8];
    int g = blockIdx.y;
    int tlin = blockIdx.x;
    int bi = 0, rem = tlin;
    while (rem >= 4 - bi) { rem -= 4 - bi; bi++; }
    int bj = bi + rem;
    const bf16* Q = qe + (size_t)g * NN * DD;
    const unsigned short* AbT = (const unsigned short*)(g_Ab + (size_t)g * NN * NN);

    int t = threadIdx.x, lane = t & 31, wid = t >> 5;
    int lr = lane >> 2, lq = lane & 3;
    int moff = (wid & 1) * 64, noff = (wid >> 1) * 32;
    int rowbase = bi * 128, colbase = bj * 128;

    float acc[4][4][4] = {};
    for (int p = 0; p < DD; p += 128) {
        stage128(Q + (size_t)rowbase * DD + p, DD, As);
        stage128(Q + (size_t)colbase * DD + p, DD, Bs);
        CP_COMMIT();
        CP_WAIT0();
        __syncthreads();
        mma_panel128(As, Bs, moff, noff, lr, lq, acc);
        if (p + 128 < DD) __syncthreads();
    }

    float spos = 0.f, sneg = 0.f, cnt = 0.f;
#pragma unroll
    for (int fm = 0; fm < 4; fm++)
#pragma unroll
        for (int fn = 0; fn < 4; fn++)
#pragma unroll
            for (int i = 0; i < 4; i++) {
                int row = rowbase + moff + fm * 16 + lr + (i >> 1) * 8;
                int col = colbase + noff + fn * 8 + 2 * lq + (i & 1);
                if (row < col) {
                    float x = acc[fm][fn][i];
                    float l1 = log1pf(__expf(-fabsf(x)));
                    float sp_p = fmaxf(x, 0.f) + l1;
                    float sp_n = fmaxf(-x, 0.f) + l1;
                    // adj[row][col] == 1  <=>  A[col][row] != 0
                    if (AbT[col * NN + row] != 0) { spos += sp_n; cnt += 1.f; }
                    else                          { sneg += sp_p; }
                }
            }
    for (int o = 16; o > 0; o >>= 1) {
        spos += __shfl_down_sync(0xffffffffu, spos, o);
        sneg += __shfl_down_sync(0xffffffffu, sneg, o);
        cnt  += __shfl_down_sync(0xffffffffu, cnt, o);
    }
    if ((t & 31) == 0) { redp[t >> 5] = spos; redn[t >> 5] = sneg; redc[t >> 5] = cnt; }
    __syncthreads();
    if (t == 0) {
        float tp = 0.f, tn = 0.f, tc = 0.f;
        for (int i = 0; i < 8; i++) { tp += redp[i]; tn += redn[i]; tc += redc[i]; }
        atomicAdd(&g_epos[g], tp);
        atomicAdd(&g_eneg[g], tn);
        atomicAdd(&g_ecnt[g], tc);
    }
}

// ---------------- finalize --------------------------------------------------
__global__ void finalize_kernel(float* out, int out_size) {
    float es = 0.f;
    for (int g = 0; g < G; g++) {
        float ne = g_ecnt[g];
        float pw = ((float)NN * NN * 0.5f - ne) / (ne + 1e-6f);
        es += (pw * g_epos[g] + g_eneg[g]) / ((float)NN * (NN - 1) * 0.5f);
    }
    es /= (float)G;
    float vq = 1000.0f * g_vqacc / ((float)G * NN * DD);
    float loss = es * 100.0f + vq;
    for (int i = 0; i < out_size; i++) out[i] = loss;
}

// ---------------- launch ----------------------------------------------------
extern "C" void kernel_launch(void* const* d_in, const int* in_sizes, int n_in,
                              void* d_out, int out_size) {
    (void)in_sizes; (void)n_in;
    const float* feats = (const float*)d_in[0];
    const int*   src   = (const int*)  d_in[1];
    const int*   dst   = (const int*)  d_in[2];
    const float* W1    = (const float*)d_in[3];
    const float* b1    = (const float*)d_in[4];
    const float* W2    = (const float*)d_in[5];
    const float* b2    = (const float*)d_in[6];
    const float* gamma = (const float*)d_in[7];
    const float* beta  = (const float*)d_in[8];
    const float* dec1W = (const float*)d_in[9];
    const float* dec1b = (const float*)d_in[10];
    const float* cb    = (const float*)d_in[13];
    float* out = (float*)d_out;

    float* pF1;
    bf16 *pAb, *pXt, *pM, *pHb, *pQb, *pQe, *pW1t, *pW2t, *pD1t;
    cudaGetSymbolAddress((void**)&pF1,  g_f1);
    cudaGetSymbolAddress((void**)&pAb,  g_Ab);
    cudaGetSymbolAddress((void**)&pXt,  g_Xt);
    cudaGetSymbolAddress((void**)&pM,   g_m);
    cudaGetSymbolAddress((void**)&pHb,  g_hb);
    cudaGetSymbolAddress((void**)&pQb,  g_qb);
    cudaGetSymbolAddress((void**)&pQe,  g_qe);
    cudaGetSymbolAddress((void**)&pW1t, g_W1t);
    cudaGetSymbolAddress((void**)&pW2t, g_W2t);
    cudaGetSymbolAddress((void**)&pD1t, g_D1t);

    const int HG_SMEM = 2 * P128_BYTES;
    cudaFuncSetAttribute(hgemm_kernel,
                         cudaFuncAttributeMaxDynamicSharedMemorySize, HG_SMEM);
    cudaFuncSetAttribute(edge_loss_kernel,
                         cudaFuncAttributeMaxDynamicSharedMemorySize, HG_SMEM);
    cudaFuncSetAttribute(argmax_vq_kernel,
                         cudaFuncAttributeMaxDynamicSharedMemorySize, AM_SMEM);

    zeroAb_kernel<<<2048, 256>>>();
    prep_kernel<<<KK + 192, 256>>>(cb, W1, W2, dec1W);
    transpose_kernel<<<dim3(DD / 32, NN / 32, G), 256>>>(
        feats, pXt, NN, DD, (size_t)NN * DD, (size_t)NN * DD);
    deg_scatter_kernel<<<G * 8, 512>>>(src, dst);

    // conv1: m = Ab @ Xt^T  (bf16 out)
    hgemm_kernel<<<dim3(DD / 128, NN / 128, G), 256, HG_SMEM>>>(
        pAb, pXt, nullptr, nullptr, pM, NN, DD, NN,
        (size_t)NN * NN, (size_t)DD * NN, (size_t)NN * DD, 0);
    // h1 = relu(m @ W1 + b1)  (fp32 out)
    hgemm_kernel<<<dim3(DD / 128, (G * NN) / 128, 1), 256, HG_SMEM>>>(
        pM, pW1t, b1, pF1, nullptr, G * NN, DD, DD, 0, 0, 0, 1);
    // fused layernorm + transpose -> Xt
    ln_transpose_kernel<<<G * 16, 256>>>(pF1, gamma, beta, pXt);
    // conv2
    hgemm_kernel<<<dim3(DD / 128, NN / 128, G), 256, HG_SMEM>>>(
        pAb, pXt, nullptr, nullptr, pM, NN, DD, NN,
        (size_t)NN * NN, (size_t)DD * NN, (size_t)NN * DD, 0);
    // hf = relu(m2 @ W2 + b2)  (fp32 + bf16 out)
    hgemm_kernel<<<dim3(DD / 128, (G * NN) / 128, 1), 256, HG_SMEM>>>(
        pM, pW2t, b2, pF1, pHb, G * NN, DD, DD, 0, 0, 0, 1);

    // VQ argmax + gather + vq loss
    argmax_vq_kernel<<<(G * NN) / 128, 256, AM_SMEM>>>(pHb, pF1, cb);

    // qe = q @ dec1_W + dec1_b  (bf16 out)
    hgemm_kernel<<<dim3(DD / 128, (G * NN) / 128, 1), 256, HG_SMEM>>>(
        pQb, pD1t, dec1b, nullptr, pQe, G * NN, DD, DD, 0, 0, 0, 0);

    // fused edge BCE loss + edge count
    edge_loss_kernel<<<dim3(10, G), 256, HG_SMEM>>>(pQe);

    finalize_kernel<<<1, 1>>>(out, out_size);
}

// round 8
// speedup vs baseline: 5.3943x; 1.0209x over previous
#include <cuda_runtime.h>
#include <cuda_bf16.h>
#include <math.h>
#include <stdint.h>

#define G   32
#define NN  512
#define EE  8192
#define DD  256
#define KK  2048

typedef __nv_bfloat16 bf16;

// K=64 double-buffered panels for hgemm (2 blocks/SM, overlapped)
#define LD64 72
#define P64_ELEMS (128 * LD64)
#define P64_BYTES (P64_ELEMS * 2)       // 18432 B
#define HG_SMEM (4 * P64_BYTES)         // 73728 B
// K=128 panels for edge kernel
#define LDQ 136
#define P128_ELEMS (128 * LDQ)
#define P128_BYTES (P128_ELEMS * 2)     // 34816 B
#define EL_SMEM (2 * P128_BYTES)
// K=256 panels for argmax kernel
#define LDP 264
#define P256_ELEMS (128 * LDP)
#define P256_BYTES (P256_ELEMS * 2)     // 67584 B

// ---------------- scratch (device globals) ---------------------------------
__device__ bf16  g_Ab  [(size_t)G * NN * NN];   // bf16 adjacency (A[dst][src])
__device__ bf16  g_Xt  [(size_t)G * DD * NN];   // transposed activations
__device__ bf16  g_m   [(size_t)G * NN * DD];   // conv output bf16
__device__ float g_f1  [(size_t)G * NN * DD];   // fp32 buffer
__device__ bf16  g_hb  [(size_t)G * NN * DD];   // hf bf16
__device__ bf16  g_qb  [(size_t)G * NN * DD];   // gathered codebook bf16
__device__ bf16  g_qe  [(size_t)G * NN * DD];   // decoded qe bf16
__device__ bf16  g_cnb [(size_t)KK * DD];       // normalized codebook bf16
__device__ bf16  g_W1t [DD * DD];
__device__ bf16  g_W2t [DD * DD];
__device__ bf16  g_D1t [DD * DD];
__device__ int   g_idx [G * NN];
__device__ float g_epos[G];
__device__ float g_eneg[G];
__device__ float g_ecnt[G];
__device__ float g_vqacc;

// ---------------- cp.async helpers -----------------------------------------
__device__ __forceinline__ void cpasync16(void* smem, const void* gptr) {
    uint32_t a = (uint32_t)__cvta_generic_to_shared(smem);
    asm volatile("cp.async.cg.shared.global [%0], [%1], 16;\n" :: "r"(a), "l"(gptr));
}
#define CP_COMMIT() asm volatile("cp.async.commit_group;\n" ::: "memory")
#define CP_WAIT0()  asm volatile("cp.async.wait_group 0;\n" ::: "memory")
#define CP_WAIT1()  asm volatile("cp.async.wait_group 1;\n" ::: "memory")

// stage 128x64 bf16 tile into smem [128][LD64]
__device__ __forceinline__ void stage64(const bf16* __restrict__ src, size_t ld,
                                        bf16* __restrict__ dstS) {
    int t = threadIdx.x;
#pragma unroll
    for (int i = 0; i < 4; i++) {
        int idx = t + i * 256;          // 0..1023
        int r = idx >> 3;
        int c = (idx & 7) * 8;
        cpasync16(&dstS[r * LD64 + c], &src[(size_t)r * ld + c]);
    }
}

// stage 128x128 bf16 tile into smem [128][LDQ]
__device__ __forceinline__ void stage128(const bf16* __restrict__ src, size_t ld,
                                         bf16* __restrict__ dstS) {
    int t = threadIdx.x;
#pragma unroll
    for (int i = 0; i < 8; i++) {
        int idx = t + i * 256;
        int r = idx >> 4;
        int c = (idx & 15) * 8;
        cpasync16(&dstS[r * LDQ + c], &src[(size_t)r * ld + c]);
    }
}

// stage 128x256 bf16 panel into smem [128][LDP]
__device__ __forceinline__ void stage256(const bf16* __restrict__ src, size_t ld,
                                         bf16* __restrict__ dstS) {
    int t = threadIdx.x;
#pragma unroll
    for (int i = 0; i < 16; i++) {
        int idx = t + i * 256;
        int r = idx >> 5;
        int c = (idx & 31) * 8;
        cpasync16(&dstS[r * LDP + c], &src[(size_t)r * ld + c]);
    }
}

// ---------------- MMA core --------------------------------------------------
__device__ __forceinline__ void mma16816(float c[4], uint32_t a0, uint32_t a1,
                                         uint32_t a2, uint32_t a3,
                                         uint32_t b0, uint32_t b1) {
    asm volatile(
        "mma.sync.aligned.m16n8k16.row.col.f32.bf16.bf16.f32 "
        "{%0,%1,%2,%3}, {%4,%5,%6,%7}, {%8,%9}, {%0,%1,%2,%3};\n"
        : "+f"(c[0]), "+f"(c[1]), "+f"(c[2]), "+f"(c[3])
        : "r"(a0), "r"(a1), "r"(a2), "r"(a3), "r"(b0), "r"(b1));
}

// generic K-tile compute with pitch ldp, K elements = kw
template <int LDPITCH, int KW>
__device__ __forceinline__ void mma_panel(const bf16* As, const bf16* Bs,
                                          int moff, int noff,
                                          int lr, int lq, float acc[4][4][4]) {
#pragma unroll
    for (int kt = 0; kt < KW; kt += 16) {
        int kk = kt + 2 * lq;
        uint32_t bfr[4][2];
#pragma unroll
        for (int fn = 0; fn < 4; fn++) {
            const bf16* bp = &Bs[(noff + fn * 8 + lr) * LDPITCH + kk];
            bfr[fn][0] = *(const uint32_t*)bp;
            bfr[fn][1] = *(const uint32_t*)(bp + 8);
        }
#pragma unroll
        for (int fm = 0; fm < 4; fm++) {
            const bf16* ap = &As[(moff + fm * 16 + lr) * LDPITCH + kk];
            uint32_t a0 = *(const uint32_t*)ap;
            uint32_t a1 = *(const uint32_t*)(ap + 8 * LDPITCH);
            uint32_t a2 = *(const uint32_t*)(ap + 8);
            uint32_t a3 = *(const uint32_t*)(ap + 8 * LDPITCH + 8);
#pragma unroll
            for (int fn = 0; fn < 4; fn++)
                mma16816(acc[fm][fn], a0, a1, a2, a3, bfr[fn][0], bfr[fn][1]);
        }
    }
}

// ---------------- zero bf16 A + accumulators (full chip) --------------------
__global__ __launch_bounds__(256) void zeroAb_kernel() {
    uint4* A4 = (uint4*)g_Ab;
    size_t n = (size_t)G * NN * NN * 2 / 16;
    for (size_t i = (size_t)blockIdx.x * blockDim.x + threadIdx.x; i < n;
         i += (size_t)gridDim.x * blockDim.x)
        A4[i] = make_uint4(0u, 0u, 0u, 0u);
    if (blockIdx.x == 0 && threadIdx.x < G) {
        g_epos[threadIdx.x] = 0.f;
        g_eneg[threadIdx.x] = 0.f;
        g_ecnt[threadIdx.x] = 0.f;
        if (threadIdx.x == 0) g_vqacc = 0.f;
    }
}

// ---------------- degrees + scatter (native paired bf16 atomics) ------------
__global__ __launch_bounds__(512) void deg_scatter_kernel(const int* __restrict__ src,
                                                          const int* __restrict__ dst) {
    int g = blockIdx.x >> 3;
    int part = blockIdx.x & 7;
    int t = threadIdx.x;
    __shared__ int co[NN], ci[NN];
    __shared__ float rso[NN], rsi[NN];
    for (int i = t; i < NN; i += 512) { co[i] = 0; ci[i] = 0; }
    __syncthreads();
    const int* s = src + g * EE;
    const int* d = dst + g * EE;
    for (int e = t; e < EE; e += 512) {
        atomicAdd(&co[s[e]], 1);
        atomicAdd(&ci[d[e]], 1);
    }
    __syncthreads();
    for (int i = t; i < NN; i += 512) {
        rso[i] = rsqrtf((float)max(co[i], 1));
        rsi[i] = rsqrtf((float)max(ci[i], 1));
    }
    __syncthreads();
    bf16* A = g_Ab + (size_t)g * NN * NN;
    int e0 = part * (EE / 8);
    for (int e = e0 + t; e < e0 + EE / 8; e += 512) {
        int ss = s[e], dd = d[e];
        int idx = dd * NN + ss;
        bf16 v = __float2bfloat16(rsi[dd] * rso[ss]);
        bf16 z = __float2bfloat16(0.f);
        __nv_bfloat162 val = (idx & 1) ? __halves2bfloat162(z, v)
                                       : __halves2bfloat162(v, z);
        atomicAdd((__nv_bfloat162*)(A + (idx & ~1)), val);   // native RED.v2.bf16
    }
}

// ---------------- prep: codebook norm + 3 weight transposes -----------------
__global__ __launch_bounds__(256) void prep_kernel(const float* __restrict__ cb,
                                                   const float* __restrict__ W1,
                                                   const float* __restrict__ W2,
                                                   const float* __restrict__ D1) {
    __shared__ float tile[32][33];
    int b = blockIdx.x;
    if (b < KK) {
        int k = b;
        float v = cb[(size_t)k * DD + threadIdx.x];
        float ss = v * v;
        __shared__ float red[8];
        for (int o = 16; o > 0; o >>= 1) ss += __shfl_down_sync(0xffffffffu, ss, o);
        if ((threadIdx.x & 31) == 0) red[threadIdx.x >> 5] = ss;
        __syncthreads();
        if (threadIdx.x == 0) {
            float t = 0.f;
            for (int i = 0; i < 8; i++) t += red[i];
            red[0] = t;
        }
        __syncthreads();
        float r = rsqrtf(red[0] + 1e-12f);
        g_cnb[(size_t)k * DD + threadIdx.x] = __float2bfloat16(v * r);
    } else {
        int r2 = b - KK;
        int which = r2 >> 6, t2 = r2 & 63;
        const float* srcW = which == 0 ? W1 : which == 1 ? W2 : D1;
        bf16* dstW = which == 0 ? g_W1t : which == 1 ? g_W2t : g_D1t;
        int bx = t2 & 7, by = t2 >> 3;
        int r0 = by * 32, c0 = bx * 32;
        int tx = threadIdx.x & 31, ty = threadIdx.x >> 5;
#pragma unroll
        for (int i = 0; i < 4; i++) {
            int r = ty + i * 8;
            tile[r][tx] = srcW[(size_t)(r0 + r) * DD + c0 + tx];
        }
        __syncthreads();
#pragma unroll
        for (int i = 0; i < 4; i++) {
            int r = ty + i * 8;
            dstW[(size_t)(c0 + r) * DD + r0 + tx] = __float2bfloat16(tile[tx][r]);
        }
    }
}

// ---------------- transpose + convert (feats) -------------------------------
__global__ __launch_bounds__(256) void transpose_kernel(
    const float* __restrict__ in, bf16* __restrict__ out,
    int R, int C, size_t sIn, size_t sOut)
{
    __shared__ float tile[32][33];
    int b = blockIdx.z;
    in  += (size_t)b * sIn;
    out += (size_t)b * sOut;
    int r0 = blockIdx.y * 32, c0 = blockIdx.x * 32;
    int tx = threadIdx.x & 31, ty = threadIdx.x >> 5;
#pragma unroll
    for (int i = 0; i < 4; i++) {
        int r = ty + i * 8;
        tile[r][tx] = in[(size_t)(r0 + r) * C + c0 + tx];
    }
    __syncthreads();
#pragma unroll
    for (int i = 0; i < 4; i++) {
        int r = ty + i * 8;
        out[(size_t)(c0 + r) * R + r0 + tx] = __float2bfloat16(tile[tx][r]);
    }
}

// ---------------- generic bf16 HMMA GEMM (double-buffered K=64 panels) ------
__global__ __launch_bounds__(256) void hgemm_kernel(
    const bf16* __restrict__ A, const bf16* __restrict__ Bt,
    const float* __restrict__ bias, float* __restrict__ Cf, bf16* __restrict__ Cb,
    int M, int Ncol, int Kd, size_t sA, size_t sBt, size_t sC, int relu)
{
    extern __shared__ bf16 dynsm[];
    bf16* Abuf[2] = { dynsm, dynsm + 2 * P64_ELEMS };
    bf16* Bbuf[2] = { dynsm + P64_ELEMS, dynsm + 3 * P64_ELEMS };
    int b = blockIdx.z;
    A  += (size_t)b * sA;
    Bt += (size_t)b * sBt;
    int rowbase = blockIdx.y * 128, colbase = blockIdx.x * 128;
    int t = threadIdx.x, lane = t & 31, wid = t >> 5;
    int lr = lane >> 2, lq = lane & 3;
    int moff = (wid & 1) * 64, noff = (wid >> 1) * 32;

    int P = Kd / 64;
    stage64(A  + (size_t)rowbase * Kd, Kd, Abuf[0]);
    stage64(Bt + (size_t)colbase * Kd, Kd, Bbuf[0]);
    CP_COMMIT();

    float acc[4][4][4] = {};
    for (int p = 0; p < P; p++) {
        if (p + 1 < P) {
            stage64(A  + (size_t)rowbase * Kd + (p + 1) * 64, Kd, Abuf[(p + 1) & 1]);
            stage64(Bt + (size_t)colbase * Kd + (p + 1) * 64, Kd, Bbuf[(p + 1) & 1]);
            CP_COMMIT();
            CP_WAIT1();
        } else {
            CP_WAIT0();
        }
        __syncthreads();
        mma_panel<LD64, 64>(Abuf[p & 1], Bbuf[p & 1], moff, noff, lr, lq, acc);
        __syncthreads();
    }
#pragma unroll
    for (int fm = 0; fm < 4; fm++)
#pragma unroll
        for (int fn = 0; fn < 4; fn++)
#pragma unroll
            for (int i = 0; i < 4; i++) {
                int row = rowbase + moff + fm * 16 + lr + (i >> 1) * 8;
                int col = colbase + noff + fn * 8 + 2 * lq + (i & 1);
                float v = acc[fm][fn][i];
                if (bias) v += bias[col];
                if (relu) v = fmaxf(v, 0.f);
                size_t o = (size_t)b * sC + (size_t)row * Ncol + col;
                if (Cf) Cf[o] = v;
                if (Cb) Cb[o] = __float2bfloat16(v);
            }
}

// ---------------- fused layernorm + transpose -------------------------------
__global__ __launch_bounds__(256) void ln_transpose_kernel(
    const float* __restrict__ x, const float* __restrict__ gamma,
    const float* __restrict__ beta, bf16* __restrict__ xt)
{
    __shared__ bf16 tile[32][258];
    __shared__ float gsh[DD], bsh[DD];
    int g = blockIdx.x >> 4;
    int rb = (blockIdx.x & 15) * 32;
    int t = threadIdx.x, lane = t & 31, warp = t >> 5;
    gsh[t] = gamma[t];
    bsh[t] = beta[t];
    __syncthreads();
#pragma unroll
    for (int rr = 0; rr < 4; rr++) {
        int row = rb + warp * 4 + rr;
        const float* xr = x + ((size_t)g * NN + row) * DD;
        float v[8];
        float s = 0.f;
#pragma unroll
        for (int j = 0; j < 8; j++) { v[j] = xr[lane + j * 32]; s += v[j]; }
        for (int o = 16; o > 0; o >>= 1) s += __shfl_xor_sync(0xffffffffu, s, o);
        float mu = s / DD;
        float s2 = 0.f;
#pragma unroll
        for (int j = 0; j < 8; j++) { float d = v[j] - mu; s2 += d * d; }
        for (int o = 16; o > 0; o >>= 1) s2 += __shfl_xor_sync(0xffffffffu, s2, o);
        float rs = rsqrtf(s2 / DD + 1e-5f);
#pragma unroll
        for (int j = 0; j < 8; j++) {
            int d = lane + j * 32;
            tile[row - rb][d] = __float2bfloat16((v[j] - mu) * rs * gsh[d] + bsh[d]);
        }
    }
    __syncthreads();
    bf16* dst = xt + (size_t)g * DD * NN;
    for (int i = t; i < 32 * DD; i += 256) {
        int d = i >> 5, node = i & 31;
        dst[(size_t)d * NN + rb + node] = tile[node][d];
    }
}

// ---------------- fused VQ argmax (double-buffered) + gather + vq loss ------
#define AM_SMEM (3 * P256_BYTES + 16 * 128 * 8)
__global__ __launch_bounds__(256, 1) void argmax_vq_kernel(
    const bf16* __restrict__ hfb, const float* __restrict__ hf,
    const float* __restrict__ cb)
{
    extern __shared__ char smraw[];
    bf16*  As   = (bf16*)smraw;
    bf16*  Bs0  = As + P256_ELEMS;
    bf16*  Bs1  = Bs0 + P256_ELEMS;
    float* redv = (float*)(Bs1 + P256_ELEMS);
    int*   redi = (int*)(redv + 16 * 128);
    int rowbase = blockIdx.x * 128;
    int t = threadIdx.x, lane = t & 31, wid = t >> 5;
    int lr = lane >> 2, lq = lane & 3;
    int moff = (wid >> 2) * 64, noff = (wid & 3) * 32;

    stage256(hfb + (size_t)rowbase * DD, DD, As);
    stage256(g_cnb, DD, Bs0);
    CP_COMMIT();
    CP_WAIT0();
    __syncthreads();

    float best[4][2];
    int   bidx[4][2];
#pragma unroll
    for (int fm = 0; fm < 4; fm++)
#pragma unroll
        for (int h = 0; h < 2; h++) { best[fm][h] = -1e30f; bidx[fm][h] = 0; }

    for (int cc = 0; cc < KK / 128; cc++) {
        bf16* Bcur  = (cc & 1) ? Bs1 : Bs0;
        bf16* Bnext = (cc & 1) ? Bs0 : Bs1;
        if (cc + 1 < KK / 128) {
            stage256(g_cnb + (size_t)(cc + 1) * 128 * DD, DD, Bnext);
            CP_COMMIT();
        }
        float acc[4][4][4] = {};
        mma_panel<LDP, 256>(As, Bcur, moff, noff, lr, lq, acc);
#pragma unroll
        for (int fm = 0; fm < 4; fm++)
#pragma unroll
            for (int fn = 0; fn < 4; fn++) {
                int colb = cc * 128 + noff + fn * 8 + 2 * lq;
                float* c = acc[fm][fn];
                if (c[0] > best[fm][0]) { best[fm][0] = c[0]; bidx[fm][0] = colb; }
                if (c[1] > best[fm][0]) { best[fm][0] = c[1]; bidx[fm][0] = colb + 1; }
                if (c[2] > best[fm][1]) { best[fm][1] = c[2]; bidx[fm][1] = colb; }
                if (c[3] > best[fm][1]) { best[fm][1] = c[3]; bidx[fm][1] = colb + 1; }
            }
        CP_WAIT0();
        __syncthreads();
    }
    int owner = (wid & 3) * 4 + lq;
#pragma unroll
    for (int fm = 0; fm < 4; fm++)
#pragma unroll
        for (int h = 0; h < 2; h++) {
            int lrow = moff + fm * 16 + lr + h * 8;
            redv[owner * 128 + lrow] = best[fm][h];
            redi[owner * 128 + lrow] = bidx[fm][h];
        }
    __syncthreads();
    if (t < 128) {
        float bv = redv[t];
        int bi = redi[t];
        for (int x = 1; x < 16; x++) {
            float v = redv[x * 128 + t];
            int ii = redi[x * 128 + t];
            if (v > bv || (v == bv && ii < bi)) { bv = v; bi = ii; }
        }
        g_idx[rowbase + t] = bi;
        redi[t] = bi;
    }
    __syncthreads();
    {
        int r = t >> 1, half = t & 1;
        int idx = redi[r];
        const float* crow = cb + (size_t)idx * DD + half * 128;
        const float* hrow = hf + (size_t)(rowbase + r) * DD + half * 128;
        bf16* qrow = g_qb + (size_t)(rowbase + r) * DD + half * 128;
        float s = 0.f;
        for (int d = 0; d < 128; d++) {
            float cv = crow[d];
            float df = cv - hrow[d];
            s += df * df;
            qrow[d] = __float2bfloat16(cv);
        }
        for (int o = 16; o > 0; o >>= 1) s += __shfl_down_sync(0xffffffffu, s, o);
        if ((t & 31) == 0) atomicAdd(&g_vqacc, s);
    }
}

// ---------------- fused edge loss: HMMA logits + BCE + edge count -----------
__global__ __launch_bounds__(256) void edge_loss_kernel(const bf16* __restrict__ qe) {
    extern __shared__ bf16 dynsm[];
    bf16* As = dynsm;
    bf16* Bs = dynsm + P128_ELEMS;
    __shared__ float redp[8], redn[8], redc[8];
    int g = blockIdx.y;
    int tlin = blockIdx.x;
    int bi = 0, rem = tlin;
    while (rem >= 4 - bi) { rem -= 4 - bi; bi++; }
    int bj = bi + rem;
    const bf16* Q = qe + (size_t)g * NN * DD;
    const unsigned short* AbT = (const unsigned short*)(g_Ab + (size_t)g * NN * NN);

    int t = threadIdx.x, lane = t & 31, wid = t >> 5;
    int lr = lane >> 2, lq = lane & 3;
    int moff = (wid & 1) * 64, noff = (wid >> 1) * 32;
    int rowbase = bi * 128, colbase = bj * 128;

    float acc[4][4][4] = {};
    for (int p = 0; p < DD; p += 128) {
        stage128(Q + (size_t)rowbase * DD + p, DD, As);
        stage128(Q + (size_t)colbase * DD + p, DD, Bs);
        CP_COMMIT();
        CP_WAIT0();
        __syncthreads();
        mma_panel<LDQ, 128>(As, Bs, moff, noff, lr, lq, acc);
        if (p + 128 < DD) __syncthreads();
    }

    float spos = 0.f, sneg = 0.f, cnt = 0.f;
#pragma unroll
    for (int fm = 0; fm < 4; fm++)
#pragma unroll
        for (int fn = 0; fn < 4; fn++)
#pragma unroll
            for (int i = 0; i < 4; i++) {
                int row = rowbase + moff + fm * 16 + lr + (i >> 1) * 8;
                int col = colbase + noff + fn * 8 + 2 * lq + (i & 1);
                if (row < col) {
                    float x = acc[fm][fn][i];
                    float l1 = log1pf(__expf(-fabsf(x)));
                    float sp_p = fmaxf(x, 0.f) + l1;
                    float sp_n = fmaxf(-x, 0.f) + l1;
                    if (AbT[col * NN + row] != 0) { spos += sp_n; cnt += 1.f; }
                    else                          { sneg += sp_p; }
                }
            }
    for (int o = 16; o > 0; o >>= 1) {
        spos += __shfl_down_sync(0xffffffffu, spos, o);
        sneg += __shfl_down_sync(0xffffffffu, sneg, o);
        cnt  += __shfl_down_sync(0xffffffffu, cnt, o);
    }
    if ((t & 31) == 0) { redp[t >> 5] = spos; redn[t >> 5] = sneg; redc[t >> 5] = cnt; }
    __syncthreads();
    if (t == 0) {
        float tp = 0.f, tn = 0.f, tc = 0.f;
        for (int i = 0; i < 8; i++) { tp += redp[i]; tn += redn[i]; tc += redc[i]; }
        atomicAdd(&g_epos[g], tp);
        atomicAdd(&g_eneg[g], tn);
        atomicAdd(&g_ecnt[g], tc);
    }
}

// ---------------- finalize --------------------------------------------------
__global__ void finalize_kernel(float* out, int out_size) {
    float es = 0.f;
    for (int g = 0; g < G; g++) {
        float ne = g_ecnt[g];
        float pw = ((float)NN * NN * 0.5f - ne) / (ne + 1e-6f);
        es += (pw * g_epos[g] + g_eneg[g]) / ((float)NN * (NN - 1) * 0.5f);
    }
    es /= (float)G;
    float vq = 1000.0f * g_vqacc / ((float)G * NN * DD);
    float loss = es * 100.0f + vq;
    for (int i = 0; i < out_size; i++) out[i] = loss;
}

// ---------------- launch ----------------------------------------------------
extern "C" void kernel_launch(void* const* d_in, const int* in_sizes, int n_in,
                              void* d_out, int out_size) {
    (void)in_sizes; (void)n_in;
    const float* feats = (const float*)d_in[0];
    const int*   src   = (const int*)  d_in[1];
    const int*   dst   = (const int*)  d_in[2];
    const float* W1    = (const float*)d_in[3];
    const float* b1    = (const float*)d_in[4];
    const float* W2    = (const float*)d_in[5];
    const float* b2    = (const float*)d_in[6];
    const float* gamma = (const float*)d_in[7];
    const float* beta  = (const float*)d_in[8];
    const float* dec1W = (const float*)d_in[9];
    const float* dec1b = (const float*)d_in[10];
    const float* cb    = (const float*)d_in[13];
    float* out = (float*)d_out;

    float* pF1;
    bf16 *pAb, *pXt, *pM, *pHb, *pQb, *pQe, *pW1t, *pW2t, *pD1t;
    cudaGetSymbolAddress((void**)&pF1,  g_f1);
    cudaGetSymbolAddress((void**)&pAb,  g_Ab);
    cudaGetSymbolAddress((void**)&pXt,  g_Xt);
    cudaGetSymbolAddress((void**)&pM,   g_m);
    cudaGetSymbolAddress((void**)&pHb,  g_hb);
    cudaGetSymbolAddress((void**)&pQb,  g_qb);
    cudaGetSymbolAddress((void**)&pQe,  g_qe);
    cudaGetSymbolAddress((void**)&pW1t, g_W1t);
    cudaGetSymbolAddress((void**)&pW2t, g_W2t);
    cudaGetSymbolAddress((void**)&pD1t, g_D1t);

    cudaFuncSetAttribute(hgemm_kernel,
                         cudaFuncAttributeMaxDynamicSharedMemorySize, HG_SMEM);
    cudaFuncSetAttribute(edge_loss_kernel,
                         cudaFuncAttributeMaxDynamicSharedMemorySize, EL_SMEM);
    cudaFuncSetAttribute(argmax_vq_kernel,
                         cudaFuncAttributeMaxDynamicSharedMemorySize, AM_SMEM);

    zeroAb_kernel<<<2048, 256>>>();
    prep_kernel<<<KK + 192, 256>>>(cb, W1, W2, dec1W);
    transpose_kernel<<<dim3(DD / 32, NN / 32, G), 256>>>(
        feats, pXt, NN, DD, (size_t)NN * DD, (size_t)NN * DD);
    deg_scatter_kernel<<<G * 8, 512>>>(src, dst);

    // conv1: m = Ab @ Xt^T  (bf16 out)
    hgemm_kernel<<<dim3(DD / 128, NN / 128, G), 256, HG_SMEM>>>(
        pAb, pXt, nullptr, nullptr, pM, NN, DD, NN,
        (size_t)NN * NN, (size_t)DD * NN, (size_t)NN * DD, 0);
    // h1 = relu(m @ W1 + b1)  (fp32 out)
    hgemm_kernel<<<dim3(DD / 128, (G * NN) / 128, 1), 256, HG_SMEM>>>(
        pM, pW1t, b1, pF1, nullptr, G * NN, DD, DD, 0, 0, 0, 1);
    // fused layernorm + transpose -> Xt
    ln_transpose_kernel<<<G * 16, 256>>>(pF1, gamma, beta, pXt);
    // conv2
    hgemm_kernel<<<dim3(DD / 128, NN / 128, G), 256, HG_SMEM>>>(
        pAb, pXt, nullptr, nullptr, pM, NN, DD, NN,
        (size_t)NN * NN, (size_t)DD * NN, (size_t)NN * DD, 0);
    // hf = relu(m2 @ W2 + b2)  (fp32 + bf16 out)
    hgemm_kernel<<<dim3(DD / 128, (G * NN) / 128, 1), 256, HG_SMEM>>>(
        pM, pW2t, b2, pF1, pHb, G * NN, DD, DD, 0, 0, 0, 1);

    // VQ argmax + gather + vq loss
    argmax_vq_kernel<<<(G * NN) / 128, 256, AM_SMEM>>>(pHb, pF1, cb);

    // qe = q @ dec1_W + dec1_b  (bf16 out)
    hgemm_kernel<<<dim3(DD / 128, (G * NN) / 128, 1), 256, HG_SMEM>>>(
        pQb, pD1t, dec1b, nullptr, pQe, G * NN, DD, DD, 0, 0, 0, 0);

    // fused edge BCE loss + edge count
    edge_loss_kernel<<<dim3(10, G), 256, EL_SMEM>>>(pQe);

    finalize_kernel<<<1, 1>>>(out, out_size);
}

// round 9
// speedup vs baseline: 5.4956x; 1.0188x over previous
#include <cuda_runtime.h>
#include <cuda_bf16.h>
#include <math.h>
#include <stdint.h>

#define G   32
#define NN  512
#define EE  8192
#define DD  256
#define KK  2048

typedef __nv_bfloat16 bf16;

// K=64 double-buffered panels for hgemm (2 blocks/SM, overlapped)
#define LD64 72
#define P64_ELEMS (128 * LD64)
#define P64_BYTES (P64_ELEMS * 2)       // 18432 B
#define HG_SMEM (4 * P64_BYTES)         // 73728 B
// K=128 panels for edge kernel
#define LDQ 136
#define P128_ELEMS (128 * LDQ)
#define P128_BYTES (P128_ELEMS * 2)     // 34816 B
#define EL_SMEM (2 * P128_BYTES)
// K=256 panels for argmax kernel
#define LDP 264
#define P256_ELEMS (128 * LDP)
#define P256_BYTES (P256_ELEMS * 2)     // 67584 B
// A-build kernel smem (fp32 accumulator slab)
#define DS_SMEM (NN * 64 * 4)           // 131072 B

// ---------------- scratch (device globals) ---------------------------------
__device__ bf16  g_Ab  [(size_t)G * NN * NN];   // bf16 adjacency (A[dst][src])
__device__ bf16  g_Xt  [(size_t)G * DD * NN];   // transposed activations
__device__ bf16  g_m   [(size_t)G * NN * DD];   // conv output bf16
__device__ float g_f1  [(size_t)G * NN * DD];   // fp32 buffer
__device__ bf16  g_hb  [(size_t)G * NN * DD];   // hf bf16
__device__ bf16  g_qb  [(size_t)G * NN * DD];   // gathered codebook bf16
__device__ bf16  g_qe  [(size_t)G * NN * DD];   // decoded qe bf16
__device__ bf16  g_cnb [(size_t)KK * DD];       // normalized codebook bf16
__device__ bf16  g_W1t [DD * DD];
__device__ bf16  g_W2t [DD * DD];
__device__ bf16  g_D1t [DD * DD];
__device__ int   g_idx [G * NN];
__device__ float g_epos[G];
__device__ float g_eneg[G];
__device__ float g_ecnt[G];
__device__ float g_vqacc;

// ---------------- cp.async helpers -----------------------------------------
__device__ __forceinline__ void cpasync16(void* smem, const void* gptr) {
    uint32_t a = (uint32_t)__cvta_generic_to_shared(smem);
    asm volatile("cp.async.cg.shared.global [%0], [%1], 16;\n" :: "r"(a), "l"(gptr));
}
#define CP_COMMIT() asm volatile("cp.async.commit_group;\n" ::: "memory")
#define CP_WAIT0()  asm volatile("cp.async.wait_group 0;\n" ::: "memory")
#define CP_WAIT1()  asm volatile("cp.async.wait_group 1;\n" ::: "memory")

__device__ __forceinline__ void stage64(const bf16* __restrict__ src, size_t ld,
                                        bf16* __restrict__ dstS) {
    int t = threadIdx.x;
#pragma unroll
    for (int i = 0; i < 4; i++) {
        int idx = t + i * 256;
        int r = idx >> 3;
        int c = (idx & 7) * 8;
        cpasync16(&dstS[r * LD64 + c], &src[(size_t)r * ld + c]);
    }
}

__device__ __forceinline__ void stage128(const bf16* __restrict__ src, size_t ld,
                                         bf16* __restrict__ dstS) {
    int t = threadIdx.x;
#pragma unroll
    for (int i = 0; i < 8; i++) {
        int idx = t + i * 256;
        int r = idx >> 4;
        int c = (idx & 15) * 8;
        cpasync16(&dstS[r * LDQ + c], &src[(size_t)r * ld + c]);
    }
}

__device__ __forceinline__ void stage256(const bf16* __restrict__ src, size_t ld,
                                         bf16* __restrict__ dstS) {
    int t = threadIdx.x;
#pragma unroll
    for (int i = 0; i < 16; i++) {
        int idx = t + i * 256;
        int r = idx >> 5;
        int c = (idx & 31) * 8;
        cpasync16(&dstS[r * LDP + c], &src[(size_t)r * ld + c]);
    }
}

// ---------------- MMA core (ldmatrix + mma.sync) ----------------------------
__device__ __forceinline__ void mma16816(float c[4], uint32_t a0, uint32_t a1,
                                         uint32_t a2, uint32_t a3,
                                         uint32_t b0, uint32_t b1) {
    asm volatile(
        "mma.sync.aligned.m16n8k16.row.col.f32.bf16.bf16.f32 "
        "{%0,%1,%2,%3}, {%4,%5,%6,%7}, {%8,%9}, {%0,%1,%2,%3};\n"
        : "+f"(c[0]), "+f"(c[1]), "+f"(c[2]), "+f"(c[3])
        : "r"(a0), "r"(a1), "r"(a2), "r"(a3), "r"(b0), "r"(b1));
}

__device__ __forceinline__ void ldsm_x4(uint32_t r[4], uint32_t addr) {
    asm volatile("ldmatrix.sync.aligned.m8n8.x4.shared.b16 {%0,%1,%2,%3}, [%4];"
        : "=r"(r[0]), "=r"(r[1]), "=r"(r[2]), "=r"(r[3]) : "r"(addr));
}

// warp tile m64 x n32, K = KW, smem pitch LDPITCH (conflict-free: pitch%64==8)
template <int LDPITCH, int KW>
__device__ __forceinline__ void mma_panel(const bf16* As, const bf16* Bs,
                                          int moff, int noff, int lane,
                                          float acc[4][4][4]) {
    // A x4: matrices (rows0-7,k0-7)(rows8-15,k0-7)(rows0-7,k8-15)(rows8-15,k8-15)
    uint32_t abase = (uint32_t)__cvta_generic_to_shared(As)
        + (uint32_t)(((moff + (lane & 15)) * LDPITCH + (lane >> 4) * 8) * 2);
    // B x4 per fn-pair: (fn even,k0-7)(fn even,k8-15)(fn odd,k0-7)(fn odd,k8-15)
    uint32_t bbase = (uint32_t)__cvta_generic_to_shared(Bs)
        + (uint32_t)(((noff + ((lane >> 4) & 1) * 8 + (lane & 7)) * LDPITCH
                      + ((lane >> 3) & 1) * 8) * 2);
#pragma unroll
    for (int kt = 0; kt < KW; kt += 16) {
        uint32_t bfr[2][4];
        ldsm_x4(bfr[0], bbase + kt * 2);
        ldsm_x4(bfr[1], bbase + (16 * LDPITCH + kt) * 2);
#pragma unroll
        for (int fm = 0; fm < 4; fm++) {
            uint32_t a[4];
            ldsm_x4(a, abase + (fm * 16 * LDPITCH + kt) * 2);
#pragma unroll
            for (int fn = 0; fn < 4; fn++)
                mma16816(acc[fm][fn], a[0], a[1], a[2], a[3],
                         bfr[fn >> 1][(fn & 1) * 2], bfr[fn >> 1][(fn & 1) * 2 + 1]);
        }
    }
}

// ---------------- build A: degrees + smem-accumulated scatter ---------------
// 8 blocks per graph; block owns src columns [part*64, part*64+64).
__global__ __launch_bounds__(512) void build_A_kernel(const int* __restrict__ src,
                                                      const int* __restrict__ dst) {
    extern __shared__ float accA[];                 // [512][64] fp32
    __shared__ int co[NN], ci[NN];
    __shared__ float rso[NN], rsi[NN];
    int g = blockIdx.x >> 3;
    int part = blockIdx.x & 7;
    int ss0 = part * 64;
    int t = threadIdx.x;
    for (int i = t; i < NN; i += 512) { co[i] = 0; ci[i] = 0; }
    for (int i = t; i < NN * 64; i += 512) accA[i] = 0.f;
    __syncthreads();
    const int* s = src + g * EE;
    const int* d = dst + g * EE;
    for (int e = t; e < EE; e += 512) {
        atomicAdd(&co[s[e]], 1);
        atomicAdd(&ci[d[e]], 1);
    }
    __syncthreads();
    for (int i = t; i < NN; i += 512) {
        rso[i] = rsqrtf((float)max(co[i], 1));
        rsi[i] = rsqrtf((float)max(ci[i], 1));
    }
    __syncthreads();
    for (int e = t; e < EE; e += 512) {
        int ss = s[e];
        if (ss >= ss0 && ss < ss0 + 64) {
            int dd = d[e];
            atomicAdd(&accA[dd * 64 + (ss - ss0)], rsi[dd] * rso[ss]);
        }
    }
    __syncthreads();
    bf16* A = g_Ab + (size_t)g * NN * NN + ss0;
    for (int i = t; i < NN * 8; i += 512) {          // 8 bf16 per thread-item
        int r = i >> 3, c8 = (i & 7) * 8;
        const float* v = &accA[r * 64 + c8];
        __nv_bfloat162 p0 = __floats2bfloat162_rn(v[0], v[1]);
        __nv_bfloat162 p1 = __floats2bfloat162_rn(v[2], v[3]);
        __nv_bfloat162 p2 = __floats2bfloat162_rn(v[4], v[5]);
        __nv_bfloat162 p3 = __floats2bfloat162_rn(v[6], v[7]);
        uint4 pk = make_uint4(*(uint32_t*)&p0, *(uint32_t*)&p1,
                              *(uint32_t*)&p2, *(uint32_t*)&p3);
        *(uint4*)(A + (size_t)r * NN + c8) = pk;
    }
}

// ---------------- prep: codebook norm + weight transposes + acc zero --------
__global__ __launch_bounds__(256) void prep_kernel(const float* __restrict__ cb,
                                                   const float* __restrict__ W1,
                                                   const float* __restrict__ W2,
                                                   const float* __restrict__ D1) {
    __shared__ float tile[32][33];
    int b = blockIdx.x;
    if (b == 0 && threadIdx.x < G) {
        g_epos[threadIdx.x] = 0.f;
        g_eneg[threadIdx.x] = 0.f;
        g_ecnt[threadIdx.x] = 0.f;
        if (threadIdx.x == 0) g_vqacc = 0.f;
    }
    if (b < KK) {
        int k = b;
        float v = cb[(size_t)k * DD + threadIdx.x];
        float ss = v * v;
        __shared__ float red[8];
        for (int o = 16; o > 0; o >>= 1) ss += __shfl_down_sync(0xffffffffu, ss, o);
        if ((threadIdx.x & 31) == 0) red[threadIdx.x >> 5] = ss;
        __syncthreads();
        if (threadIdx.x == 0) {
            float t = 0.f;
            for (int i = 0; i < 8; i++) t += red[i];
            red[0] = t;
        }
        __syncthreads();
        float r = rsqrtf(red[0] + 1e-12f);
        g_cnb[(size_t)k * DD + threadIdx.x] = __float2bfloat16(v * r);
    } else {
        int r2 = b - KK;
        int which = r2 >> 6, t2 = r2 & 63;
        const float* srcW = which == 0 ? W1 : which == 1 ? W2 : D1;
        bf16* dstW = which == 0 ? g_W1t : which == 1 ? g_W2t : g_D1t;
        int bx = t2 & 7, by = t2 >> 3;
        int r0 = by * 32, c0 = bx * 32;
        int tx = threadIdx.x & 31, ty = threadIdx.x >> 5;
#pragma unroll
        for (int i = 0; i < 4; i++) {
            int r = ty + i * 8;
            tile[r][tx] = srcW[(size_t)(r0 + r) * DD + c0 + tx];
        }
        __syncthreads();
#pragma unroll
        for (int i = 0; i < 4; i++) {
            int r = ty + i * 8;
            dstW[(size_t)(c0 + r) * DD + r0 + tx] = __float2bfloat16(tile[tx][r]);
        }
    }
}

// ---------------- transpose + convert (feats) -------------------------------
__global__ __launch_bounds__(256) void transpose_kernel(
    const float* __restrict__ in, bf16* __restrict__ out,
    int R, int C, size_t sIn, size_t sOut)
{
    __shared__ float tile[32][33];
    int b = blockIdx.z;
    in  += (size_t)b * sIn;
    out += (size_t)b * sOut;
    int r0 = blockIdx.y * 32, c0 = blockIdx.x * 32;
    int tx = threadIdx.x & 31, ty = threadIdx.x >> 5;
#pragma unroll
    for (int i = 0; i < 4; i++) {
        int r = ty + i * 8;
        tile[r][tx] = in[(size_t)(r0 + r) * C + c0 + tx];
    }
    __syncthreads();
#pragma unroll
    for (int i = 0; i < 4; i++) {
        int r = ty + i * 8;
        out[(size_t)(c0 + r) * R + r0 + tx] = __float2bfloat16(tile[tx][r]);
    }
}

// ---------------- generic bf16 HMMA GEMM (double-buffered K=64 panels) ------
__global__ __launch_bounds__(256) void hgemm_kernel(
    const bf16* __restrict__ A, const bf16* __restrict__ Bt,
    const float* __restrict__ bias, float* __restrict__ Cf, bf16* __restrict__ Cb,
    int M, int Ncol, int Kd, size_t sA, size_t sBt, size_t sC, int relu)
{
    extern __shared__ bf16 dynsm[];
    bf16* Abuf[2] = { dynsm, dynsm + 2 * P64_ELEMS };
    bf16* Bbuf[2] = { dynsm + P64_ELEMS, dynsm + 3 * P64_ELEMS };
    int b = blockIdx.z;
    A  += (size_t)b * sA;
    Bt += (size_t)b * sBt;
    int rowbase = blockIdx.y * 128, colbase = blockIdx.x * 128;
    int t = threadIdx.x, lane = t & 31, wid = t >> 5;
    int lr = lane >> 2, lq = lane & 3;
    int moff = (wid & 1) * 64, noff = (wid >> 1) * 32;

    int P = Kd / 64;
    stage64(A  + (size_t)rowbase * Kd, Kd, Abuf[0]);
    stage64(Bt + (size_t)colbase * Kd, Kd, Bbuf[0]);
    CP_COMMIT();

    float acc[4][4][4] = {};
    for (int p = 0; p < P; p++) {
        if (p + 1 < P) {
            stage64(A  + (size_t)rowbase * Kd + (p + 1) * 64, Kd, Abuf[(p + 1) & 1]);
            stage64(Bt + (size_t)colbase * Kd + (p + 1) * 64, Kd, Bbuf[(p + 1) & 1]);
            CP_COMMIT();
            CP_WAIT1();
        } else {
            CP_WAIT0();
        }
        __syncthreads();
        mma_panel<LD64, 64>(Abuf[p & 1], Bbuf[p & 1], moff, noff, lane, acc);
        __syncthreads();
    }
#pragma unroll
    for (int fm = 0; fm < 4; fm++)
#pragma unroll
        for (int fn = 0; fn < 4; fn++)
#pragma unroll
            for (int i = 0; i < 4; i++) {
                int row = rowbase + moff + fm * 16 + lr + (i >> 1) * 8;
                int col = colbase + noff + fn * 8 + 2 * lq + (i & 1);
                float v = acc[fm][fn][i];
                if (bias) v += bias[col];
                if (relu) v = fmaxf(v, 0.f);
                size_t o = (size_t)b * sC + (size_t)row * Ncol + col;
                if (Cf) Cf[o] = v;
                if (Cb) Cb[o] = __float2bfloat16(v);
            }
}

// ---------------- fused layernorm + transpose -------------------------------
__global__ __launch_bounds__(256) void ln_transpose_kernel(
    const float* __restrict__ x, const float* __restrict__ gamma,
    const float* __restrict__ beta, bf16* __restrict__ xt)
{
    __shared__ bf16 tile[32][258];
    __shared__ float gsh[DD], bsh[DD];
    int g = blockIdx.x >> 4;
    int rb = (blockIdx.x & 15) * 32;
    int t = threadIdx.x, lane = t & 31, warp = t >> 5;
    gsh[t] = gamma[t];
    bsh[t] = beta[t];
    __syncthreads();
#pragma unroll
    for (int rr = 0; rr < 4; rr++) {
        int row = rb + warp * 4 + rr;
        const float* xr = x + ((size_t)g * NN + row) * DD;
        float v[8];
        float s = 0.f;
#pragma unroll
        for (int j = 0; j < 8; j++) { v[j] = xr[lane + j * 32]; s += v[j]; }
        for (int o = 16; o > 0; o >>= 1) s += __shfl_xor_sync(0xffffffffu, s, o);
        float mu = s / DD;
        float s2 = 0.f;
#pragma unroll
        for (int j = 0; j < 8; j++) { float d = v[j] - mu; s2 += d * d; }
        for (int o = 16; o > 0; o >>= 1) s2 += __shfl_xor_sync(0xffffffffu, s2, o);
        float rs = rsqrtf(s2 / DD + 1e-5f);
#pragma unroll
        for (int j = 0; j < 8; j++) {
            int d = lane + j * 32;
            tile[row - rb][d] = __float2bfloat16((v[j] - mu) * rs * gsh[d] + bsh[d]);
        }
    }
    __syncthreads();
    bf16* dst = xt + (size_t)g * DD * NN;
    for (int i = t; i < 32 * DD; i += 256) {
        int d = i >> 5, node = i & 31;
        dst[(size_t)d * NN + rb + node] = tile[node][d];
    }
}

// ---------------- fused VQ argmax (double-buffered) + gather + vq loss ------
#define AM_SMEM (3 * P256_BYTES + 16 * 128 * 8)
__global__ __launch_bounds__(256, 1) void argmax_vq_kernel(
    const bf16* __restrict__ hfb, const float* __restrict__ hf,
    const float* __restrict__ cb)
{
    extern __shared__ char smraw[];
    bf16*  As   = (bf16*)smraw;
    bf16*  Bs0  = As + P256_ELEMS;
    bf16*  Bs1  = Bs0 + P256_ELEMS;
    float* redv = (float*)(Bs1 + P256_ELEMS);
    int*   redi = (int*)(redv + 16 * 128);
    int rowbase = blockIdx.x * 128;
    int t = threadIdx.x, lane = t & 31, wid = t >> 5;
    int lr = lane >> 2, lq = lane & 3;
    int moff = (wid >> 2) * 64, noff = (wid & 3) * 32;

    stage256(hfb + (size_t)rowbase * DD, DD, As);
    stage256(g_cnb, DD, Bs0);
    CP_COMMIT();
    CP_WAIT0();
    __syncthreads();

    float best[4][2];
    int   bidx[4][2];
#pragma unroll
    for (int fm = 0; fm < 4; fm++)
#pragma unroll
        for (int h = 0; h < 2; h++) { best[fm][h] = -1e30f; bidx[fm][h] = 0; }

    for (int cc = 0; cc < KK / 128; cc++) {
        bf16* Bcur  = (cc & 1) ? Bs1 : Bs0;
        bf16* Bnext = (cc & 1) ? Bs0 : Bs1;
        if (cc + 1 < KK / 128) {
            stage256(g_cnb + (size_t)(cc + 1) * 128 * DD, DD, Bnext);
            CP_COMMIT();
        }
        float acc[4][4][4] = {};
        mma_panel<LDP, 256>(As, Bcur, moff, noff, lane, acc);
#pragma unroll
        for (int fm = 0; fm < 4; fm++)
#pragma unroll
            for (int fn = 0; fn < 4; fn++) {
                int colb = cc * 128 + noff + fn * 8 + 2 * lq;
                float* c = acc[fm][fn];
                if (c[0] > best[fm][0]) { best[fm][0] = c[0]; bidx[fm][0] = colb; }
                if (c[1] > best[fm][0]) { best[fm][0] = c[1]; bidx[fm][0] = colb + 1; }
                if (c[2] > best[fm][1]) { best[fm][1] = c[2]; bidx[fm][1] = colb; }
                if (c[3] > best[fm][1]) { best[fm][1] = c[3]; bidx[fm][1] = colb + 1; }
            }
        CP_WAIT0();
        __syncthreads();
    }
    int owner = (wid & 3) * 4 + lq;
#pragma unroll
    for (int fm = 0; fm < 4; fm++)
#pragma unroll
        for (int h = 0; h < 2; h++) {
            int lrow = moff + fm * 16 + lr + h * 8;
            redv[owner * 128 + lrow] = best[fm][h];
            redi[owner * 128 + lrow] = bidx[fm][h];
        }
    __syncthreads();
    if (t < 128) {
        float bv = redv[t];
        int bi = redi[t];
        for (int x = 1; x < 16; x++) {
            float v = redv[x * 128 + t];
            int ii = redi[x * 128 + t];
            if (v > bv || (v == bv && ii < bi)) { bv = v; bi = ii; }
        }
        g_idx[rowbase + t] = bi;
        redi[t] = bi;
    }
    __syncthreads();
    {
        int r = t >> 1, half = t & 1;
        int idx = redi[r];
        const float* crow = cb + (size_t)idx * DD + half * 128;
        const float* hrow = hf + (size_t)(rowbase + r) * DD + half * 128;
        bf16* qrow = g_qb + (size_t)(rowbase + r) * DD + half * 128;
        float s = 0.f;
        for (int d = 0; d < 128; d++) {
            float cv = crow[d];
            float df = cv - hrow[d];
            s += df * df;
            qrow[d] = __float2bfloat16(cv);
        }
        for (int o = 16; o > 0; o >>= 1) s += __shfl_down_sync(0xffffffffu, s, o);
        if ((t & 31) == 0) atomicAdd(&g_vqacc, s);
    }
}

// ---------------- fused edge loss: HMMA logits + BCE + edge count -----------
__global__ __launch_bounds__(256) void edge_loss_kernel(const bf16* __restrict__ qe) {
    extern __shared__ bf16 dynsm[];
    bf16* As = dynsm;
    bf16* Bs = dynsm + P128_ELEMS;
    __shared__ float redp[8], redn[8], redc[8];
    int g = blockIdx.y;
    int tlin = blockIdx.x;
    int bi = 0, rem = tlin;
    while (rem >= 4 - bi) { rem -= 4 - bi; bi++; }
    int bj = bi + rem;
    const bf16* Q = qe + (size_t)g * NN * DD;
    const unsigned short* AbT = (const unsigned short*)(g_Ab + (size_t)g * NN * NN);

    int t = threadIdx.x, lane = t & 31, wid = t >> 5;
    int lr = lane >> 2, lq = lane & 3;
    int moff = (wid & 1) * 64, noff = (wid >> 1) * 32;
    int rowbase = bi * 128, colbase = bj * 128;

    float acc[4][4][4] = {};
    for (int p = 0; p < DD; p += 128) {
        stage128(Q + (size_t)rowbase * DD + p, DD, As);
        stage128(Q + (size_t)colbase * DD + p, DD, Bs);
        CP_COMMIT();
        CP_WAIT0();
        __syncthreads();
        mma_panel<LDQ, 128>(As, Bs, moff, noff, lane, acc);
        if (p + 128 < DD) __syncthreads();
    }

    float spos = 0.f, sneg = 0.f, cnt = 0.f;
#pragma unroll
    for (int fm = 0; fm < 4; fm++)
#pragma unroll
        for (int fn = 0; fn < 4; fn++)
#pragma unroll
            for (int i = 0; i < 4; i++) {
                int row = rowbase + moff + fm * 16 + lr + (i >> 1) * 8;
                int col = colbase + noff + fn * 8 + 2 * lq + (i & 1);
                if (row < col) {
                    float x = acc[fm][fn][i];
                    float l1 = log1pf(__expf(-fabsf(x)));
                    float sp_p = fmaxf(x, 0.f) + l1;
                    float sp_n = fmaxf(-x, 0.f) + l1;
                    if (AbT[col * NN + row] != 0) { spos += sp_n; cnt += 1.f; }
                    else                          { sneg += sp_p; }
                }
            }
    for (int o = 16; o > 0; o >>= 1) {
        spos += __shfl_down_sync(0xffffffffu, spos, o);
        sneg += __shfl_down_sync(0xffffffffu, sneg, o);
        cnt  += __shfl_down_sync(0xffffffffu, cnt, o);
    }
    if ((t & 31) == 0) { redp[t >> 5] = spos; redn[t >> 5] = sneg; redc[t >> 5] = cnt; }
    __syncthreads();
    if (t == 0) {
        float tp = 0.f, tn = 0.f, tc = 0.f;
        for (int i = 0; i < 8; i++) { tp += redp[i]; tn += redn[i]; tc += redc[i]; }
        atomicAdd(&g_epos[g], tp);
        atomicAdd(&g_eneg[g], tn);
        atomicAdd(&g_ecnt[g], tc);
    }
}

// ---------------- finalize --------------------------------------------------
__global__ void finalize_kernel(float* out, int out_size) {
    float es = 0.f;
    for (int g = 0; g < G; g++) {
        float ne = g_ecnt[g];
        float pw = ((float)NN * NN * 0.5f - ne) / (ne + 1e-6f);
        es += (pw * g_epos[g] + g_eneg[g]) / ((float)NN * (NN - 1) * 0.5f);
    }
    es /= (float)G;
    float vq = 1000.0f * g_vqacc / ((float)G * NN * DD);
    float loss = es * 100.0f + vq;
    for (int i = 0; i < out_size; i++) out[i] = loss;
}

// ---------------- launch ----------------------------------------------------
extern "C" void kernel_launch(void* const* d_in, const int* in_sizes, int n_in,
                              void* d_out, int out_size) {
    (void)in_sizes; (void)n_in;
    const float* feats = (const float*)d_in[0];
    const int*   src   = (const int*)  d_in[1];
    const int*   dst   = (const int*)  d_in[2];
    const float* W1    = (const float*)d_in[3];
    const float* b1    = (const float*)d_in[4];
    const float* W2    = (const float*)d_in[5];
    const float* b2    = (const float*)d_in[6];
    const float* gamma = (const float*)d_in[7];
    const float* beta  = (const float*)d_in[8];
    const float* dec1W = (const float*)d_in[9];
    const float* dec1b = (const float*)d_in[10];
    const float* cb    = (const float*)d_in[13];
    float* out = (float*)d_out;

    float* pF1;
    bf16 *pAb, *pXt, *pM, *pHb, *pQb, *pQe, *pW1t, *pW2t, *pD1t;
    cudaGetSymbolAddress((void**)&pF1,  g_f1);
    cudaGetSymbolAddress((void**)&pAb,  g_Ab);
    cudaGetSymbolAddress((void**)&pXt,  g_Xt);
    cudaGetSymbolAddress((void**)&pM,   g_m);
    cudaGetSymbolAddress((void**)&pHb,  g_hb);
    cudaGetSymbolAddress((void**)&pQb,  g_qb);
    cudaGetSymbolAddress((void**)&pQe,  g_qe);
    cudaGetSymbolAddress((void**)&pW1t, g_W1t);
    cudaGetSymbolAddress((void**)&pW2t, g_W2t);
    cudaGetSymbolAddress((void**)&pD1t, g_D1t);

    cudaFuncSetAttribute(hgemm_kernel,
                         cudaFuncAttributeMaxDynamicSharedMemorySize, HG_SMEM);
    cudaFuncSetAttribute(edge_loss_kernel,
                         cudaFuncAttributeMaxDynamicSharedMemorySize, EL_SMEM);
    cudaFuncSetAttribute(argmax_vq_kernel,
                         cudaFuncAttributeMaxDynamicSharedMemorySize, AM_SMEM);
    cudaFuncSetAttribute(build_A_kernel,
                         cudaFuncAttributeMaxDynamicSharedMemorySize, DS_SMEM);

    prep_kernel<<<KK + 192, 256>>>(cb, W1, W2, dec1W);
    transpose_kernel<<<dim3(DD / 32, NN / 32, G), 256>>>(
        feats, pXt, NN, DD, (size_t)NN * DD, (size_t)NN * DD);
    build_A_kernel<<<G * 8, 512, DS_SMEM>>>(src, dst);

    // conv1: m = Ab @ Xt^T  (bf16 out)
    hgemm_kernel<<<dim3(DD / 128, NN / 128, G), 256, HG_SMEM>>>(
        pAb, pXt, nullptr, nullptr, pM, NN, DD, NN,
        (size_t)NN * NN, (size_t)DD * NN, (size_t)NN * DD, 0);
    // h1 = relu(m @ W1 + b1)  (fp32 out)
    hgemm_kernel<<<dim3(DD / 128, (G * NN) / 128, 1), 256, HG_SMEM>>>(
        pM, pW1t, b1, pF1, nullptr, G * NN, DD, DD, 0, 0, 0, 1);
    // fused layernorm + transpose -> Xt
    ln_transpose_kernel<<<G * 16, 256>>>(pF1, gamma, beta, pXt);
    // conv2
    hgemm_kernel<<<dim3(DD / 128, NN / 128, G), 256, HG_SMEM>>>(
        pAb, pXt, nullptr, nullptr, pM, NN, DD, NN,
        (size_t)NN * NN, (size_t)DD * NN, (size_t)NN * DD, 0);
    // hf = relu(m2 @ W2 + b2)  (fp32 + bf16 out)
    hgemm_kernel<<<dim3(DD / 128, (G * NN) / 128, 1), 256, HG_SMEM>>>(
        pM, pW2t, b2, pF1, pHb, G * NN, DD, DD, 0, 0, 0, 1);

    // VQ argmax + gather + vq loss
    argmax_vq_kernel<<<(G * NN) / 128, 256, AM_SMEM>>>(pHb, pF1, cb);

    // qe = q @ dec1_W + dec1_b  (bf16 out)
    hgemm_kernel<<<dim3(DD / 128, (G * NN) / 128, 1), 256, HG_SMEM>>>(
        pQb, pD1t, dec1b, nullptr, pQe, G * NN, DD, DD, 0, 0, 0, 0);

    // fused edge BCE loss + edge count
    edge_loss_kernel<<<dim3(10, G), 256, EL_SMEM>>>(pQe);

    finalize_kernel<<<1, 1>>>(out, out_size);
}

// round 10
// speedup vs baseline: 5.5634x; 1.0123x over previous
#include <cuda_runtime.h>
#include <cuda_bf16.h>
#include <math.h>
#include <stdint.h>

#define G   32
#define NN  512
#define EE  8192
#define DD  256
#define KK  2048

typedef __nv_bfloat16 bf16;

#define LD64 72
#define P64_ELEMS (128 * LD64)
#define P64_BYTES (P64_ELEMS * 2)       // 18432 B
#define HG_SMEM (4 * P64_BYTES)         // 73728 B
#define LDQ 136
#define P128_ELEMS (128 * LDQ)
#define P128_BYTES (P128_ELEMS * 2)     // 34816 B
#define EL_SMEM (2 * P128_BYTES)
#define LDP 264
#define P256_ELEMS (128 * LDP)
#define P256_BYTES (P256_ELEMS * 2)     // 67584 B
#define DS_SMEM (NN * 64 * 4)           // 131072 B

// ---------------- scratch (device globals) ---------------------------------
__device__ bf16  g_Ab  [(size_t)G * NN * NN];
__device__ bf16  g_Xt  [(size_t)G * DD * NN];
__device__ bf16  g_m   [(size_t)G * NN * DD];
__device__ float g_f1  [(size_t)G * NN * DD];
__device__ bf16  g_hb  [(size_t)G * NN * DD];
__device__ bf16  g_qb  [(size_t)G * NN * DD];
__device__ bf16  g_qe  [(size_t)G * NN * DD];
__device__ bf16  g_cnb [(size_t)KK * DD];
__device__ bf16  g_W1t [DD * DD];
__device__ bf16  g_W2t [DD * DD];
__device__ bf16  g_D1t [DD * DD];
__device__ int   g_idx [G * NN];
__device__ float g_epos[G];
__device__ float g_eneg[G];
__device__ float g_ecnt[G];
__device__ float g_vqacc;

// ---------------- cp.async helpers -----------------------------------------
__device__ __forceinline__ void cpasync16(void* smem, const void* gptr) {
    uint32_t a = (uint32_t)__cvta_generic_to_shared(smem);
    asm volatile("cp.async.cg.shared.global [%0], [%1], 16;\n" :: "r"(a), "l"(gptr));
}
#define CP_COMMIT() asm volatile("cp.async.commit_group;\n" ::: "memory")
#define CP_WAIT0()  asm volatile("cp.async.wait_group 0;\n" ::: "memory")

__device__ __forceinline__ void stage64(const bf16* __restrict__ src, size_t ld,
                                        bf16* __restrict__ dstS) {
    int t = threadIdx.x;
#pragma unroll
    for (int i = 0; i < 4; i++) {
        int idx = t + i * 256;
        int r = idx >> 3;
        int c = (idx & 7) * 8;
        cpasync16(&dstS[r * LD64 + c], &src[(size_t)r * ld + c]);
    }
}

__device__ __forceinline__ void stage128(const bf16* __restrict__ src, size_t ld,
                                         bf16* __restrict__ dstS) {
    int t = threadIdx.x;
#pragma unroll
    for (int i = 0; i < 8; i++) {
        int idx = t + i * 256;
        int r = idx >> 4;
        int c = (idx & 15) * 8;
        cpasync16(&dstS[r * LDQ + c], &src[(size_t)r * ld + c]);
    }
}

__device__ __forceinline__ void stage256(const bf16* __restrict__ src, size_t ld,
                                         bf16* __restrict__ dstS) {
    int t = threadIdx.x;
#pragma unroll
    for (int i = 0; i < 16; i++) {
        int idx = t + i * 256;
        int r = idx >> 5;
        int c = (idx & 31) * 8;
        cpasync16(&dstS[r * LDP + c], &src[(size_t)r * ld + c]);
    }
}

// ---------------- MMA core (ldmatrix + mma.sync) ----------------------------
__device__ __forceinline__ void mma16816(float c[4], uint32_t a0, uint32_t a1,
                                         uint32_t a2, uint32_t a3,
                                         uint32_t b0, uint32_t b1) {
    asm volatile(
        "mma.sync.aligned.m16n8k16.row.col.f32.bf16.bf16.f32 "
        "{%0,%1,%2,%3}, {%4,%5,%6,%7}, {%8,%9}, {%0,%1,%2,%3};\n"
        : "+f"(c[0]), "+f"(c[1]), "+f"(c[2]), "+f"(c[3])
        : "r"(a0), "r"(a1), "r"(a2), "r"(a3), "r"(b0), "r"(b1));
}

__device__ __forceinline__ void ldsm_x4(uint32_t r[4], uint32_t addr) {
    asm volatile("ldmatrix.sync.aligned.m8n8.x4.shared.b16 {%0,%1,%2,%3}, [%4];"
        : "=r"(r[0]), "=r"(r[1]), "=r"(r[2]), "=r"(r[3]) : "r"(addr));
}

template <int LDPITCH, int KW>
__device__ __forceinline__ void mma_panel(const bf16* As, const bf16* Bs,
                                          int moff, int noff, int lane,
                                          float acc[4][4][4]) {
    uint32_t abase = (uint32_t)__cvta_generic_to_shared(As)
        + (uint32_t)(((moff + (lane & 15)) * LDPITCH + (lane >> 4) * 8) * 2);
    uint32_t bbase = (uint32_t)__cvta_generic_to_shared(Bs)
        + (uint32_t)(((noff + ((lane >> 4) & 1) * 8 + (lane & 7)) * LDPITCH
                      + ((lane >> 3) & 1) * 8) * 2);
#pragma unroll
    for (int kt = 0; kt < KW; kt += 16) {
        uint32_t bfr[2][4];
        ldsm_x4(bfr[0], bbase + kt * 2);
        ldsm_x4(bfr[1], bbase + (16 * LDPITCH + kt) * 2);
#pragma unroll
        for (int fm = 0; fm < 4; fm++) {
            uint32_t a[4];
            ldsm_x4(a, abase + (fm * 16 * LDPITCH + kt) * 2);
#pragma unroll
            for (int fn = 0; fn < 4; fn++)
                mma16816(acc[fm][fn], a[0], a[1], a[2], a[3],
                         bfr[fn >> 1][(fn & 1) * 2], bfr[fn >> 1][(fn & 1) * 2 + 1]);
        }
    }
}

// ---------------- build A: degrees + smem-accumulated scatter ---------------
__global__ __launch_bounds__(512) void build_A_kernel(const int* __restrict__ src,
                                                      const int* __restrict__ dst) {
    extern __shared__ float accA[];
    __shared__ int co[NN], ci[NN];
    __shared__ float rso[NN], rsi[NN];
    int g = blockIdx.x >> 3;
    int part = blockIdx.x & 7;
    int ss0 = part * 64;
    int t = threadIdx.x;
    for (int i = t; i < NN; i += 512) { co[i] = 0; ci[i] = 0; }
    for (int i = t; i < NN * 64; i += 512) accA[i] = 0.f;
    __syncthreads();
    const int* s = src + g * EE;
    const int* d = dst + g * EE;
    for (int e = t; e < EE; e += 512) {
        atomicAdd(&co[s[e]], 1);
        atomicAdd(&ci[d[e]], 1);
    }
    __syncthreads();
    for (int i = t; i < NN; i += 512) {
        rso[i] = rsqrtf((float)max(co[i], 1));
        rsi[i] = rsqrtf((float)max(ci[i], 1));
    }
    __syncthreads();
    for (int e = t; e < EE; e += 512) {
        int ss = s[e];
        if (ss >= ss0 && ss < ss0 + 64) {
            int dd = d[e];
            atomicAdd(&accA[dd * 64 + (ss - ss0)], rsi[dd] * rso[ss]);
        }
    }
    __syncthreads();
    bf16* A = g_Ab + (size_t)g * NN * NN + ss0;
    for (int i = t; i < NN * 8; i += 512) {
        int r = i >> 3, c8 = (i & 7) * 8;
        const float* v = &accA[r * 64 + c8];
        __nv_bfloat162 p0 = __floats2bfloat162_rn(v[0], v[1]);
        __nv_bfloat162 p1 = __floats2bfloat162_rn(v[2], v[3]);
        __nv_bfloat162 p2 = __floats2bfloat162_rn(v[4], v[5]);
        __nv_bfloat162 p3 = __floats2bfloat162_rn(v[6], v[7]);
        uint4 pk = make_uint4(*(uint32_t*)&p0, *(uint32_t*)&p1,
                              *(uint32_t*)&p2, *(uint32_t*)&p3);
        *(uint4*)(A + (size_t)r * NN + c8) = pk;
    }
}

// ---------------- prep: codebook norm + weight transposes + acc zero --------
__global__ __launch_bounds__(256) void prep_kernel(const float* __restrict__ cb,
                                                   const float* __restrict__ W1,
                                                   const float* __restrict__ W2,
                                                   const float* __restrict__ D1) {
    __shared__ float tile[32][33];
    int b = blockIdx.x;
    if (b == 0 && threadIdx.x < G) {
        g_epos[threadIdx.x] = 0.f;
        g_eneg[threadIdx.x] = 0.f;
        g_ecnt[threadIdx.x] = 0.f;
        if (threadIdx.x == 0) g_vqacc = 0.f;
    }
    if (b < KK) {
        int k = b;
        float v = cb[(size_t)k * DD + threadIdx.x];
        float ss = v * v;
        __shared__ float red[8];
        for (int o = 16; o > 0; o >>= 1) ss += __shfl_down_sync(0xffffffffu, ss, o);
        if ((threadIdx.x & 31) == 0) red[threadIdx.x >> 5] = ss;
        __syncthreads();
        if (threadIdx.x == 0) {
            float t = 0.f;
            for (int i = 0; i < 8; i++) t += red[i];
            red[0] = t;
        }
        __syncthreads();
        float r = rsqrtf(red[0] + 1e-12f);
        g_cnb[(size_t)k * DD + threadIdx.x] = __float2bfloat16(v * r);
    } else {
        int r2 = b - KK;
        int which = r2 >> 6, t2 = r2 & 63;
        const float* srcW = which == 0 ? W1 : which == 1 ? W2 : D1;
        bf16* dstW = which == 0 ? g_W1t : which == 1 ? g_W2t : g_D1t;
        int bx = t2 & 7, by = t2 >> 3;
        int r0 = by * 32, c0 = bx * 32;
        int tx = threadIdx.x & 31, ty = threadIdx.x >> 5;
#pragma unroll
        for (int i = 0; i < 4; i++) {
            int r = ty + i * 8;
            tile[r][tx] = srcW[(size_t)(r0 + r) * DD + c0 + tx];
        }
        __syncthreads();
#pragma unroll
        for (int i = 0; i < 4; i++) {
            int r = ty + i * 8;
            dstW[(size_t)(c0 + r) * DD + r0 + tx] = __float2bfloat16(tile[tx][r]);
        }
    }
}

// ---------------- transpose + convert (feats) -------------------------------
__global__ __launch_bounds__(256) void transpose_kernel(
    const float* __restrict__ in, bf16* __restrict__ out,
    int R, int C, size_t sIn, size_t sOut)
{
    __shared__ float tile[32][33];
    int b = blockIdx.z;
    in  += (size_t)b * sIn;
    out += (size_t)b * sOut;
    int r0 = blockIdx.y * 32, c0 = blockIdx.x * 32;
    int tx = threadIdx.x & 31, ty = threadIdx.x >> 5;
#pragma unroll
    for (int i = 0; i < 4; i++) {
        int r = ty + i * 8;
        tile[r][tx] = in[(size_t)(r0 + r) * C + c0 + tx];
    }
    __syncthreads();
#pragma unroll
    for (int i = 0; i < 4; i++) {
        int r = ty + i * 8;
        out[(size_t)(c0 + r) * R + r0 + tx] = __float2bfloat16(tile[tx][r]);
    }
}

// ---------------- generic bf16 HMMA GEMM (single-sync pipeline) -------------
__global__ __launch_bounds__(256) void hgemm_kernel(
    const bf16* __restrict__ A, const bf16* __restrict__ Bt,
    const float* __restrict__ bias, float* __restrict__ Cf, bf16* __restrict__ Cb,
    int M, int Ncol, int Kd, size_t sA, size_t sBt, size_t sC, int relu)
{
    extern __shared__ bf16 dynsm[];
    bf16* Abuf[2] = { dynsm, dynsm + 2 * P64_ELEMS };
    bf16* Bbuf[2] = { dynsm + P64_ELEMS, dynsm + 3 * P64_ELEMS };
    int b = blockIdx.z;
    A  += (size_t)b * sA;
    Bt += (size_t)b * sBt;
    int rowbase = blockIdx.y * 128, colbase = blockIdx.x * 128;
    int t = threadIdx.x, lane = t & 31, wid = t >> 5;
    int lr = lane >> 2, lq = lane & 3;
    int moff = (wid & 1) * 64, noff = (wid >> 1) * 32;

    int P = Kd / 64;
    stage64(A  + (size_t)rowbase * Kd, Kd, Abuf[0]);
    stage64(Bt + (size_t)colbase * Kd, Kd, Bbuf[0]);
    CP_COMMIT();

    float acc[4][4][4] = {};
    for (int p = 0; p < P; p++) {
        CP_WAIT0();                 // group p done (overlapped with compute p-1)
        __syncthreads();            // also proves compute p-1 done for all warps
        if (p + 1 < P) {
            stage64(A  + (size_t)rowbase * Kd + (p + 1) * 64, Kd, Abuf[(p + 1) & 1]);
            stage64(Bt + (size_t)colbase * Kd + (p + 1) * 64, Kd, Bbuf[(p + 1) & 1]);
            CP_COMMIT();
        }
        mma_panel<LD64, 64>(Abuf[p & 1], Bbuf[p & 1], moff, noff, lane, acc);
    }
#pragma unroll
    for (int fm = 0; fm < 4; fm++)
#pragma unroll
        for (int fn = 0; fn < 4; fn++)
#pragma unroll
            for (int i = 0; i < 4; i++) {
                int row = rowbase + moff + fm * 16 + lr + (i >> 1) * 8;
                int col = colbase + noff + fn * 8 + 2 * lq + (i & 1);
                float v = acc[fm][fn][i];
                if (bias) v += bias[col];
                if (relu) v = fmaxf(v, 0.f);
                size_t o = (size_t)b * sC + (size_t)row * Ncol + col;
                if (Cf) Cf[o] = v;
                if (Cb) Cb[o] = __float2bfloat16(v);
            }
}

// ---------------- fused layernorm + transpose -------------------------------
__global__ __launch_bounds__(256) void ln_transpose_kernel(
    const float* __restrict__ x, const float* __restrict__ gamma,
    const float* __restrict__ beta, bf16* __restrict__ xt)
{
    __shared__ bf16 tile[32][258];
    __shared__ float gsh[DD], bsh[DD];
    int g = blockIdx.x >> 4;
    int rb = (blockIdx.x & 15) * 32;
    int t = threadIdx.x, lane = t & 31, warp = t >> 5;
    gsh[t] = gamma[t];
    bsh[t] = beta[t];
    __syncthreads();
#pragma unroll
    for (int rr = 0; rr < 4; rr++) {
        int row = rb + warp * 4 + rr;
        const float* xr = x + ((size_t)g * NN + row) * DD;
        float v[8];
        float s = 0.f;
#pragma unroll
        for (int j = 0; j < 8; j++) { v[j] = xr[lane + j * 32]; s += v[j]; }
        for (int o = 16; o > 0; o >>= 1) s += __shfl_xor_sync(0xffffffffu, s, o);
        float mu = s / DD;
        float s2 = 0.f;
#pragma unroll
        for (int j = 0; j < 8; j++) { float d = v[j] - mu; s2 += d * d; }
        for (int o = 16; o > 0; o >>= 1) s2 += __shfl_xor_sync(0xffffffffu, s2, o);
        float rs = rsqrtf(s2 / DD + 1e-5f);
#pragma unroll
        for (int j = 0; j < 8; j++) {
            int d = lane + j * 32;
            tile[row - rb][d] = __float2bfloat16((v[j] - mu) * rs * gsh[d] + bsh[d]);
        }
    }
    __syncthreads();
    bf16* dst = xt + (size_t)g * DD * NN;
    for (int i = t; i < 32 * DD; i += 256) {
        int d = i >> 5, node = i & 31;
        dst[(size_t)d * NN + rb + node] = tile[node][d];
    }
}

// ---------------- fused VQ argmax (single-sync pipeline) --------------------
#define AM_SMEM (3 * P256_BYTES + 16 * 128 * 8)
__global__ __launch_bounds__(256, 1) void argmax_vq_kernel(
    const bf16* __restrict__ hfb, const float* __restrict__ hf,
    const float* __restrict__ cb)
{
    extern __shared__ char smraw[];
    bf16*  As   = (bf16*)smraw;
    bf16*  Bs0  = As + P256_ELEMS;
    bf16*  Bs1  = Bs0 + P256_ELEMS;
    float* redv = (float*)(Bs1 + P256_ELEMS);
    int*   redi = (int*)(redv + 16 * 128);
    int rowbase = blockIdx.x * 128;
    int t = threadIdx.x, lane = t & 31, wid = t >> 5;
    int lr = lane >> 2, lq = lane & 3;
    int moff = (wid >> 2) * 64, noff = (wid & 3) * 32;

    stage256(hfb + (size_t)rowbase * DD, DD, As);
    stage256(g_cnb, DD, Bs0);
    CP_COMMIT();

    float best[4][2];
    int   bidx[4][2];
#pragma unroll
    for (int fm = 0; fm < 4; fm++)
#pragma unroll
        for (int h = 0; h < 2; h++) { best[fm][h] = -1e30f; bidx[fm][h] = 0; }

    for (int cc = 0; cc < KK / 128; cc++) {
        CP_WAIT0();                 // chunk cc ready (overlapped w/ compute cc-1)
        __syncthreads();
        if (cc + 1 < KK / 128) {
            bf16* Bnext = (cc & 1) ? Bs0 : Bs1;
            stage256(g_cnb + (size_t)(cc + 1) * 128 * DD, DD, Bnext);
            CP_COMMIT();
        }
        bf16* Bcur = (cc & 1) ? Bs1 : Bs0;
        float acc[4][4][4] = {};
        mma_panel<LDP, 256>(As, Bcur, moff, noff, lane, acc);
#pragma unroll
        for (int fm = 0; fm < 4; fm++)
#pragma unroll
            for (int fn = 0; fn < 4; fn++) {
                int colb = cc * 128 + noff + fn * 8 + 2 * lq;
                float* c = acc[fm][fn];
                if (c[0] > best[fm][0]) { best[fm][0] = c[0]; bidx[fm][0] = colb; }
                if (c[1] > best[fm][0]) { best[fm][0] = c[1]; bidx[fm][0] = colb + 1; }
                if (c[2] > best[fm][1]) { best[fm][1] = c[2]; bidx[fm][1] = colb; }
                if (c[3] > best[fm][1]) { best[fm][1] = c[3]; bidx[fm][1] = colb + 1; }
            }
    }
    int owner = (wid & 3) * 4 + lq;
#pragma unroll
    for (int fm = 0; fm < 4; fm++)
#pragma unroll
        for (int h = 0; h < 2; h++) {
            int lrow = moff + fm * 16 + lr + h * 8;
            redv[owner * 128 + lrow] = best[fm][h];
            redi[owner * 128 + lrow] = bidx[fm][h];
        }
    __syncthreads();
    if (t < 128) {
        float bv = redv[t];
        int bi = redi[t];
        for (int x = 1; x < 16; x++) {
            float v = redv[x * 128 + t];
            int ii = redi[x * 128 + t];
            if (v > bv || (v == bv && ii < bi)) { bv = v; bi = ii; }
        }
        g_idx[rowbase + t] = bi;
        redi[t] = bi;
    }
    __syncthreads();
    {
        int r = t >> 1, half = t & 1;
        int idx = redi[r];
        const float* crow = cb + (size_t)idx * DD + half * 128;
        const float* hrow = hf + (size_t)(rowbase + r) * DD + half * 128;
        bf16* qrow = g_qb + (size_t)(rowbase + r) * DD + half * 128;
        float s = 0.f;
        for (int d = 0; d < 128; d++) {
            float cv = crow[d];
            float df = cv - hrow[d];
            s += df * df;
            qrow[d] = __float2bfloat16(cv);
        }
        for (int o = 16; o > 0; o >>= 1) s += __shfl_down_sync(0xffffffffu, s, o);
        if ((t & 31) == 0) atomicAdd(&g_vqacc, s);
    }
}

// ---------------- fused edge loss (single-sync pipeline) --------------------
__global__ __launch_bounds__(256) void edge_loss_kernel(const bf16* __restrict__ qe) {
    extern __shared__ bf16 dynsm[];
    bf16* As = dynsm;
    bf16* Bs = dynsm + P128_ELEMS;
    __shared__ float redp[8], redn[8], redc[8];
    int g = blockIdx.y;
    int tlin = blockIdx.x;
    int bi = 0, rem = tlin;
    while (rem >= 4 - bi) { rem -= 4 - bi; bi++; }
    int bj = bi + rem;
    const bf16* Q = qe + (size_t)g * NN * DD;
    const unsigned short* AbT = (const unsigned short*)(g_Ab + (size_t)g * NN * NN);

    int t = threadIdx.x, lane = t & 31, wid = t >> 5;
    int lr = lane >> 2, lq = lane & 3;
    int moff = (wid & 1) * 64, noff = (wid >> 1) * 32;
    int rowbase = bi * 128, colbase = bj * 128;

    stage128(Q + (size_t)rowbase * DD, DD, As);
    stage128(Q + (size_t)colbase * DD, DD, Bs);
    CP_COMMIT();
    CP_WAIT0();
    __syncthreads();
    float acc[4][4][4] = {};
    mma_panel<LDQ, 128>(As, Bs, moff, noff, lane, acc);
    __syncthreads();
    stage128(Q + (size_t)rowbase * DD + 128, DD, As);
    stage128(Q + (size_t)colbase * DD + 128, DD, Bs);
    CP_COMMIT();
    CP_WAIT0();
    __syncthreads();
    mma_panel<LDQ, 128>(As, Bs, moff, noff, lane, acc);

    float spos = 0.f, sneg = 0.f, cnt = 0.f;
#pragma unroll
    for (int fm = 0; fm < 4; fm++)
#pragma unroll
        for (int fn = 0; fn < 4; fn++)
#pragma unroll
            for (int i = 0; i < 4; i++) {
                int row = rowbase + moff + fm * 16 + lr + (i >> 1) * 8;
                int col = colbase + noff + fn * 8 + 2 * lq + (i & 1);
                if (row < col) {
                    float x = acc[fm][fn][i];
                    float l1 = log1pf(__expf(-fabsf(x)));
                    float sp_p = fmaxf(x, 0.f) + l1;
                    float sp_n = fmaxf(-x, 0.f) + l1;
                    if (AbT[col * NN + row] != 0) { spos += sp_n; cnt += 1.f; }
                    else                          { sneg += sp_p; }
                }
            }
    for (int o = 16; o > 0; o >>= 1) {
        spos += __shfl_down_sync(0xffffffffu, spos, o);
        sneg += __shfl_down_sync(0xffffffffu, sneg, o);
        cnt  += __shfl_down_sync(0xffffffffu, cnt, o);
    }
    if ((t & 31) == 0) { redp[t >> 5] = spos; redn[t >> 5] = sneg; redc[t >> 5] = cnt; }
    __syncthreads();
    if (t == 0) {
        float tp = 0.f, tn = 0.f, tc = 0.f;
        for (int i = 0; i < 8; i++) { tp += redp[i]; tn += redn[i]; tc += redc[i]; }
        atomicAdd(&g_epos[g], tp);
        atomicAdd(&g_eneg[g], tn);
        atomicAdd(&g_ecnt[g], tc);
    }
}

// ---------------- finalize --------------------------------------------------
__global__ void finalize_kernel(float* out, int out_size) {
    float es = 0.f;
    for (int g = 0; g < G; g++) {
        float ne = g_ecnt[g];
        float pw = ((float)NN * NN * 0.5f - ne) / (ne + 1e-6f);
        es += (pw * g_epos[g] + g_eneg[g]) / ((float)NN * (NN - 1) * 0.5f);
    }
    es /= (float)G;
    float vq = 1000.0f * g_vqacc / ((float)G * NN * DD);
    float loss = es * 100.0f + vq;
    for (int i = 0; i < out_size; i++) out[i] = loss;
}

// ---------------- launch ----------------------------------------------------
extern "C" void kernel_launch(void* const* d_in, const int* in_sizes, int n_in,
                              void* d_out, int out_size) {
    (void)in_sizes; (void)n_in;
    const float* feats = (const float*)d_in[0];
    const int*   src   = (const int*)  d_in[1];
    const int*   dst   = (const int*)  d_in[2];
    const float* W1    = (const float*)d_in[3];
    const float* b1    = (const float*)d_in[4];
    const float* W2    = (const float*)d_in[5];
    const float* b2    = (const float*)d_in[6];
    const float* gamma = (const float*)d_in[7];
    const float* beta  = (const float*)d_in[8];
    const float* dec1W = (const float*)d_in[9];
    const float* dec1b = (const float*)d_in[10];
    const float* cb    = (const float*)d_in[13];
    float* out = (float*)d_out;

    float* pF1;
    bf16 *pAb, *pXt, *pM, *pHb, *pQb, *pQe, *pW1t, *pW2t, *pD1t;
    cudaGetSymbolAddress((void**)&pF1,  g_f1);
    cudaGetSymbolAddress((void**)&pAb,  g_Ab);
    cudaGetSymbolAddress((void**)&pXt,  g_Xt);
    cudaGetSymbolAddress((void**)&pM,   g_m);
    cudaGetSymbolAddress((void**)&pHb,  g_hb);
    cudaGetSymbolAddress((void**)&pQb,  g_qb);
    cudaGetSymbolAddress((void**)&pQe,  g_qe);
    cudaGetSymbolAddress((void**)&pW1t, g_W1t);
    cudaGetSymbolAddress((void**)&pW2t, g_W2t);
    cudaGetSymbolAddress((void**)&pD1t, g_D1t);

    cudaFuncSetAttribute(hgemm_kernel,
                         cudaFuncAttributeMaxDynamicSharedMemorySize, HG_SMEM);
    cudaFuncSetAttribute(edge_loss_kernel,
                         cudaFuncAttributeMaxDynamicSharedMemorySize, EL_SMEM);
    cudaFuncSetAttribute(argmax_vq_kernel,
                         cudaFuncAttributeMaxDynamicSharedMemorySize, AM_SMEM);
    cudaFuncSetAttribute(build_A_kernel,
                         cudaFuncAttributeMaxDynamicSharedMemorySize, DS_SMEM);

    prep_kernel<<<KK + 192, 256>>>(cb, W1, W2, dec1W);
    transpose_kernel<<<dim3(DD / 32, NN / 32, G), 256>>>(
        feats, pXt, NN, DD, (size_t)NN * DD, (size_t)NN * DD);
    build_A_kernel<<<G * 8, 512, DS_SMEM>>>(src, dst);

    hgemm_kernel<<<dim3(DD / 128, NN / 128, G), 256, HG_SMEM>>>(
        pAb, pXt, nullptr, nullptr, pM, NN, DD, NN,
        (size_t)NN * NN, (size_t)DD * NN, (size_t)NN * DD, 0);
    hgemm_kernel<<<dim3(DD / 128, (G * NN) / 128, 1), 256, HG_SMEM>>>(
        pM, pW1t, b1, pF1, nullptr, G * NN, DD, DD, 0, 0, 0, 1);
    ln_transpose_kernel<<<G * 16, 256>>>(pF1, gamma, beta, pXt);
    hgemm_kernel<<<dim3(DD / 128, NN / 128, G), 256, HG_SMEM>>>(
        pAb, pXt, nullptr, nullptr, pM, NN, DD, NN,
        (size_t)NN * NN, (size_t)DD * NN, (size_t)NN * DD, 0);
    hgemm_kernel<<<dim3(DD / 128, (G * NN) / 128, 1), 256, HG_SMEM>>>(
        pM, pW2t, b2, pF1, pHb, G * NN, DD, DD, 0, 0, 0, 1);

    argmax_vq_kernel<<<(G * NN) / 128, 256, AM_SMEM>>>(pHb, pF1, cb);

    hgemm_kernel<<<dim3(DD / 128, (G * NN) / 128, 1), 256, HG_SMEM>>>(
        pQb, pD1t, dec1b, nullptr, pQe, G * NN, DD, DD, 0, 0, 0, 0);

    edge_loss_kernel<<<dim3(10, G), 256, EL_SMEM>>>(pQe);

    finalize_kernel<<<1, 1>>>(out, out_size);
}